// round 5
// baseline (speedup 1.0000x reference)
#include <cuda_runtime.h>
#include <math.h>
#include <stdint.h>

#define Bb 64
#define Tt 512
#define Hh 768
#define Nn 2048
#define Pp 300
#define KP 320
#define BT (Bb*Tt)

// ---------------- scratch (device globals; no allocation allowed) ----------
__device__ float g_hidden_hl[(size_t)BT*Hh*2];
__device__ float g_ent_hl[(size_t)Nn*Hh*2];
__device__ float g_W1_hl[(size_t)Hh*Hh*2];
__device__ float g_Wm_hl[(size_t)Pp*Hh*2];
__device__ float g_Wd_hl[(size_t)Pp*Hh*2];
__device__ float g_h[(size_t)BT*Hh];
__device__ float g_pooled_hl[(size_t)BT*Hh*2];
__device__ float g_pm_hl[(size_t)BT*KP*2];
__device__ float g_pd_hl[(size_t)Nn*KP*2];
__device__ float g_sc[(size_t)BT*Nn];
__device__ int   g_pred[BT];
__device__ int   g_rowinfo[BT];
__device__ int   g_nvraw[Bb];
__device__ int   g_dest[Bb];
__device__ int   g_nvout[Bb];
__device__ int   g_rowvalid[Bb];

// ---------------- helpers ----------------------------------------------------
__device__ __forceinline__ uint32_t smem_u32(const void* p){
    uint32_t a;
    asm("{ .reg .u64 t; cvta.to.shared.u64 t, %1; cvt.u32.u64 %0, t; }" : "=r"(a) : "l"(p));
    return a;
}
__device__ __forceinline__ void cp_async16(uint32_t dst, const float* src, bool ok){
    int sz = ok ? 16 : 0;   // src-size 0 -> zero-fill 16B
    asm volatile("cp.async.cg.shared.global [%0], [%1], 16, %2;" :: "r"(dst), "l"(src), "r"(sz));
}
__device__ __forceinline__ void cp_commit(){ asm volatile("cp.async.commit_group;" ::: "memory"); }
template<int N> __device__ __forceinline__ void cp_wait(){ asm volatile("cp.async.wait_group %0;" :: "n"(N) : "memory"); }

__device__ __forceinline__ float trhi(float x){   // tf32-exact hi part
    return __uint_as_float(__float_as_uint(x) & 0xFFFFE000u);
}
__device__ __forceinline__ float2 mk_hl(float v){
    float h = trhi(v);
    float l = v - h;
    uint32_t lr;
    asm("cvt.rna.tf32.f32 %0, %1;" : "=r"(lr) : "f"(l));
    return make_float2(h, __uint_as_float(lr));
}
__device__ __forceinline__ void mma_f(float* d,
    uint32_t a0, uint32_t a1, uint32_t a2, uint32_t a3, uint32_t b0, uint32_t b1){
    asm volatile(
        "mma.sync.aligned.m16n8k8.row.col.f32.tf32.tf32.f32 "
        "{%0,%1,%2,%3}, {%4,%5,%6,%7}, {%8,%9}, {%0,%1,%2,%3};"
        : "+f"(d[0]), "+f"(d[1]), "+f"(d[2]), "+f"(d[3])
        : "r"(a0), "r"(a1), "r"(a2), "r"(a3), "r"(b0), "r"(b1));
}
#define U(x) __float_as_uint(x)

// ---------------- tensor-core 3xTF32 GEMM (pre-split hl operands) -----------
// C[M,N] = A[M,K] @ B[N,K]^T ; A,B are interleaved (hi,lo) float2 arrays.
enum { EP_BIASRELU = 0, EP_PAD = 1, EP_PLAIN = 2 };
#define BKF 16
#define ROWF2 20                      // float2 per smem row (16 data + 4 pad)
#define TILE2 (128*ROWF2)             // float2 per tile
#define SMEMSZ (4*TILE2*8)            // 2 stages x (A+B) x 8B = 81920

template<int EPI, bool ROWMASK>
__global__ void __launch_bounds__(256, 1) mma_gemm(
    const float* __restrict__ A, const float* __restrict__ Bm,
    float* __restrict__ C, int lda, int ldb, int ldc,
    int K, int Nreal, int NBreal,
    const float* __restrict__ bias, const int* __restrict__ nvout)
{
    extern __shared__ float2 sm2[];
    const int m0 = blockIdx.y * 128, n0 = blockIdx.x * 128;
    const int tid = threadIdx.x;
    if (ROWMASK){
        int nv = nvout[m0 >> 9];
        if ((m0 & 511) >= nv) return;   // invalid rows never read downstream
    }
    float2* As[2] = { sm2,           sm2 + TILE2 };
    float2* Bs[2] = { sm2 + 2*TILE2, sm2 + 3*TILE2 };

    const int warp = tid >> 5, lane = tid & 31;
    const int wm = warp & 1, wn = warp >> 1;     // 2 x 4 warp grid
    const int lr = lane >> 2, lc = lane & 3;

    float acc[4][4][4];
    #pragma unroll
    for (int i=0;i<4;i++)
        #pragma unroll
        for (int j=0;j<4;j++)
            #pragma unroll
            for (int q=0;q<4;q++) acc[i][j][q] = 0.f;

    auto load_tile = [&](int kt, int s){
        const int k0 = kt * BKF;
        const uint32_t ab = smem_u32(As[s]);
        const uint32_t bb = smem_u32(Bs[s]);
        #pragma unroll
        for (int j = 0; j < 4; j++){
            int idx = tid + j*256;             // 1024 chunks of 16B per tile
            int row = idx >> 3, q = idx & 7;   // q: 8 x (2 float2) per row
            uint32_t so = (uint32_t)(row*ROWF2 + q*2) * 8u;
            cp_async16(ab + so, A + ((size_t)(m0 + row)*lda + k0 + q*2)*2, true);
            bool ok = (n0 + row) < NBreal;
            const float* bsrc = ok ? (Bm + ((size_t)(n0 + row)*ldb + k0 + q*2)*2) : Bm;
            cp_async16(bb + so, bsrc, ok);
        }
        cp_commit();
    };

    const int nkt = K >> 4;
    load_tile(0, 0);
    for (int kt = 0; kt < nkt; kt++){
        const int s = kt & 1;
        if (kt + 1 < nkt){ load_tile(kt + 1, s ^ 1); cp_wait<1>(); }
        else cp_wait<0>();
        __syncthreads();
        const float2* as = As[s];
        const float2* bs = Bs[s];

        #pragma unroll
        for (int ks = 0; ks < 2; ks++){
            const int kb = ks * 8;
            float2 af[4][4], bf[4][2];
            #pragma unroll
            for (int mt = 0; mt < 4; mt++){
                int r = wm*64 + mt*16 + lr;
                int c = kb + lc;
                af[mt][0] = as[r*ROWF2 + c];
                af[mt][1] = as[(r+8)*ROWF2 + c];
                af[mt][2] = as[r*ROWF2 + c + 4];
                af[mt][3] = as[(r+8)*ROWF2 + c + 4];
            }
            #pragma unroll
            for (int nt = 0; nt < 4; nt++){
                int n = wn*32 + nt*8 + lr;
                int k = kb + lc;
                bf[nt][0] = bs[n*ROWF2 + k];
                bf[nt][1] = bs[n*ROWF2 + k + 4];
            }
            #pragma unroll
            for (int mt = 0; mt < 4; mt++)
                #pragma unroll
                for (int nt = 0; nt < 4; nt++){
                    float* d = acc[mt][nt];
                    // hi*hi, hi*lo, lo*hi
                    mma_f(d, U(af[mt][0].x),U(af[mt][1].x),U(af[mt][2].x),U(af[mt][3].x),
                             U(bf[nt][0].x),U(bf[nt][1].x));
                    mma_f(d, U(af[mt][0].x),U(af[mt][1].x),U(af[mt][2].x),U(af[mt][3].x),
                             U(bf[nt][0].y),U(bf[nt][1].y));
                    mma_f(d, U(af[mt][0].y),U(af[mt][1].y),U(af[mt][2].y),U(af[mt][3].y),
                             U(bf[nt][0].x),U(bf[nt][1].x));
                }
        }
        __syncthreads();
    }

    // epilogue
    #pragma unroll
    for (int mt = 0; mt < 4; mt++){
        #pragma unroll
        for (int nt = 0; nt < 4; nt++){
            int row = m0 + wm*64 + mt*16 + lr;
            int col = n0 + wn*32 + nt*8 + lc*2;
            float* a = acc[mt][nt];
            if (EPI == EP_BIASRELU){
                float b0 = bias[col], b1 = bias[col+1];
                float v0 = a[0] + b0, v1 = a[1] + b1, v2 = a[2] + b0, v3 = a[3] + b1;
                v0 = v0 > 0.f ? v0 : 0.f; v1 = v1 > 0.f ? v1 : 0.f;
                v2 = v2 > 0.f ? v2 : 0.f; v3 = v3 > 0.f ? v3 : 0.f;
                *(float2*)&C[(size_t)row*ldc + col]     = make_float2(v0, v1);
                *(float2*)&C[(size_t)(row+8)*ldc + col] = make_float2(v2, v3);
            } else if (EPI == EP_PLAIN){
                *(float2*)&C[(size_t)row*ldc + col]     = make_float2(a[0], a[1]);
                *(float2*)&C[(size_t)(row+8)*ldc + col] = make_float2(a[2], a[3]);
            } else { // EP_PAD: write interleaved hl, zero pad columns
                if (col + 2 <= ldc){
                    float v0 = (col   < Nreal) ? a[0] : 0.f;
                    float v1 = (col+1 < Nreal) ? a[1] : 0.f;
                    float v2 = (col   < Nreal) ? a[2] : 0.f;
                    float v3 = (col+1 < Nreal) ? a[3] : 0.f;
                    float2 h0 = mk_hl(v0), h1 = mk_hl(v1), h2 = mk_hl(v2), h3 = mk_hl(v3);
                    float4 w0; w0.x=h0.x; w0.y=h0.y; w0.z=h1.x; w0.w=h1.y;
                    float4 w1; w1.x=h2.x; w1.y=h2.y; w1.z=h3.x; w1.w=h3.y;
                    *(float4*)&C[((size_t)row*ldc + col)*2]     = w0;
                    *(float4*)&C[((size_t)(row+8)*ldc + col)*2] = w1;
                }
            }
        }
    }
}

// ---------------- pre-split: x -> interleaved (hi, lo) ------------------------
__global__ void __launch_bounds__(256) split_kernel(
    const float* __restrict__ x, float2* __restrict__ out, int n)
{
    int i = blockIdx.x*256 + threadIdx.x;
    if (i < n) out[i] = mk_hl(x[i]);
}

// ---------------- 3-class head ------------------------------------------------
__global__ void __launch_bounds__(256) logits_kernel(
    const float* __restrict__ h, const float* __restrict__ W2,
    const float* __restrict__ b2, float* __restrict__ out0, int* __restrict__ pred)
{
    __shared__ float w2s[3*Hh];
    int tid = threadIdx.x;
    for (int i = tid; i < 3*Hh; i += 256) w2s[i] = W2[i];
    __syncthreads();
    int warp = tid >> 5, lane = tid & 31;
    int row = blockIdx.x*8 + warp;
    const float* hp = h + (size_t)row*Hh;
    float s0=0.f, s1=0.f, s2=0.f;
    for (int i = lane; i < Hh; i += 32){
        float hv = hp[i];
        s0 += hv*w2s[i]; s1 += hv*w2s[Hh+i]; s2 += hv*w2s[2*Hh+i];
    }
    #pragma unroll
    for (int off=16; off; off>>=1){
        s0 += __shfl_xor_sync(0xffffffffu, s0, off);
        s1 += __shfl_xor_sync(0xffffffffu, s1, off);
        s2 += __shfl_xor_sync(0xffffffffu, s2, off);
    }
    if (lane == 0){
        s0 += b2[0]; s1 += b2[1]; s2 += b2[2];
        float m = fmaxf(s0, fmaxf(s1, s2));
        float lse = m + logf(expf(s0-m)+expf(s1-m)+expf(s2-m));
        size_t o = (size_t)row*3;
        out0[o+0] = s0 - lse; out0[o+1] = s1 - lse; out0[o+2] = s2 - lse;
        int idx = 0; float best = s0;
        if (s1 > best){ best = s1; idx = 1; }
        if (s2 > best){ idx = 2; }
        pred[row] = idx;
    }
}

// ---------------- BIO segment scan (warp-parallel, ballot-based) --------------
__global__ void scan_kernel(const int* __restrict__ labels,
                            int* __restrict__ rowinfo, int* __restrict__ nvraw,
                            int* __restrict__ rowvalid)
{
    __shared__ int pos[513];
    int b = blockIdx.x, lane = threadIdx.x;
    const int* lab = labels + b*Tt;
    int base = 0;
    int first1 = Tt;
    int any2 = 0;          // any '2' strictly before the first '1' (warp-uniform)
    #pragma unroll 1
    for (int c = 0; c < Tt/32; c++){
        int l = lab[c*32 + lane];
        unsigned m1 = __ballot_sync(0xffffffffu, l == 1);
        unsigned m2 = __ballot_sync(0xffffffffu, l == 2);
        if (l == 1) pos[base + __popc(m1 & ((1u<<lane)-1))] = c*32 + lane;
        if (first1 == Tt){
            if (m1){
                int fl = __ffs(m1) - 1;
                first1 = c*32 + fl;
                any2 |= (m2 & ((1u<<fl)-1)) != 0;
            } else any2 |= (m2 != 0);
        }
        base += __popc(m1);
    }
    int m = base;          // total '1's (uniform)
    int lead = any2;       // leading segment exists iff kept tokens precede first '1'
    __syncwarp();
    if (lane == 0){
        pos[m] = Tt;       // sentinel
        if (lead) rowinfo[b*Tt] = (0<<16) | (m ? pos[0] : Tt);
        nvraw[b] = lead + m;
        rowvalid[b] = (lead + m) > 0;
    }
    __syncwarp();
    for (int j = lane; j < m; j += 32){
        int s = pos[j], e = pos[j+1];
        rowinfo[b*Tt + lead + j] = (s<<16) | e;
    }
}

__global__ void combine_kernel(const int* __restrict__ nvraw, const int* __restrict__ rowvalid,
                               int* __restrict__ dest, int* __restrict__ nvout)
{
    if (threadIdx.x || blockIdx.x) return;
    int cnt = 0;
    for (int b=0;b<Bb;b++) dest[b] = rowvalid[b] ? cnt++ : -1;
    for (int b=0;b<Bb;b++) nvout[b] = 0;
    for (int b=0;b<Bb;b++) if (dest[b] >= 0) nvout[dest[b]] = nvraw[b];
}

// ---------------- segment means -> compacted pooled rows (hl interleaved) -----
__global__ void __launch_bounds__(256) pool_kernel(
    const int* __restrict__ labels, const float* __restrict__ hidden,
    const int* __restrict__ rowinfo, const int* __restrict__ nvraw,
    const int* __restrict__ dest, float2* __restrict__ pooled)
{
    int b = blockIdx.x;
    int d = dest[b];
    if (d < 0) return;
    int nv = nvraw[b];
    __shared__ int labs[Tt];
    int tid = threadIdx.x;
    for (int i=tid;i<Tt;i+=256) labs[i] = labels[b*Tt+i];
    __syncthreads();
    int r0 = blockIdx.y * 32;
    int r1 = min(r0+32, nv);
    for (int r=r0; r<r1; r++){
        int info = rowinfo[b*Tt + r];
        int s = info >> 16, e = info & 0xffff;
        float a0=0.f,a1=0.f,a2=0.f;
        int cnt = 0;
        for (int t=s;t<e;t++){
            if (labs[t] != 0){
                cnt++;
                const float* hp = hidden + ((size_t)(b*Tt)+t)*Hh;
                a0 += hp[tid]; a1 += hp[tid+256]; a2 += hp[tid+512];
            }
        }
        float inv = 1.0f / (float)cnt;
        float2* op = pooled + ((size_t)(d*Tt)+r)*Hh;
        op[tid]     = mk_hl(a0*inv);
        op[tid+256] = mk_hl(a1*inv);
        op[tid+512] = mk_hl(a2*inv);
    }
}

// ---------------- row log-softmax over sc ---------------------------------------
__global__ void __launch_bounds__(256) lsm_kernel(
    const float* __restrict__ sc, const int* __restrict__ nvout, float* __restrict__ out)
{
    int row = blockIdx.x*8 + (threadIdx.x >> 5);
    int lane = threadIdx.x & 31;
    int nv = nvout[row >> 9];
    float* op = out + (size_t)row*Nn;
    if ((row & 511) >= nv){
        const float CNEG = -7.6246189861593985f;   // -log(2048)
        float4 c4 = make_float4(CNEG,CNEG,CNEG,CNEG);
        for (int i=lane;i<Nn/4;i+=32) ((float4*)op)[i] = c4;
        return;
    }
    const float4* ip = (const float4*)(sc + (size_t)row*Nn);
    float4 v[16];
    float m = -3.4e38f;
    #pragma unroll
    for (int i=0;i<16;i++){
        v[i] = ip[lane + i*32];
        m = fmaxf(m, fmaxf(fmaxf(v[i].x,v[i].y), fmaxf(v[i].z,v[i].w)));
    }
    #pragma unroll
    for (int off=16;off;off>>=1) m = fmaxf(m, __shfl_xor_sync(0xffffffffu, m, off));
    float s = 0.f;
    #pragma unroll
    for (int i=0;i<16;i++)
        s += expf(v[i].x-m)+expf(v[i].y-m)+expf(v[i].z-m)+expf(v[i].w-m);
    #pragma unroll
    for (int off=16;off;off>>=1) s += __shfl_xor_sync(0xffffffffu, s, off);
    float corr = m + logf(s);
    #pragma unroll
    for (int i=0;i<16;i++){
        float4 o = v[i];
        o.x-=corr; o.y-=corr; o.z-=corr; o.w-=corr;
        ((float4*)op)[lane + i*32] = o;
    }
}

// ---------------- host -----------------------------------------------------------
extern "C" void kernel_launch(void* const* d_in, const int* in_sizes, int n_in,
                              void* d_out, int out_size)
{
    (void)in_sizes; (void)n_in; (void)out_size;
    const int*   labels = (const int*)  d_in[0];
    const float* hidden = (const float*)d_in[1];
    const float* ent    = (const float*)d_in[2];
    const float* W1     = (const float*)d_in[3];
    const float* b1     = (const float*)d_in[4];
    const float* W2     = (const float*)d_in[5];
    const float* b2     = (const float*)d_in[6];
    const float* Wm     = (const float*)d_in[7];
    const float* Wd     = (const float*)d_in[8];

    float* out0 = (float*)d_out;
    float* s1o  = out0 + (size_t)BT*3;
    float* s2o  = s1o  + (size_t)BT*Nn;

    float *hid_hl, *ent_hl, *w1_hl, *wm_hl, *wd_hl;
    float *h, *pooled_hl, *pm_hl, *pd_hl, *sc;
    int *pred, *rowinfo, *nvraw, *dest, *nvout, *rowvalid;
    cudaGetSymbolAddress((void**)&hid_hl,   g_hidden_hl);
    cudaGetSymbolAddress((void**)&ent_hl,   g_ent_hl);
    cudaGetSymbolAddress((void**)&w1_hl,    g_W1_hl);
    cudaGetSymbolAddress((void**)&wm_hl,    g_Wm_hl);
    cudaGetSymbolAddress((void**)&wd_hl,    g_Wd_hl);
    cudaGetSymbolAddress((void**)&h,        g_h);
    cudaGetSymbolAddress((void**)&pooled_hl,g_pooled_hl);
    cudaGetSymbolAddress((void**)&pm_hl,    g_pm_hl);
    cudaGetSymbolAddress((void**)&pd_hl,    g_pd_hl);
    cudaGetSymbolAddress((void**)&sc,       g_sc);
    cudaGetSymbolAddress((void**)&pred,     g_pred);
    cudaGetSymbolAddress((void**)&rowinfo,  g_rowinfo);
    cudaGetSymbolAddress((void**)&nvraw,    g_nvraw);
    cudaGetSymbolAddress((void**)&dest,     g_dest);
    cudaGetSymbolAddress((void**)&nvout,    g_nvout);
    cudaGetSymbolAddress((void**)&rowvalid, g_rowvalid);

    cudaFuncSetAttribute((const void*)mma_gemm<EP_BIASRELU,false>, cudaFuncAttributeMaxDynamicSharedMemorySize, SMEMSZ);
    cudaFuncSetAttribute((const void*)mma_gemm<EP_PAD,false>,      cudaFuncAttributeMaxDynamicSharedMemorySize, SMEMSZ);
    cudaFuncSetAttribute((const void*)mma_gemm<EP_PAD,true>,       cudaFuncAttributeMaxDynamicSharedMemorySize, SMEMSZ);
    cudaFuncSetAttribute((const void*)mma_gemm<EP_PLAIN,true>,     cudaFuncAttributeMaxDynamicSharedMemorySize, SMEMSZ);

    // 0) pre-split all static operands into interleaved (hi,lo)
    split_kernel<<<(BT*Hh+255)/256, 256>>>(hidden, (float2*)hid_hl, BT*Hh);
    split_kernel<<<(Nn*Hh+255)/256, 256>>>(ent,    (float2*)ent_hl, Nn*Hh);
    split_kernel<<<(Hh*Hh+255)/256, 256>>>(W1,     (float2*)w1_hl,  Hh*Hh);
    split_kernel<<<(Pp*Hh+255)/256, 256>>>(Wm,     (float2*)wm_hl,  Pp*Hh);
    split_kernel<<<(Pp*Hh+255)/256, 256>>>(Wd,     (float2*)wd_hl,  Pp*Hh);

    // 1) h = relu(x @ W1^T + b1)
    mma_gemm<EP_BIASRELU,false><<<dim3(Hh/128, BT/128), 256, SMEMSZ>>>(
        hid_hl, w1_hl, h, Hh, Hh, Hh, Hh, Hh, Hh, b1, nullptr);

    // 2) bio logits -> out0 + predicted labels
    logits_kernel<<<BT/8, 256>>>(h, W2, b2, out0, pred);

    // 3) pd = ent @ Wd^T, K-padded to KP, hl-interleaved output
    mma_gemm<EP_PAD,false><<<dim3(3, Nn/128), 256, SMEMSZ>>>(
        ent_hl, wd_hl, pd_hl, Hh, Hh, KP, Hh, Pp, Pp, nullptr, nullptr);

    // 4/5) two pooling passes: gold labels, then predicted
    for (int pass = 0; pass < 2; pass++){
        const int* lsrc = (pass == 0) ? labels : pred;
        float* so = (pass == 0) ? s1o : s2o;

        scan_kernel<<<Bb, 32>>>(lsrc, rowinfo, nvraw, rowvalid);
        combine_kernel<<<1, 1>>>(nvraw, rowvalid, dest, nvout);
        pool_kernel<<<dim3(Bb, 16), 256>>>(lsrc, hidden, rowinfo, nvraw, dest, (float2*)pooled_hl);

        mma_gemm<EP_PAD,true><<<dim3(3, BT/128), 256, SMEMSZ>>>(
            pooled_hl, wm_hl, pm_hl, Hh, Hh, KP, Hh, Pp, Pp, nullptr, nvout);

        mma_gemm<EP_PLAIN,true><<<dim3(Nn/128, BT/128), 256, SMEMSZ>>>(
            pm_hl, pd_hl, sc, KP, KP, Nn, KP, Nn, Nn, nullptr, nvout);

        lsm_kernel<<<BT/8, 256>>>(sc, nvout, so);
    }
}

// round 6
// speedup vs baseline: 2.2095x; 2.2095x over previous
#include <cuda_runtime.h>
#include <cuda_fp16.h>
#include <math.h>
#include <stdint.h>

#define Bb 64
#define Tt 512
#define Hh 768
#define Nn 2048
#define Pp 300
#define KP 320
#define BT (Bb*Tt)

// ---------------- scratch (device globals; no allocation allowed) ----------
__device__ __half g_hid_h[(size_t)BT*Hh],  g_hid_l[(size_t)BT*Hh];
__device__ __half g_ent_h[(size_t)Nn*Hh],  g_ent_l[(size_t)Nn*Hh];
__device__ __half g_W1_h[Hh*Hh],           g_W1_l[Hh*Hh];
__device__ __half g_Wm_h[Pp*Hh],           g_Wm_l[Pp*Hh];
__device__ __half g_Wd_h[Pp*Hh],           g_Wd_l[Pp*Hh];
__device__ __half g_pool_h[(size_t)BT*Hh], g_pool_l[(size_t)BT*Hh];
__device__ __half g_pm_h[(size_t)BT*KP],   g_pm_l[(size_t)BT*KP];
__device__ __half g_pd_h[(size_t)Nn*KP],   g_pd_l[(size_t)Nn*KP];
__device__ float  g_h[(size_t)BT*Hh];
__device__ float  g_sc[(size_t)BT*Nn];
__device__ int    g_pred[BT];
__device__ int    g_rowinfo[BT];
__device__ int    g_nvraw[Bb];
__device__ int    g_dest[Bb];
__device__ int    g_nvout[Bb];
__device__ int    g_rowvalid[Bb];

// ---------------- helpers ----------------------------------------------------
__device__ __forceinline__ uint32_t smem_u32(const void* p){
    uint32_t a;
    asm("{ .reg .u64 t; cvta.to.shared.u64 t, %1; cvt.u32.u64 %0, t; }" : "=r"(a) : "l"(p));
    return a;
}
__device__ __forceinline__ void cp_async16(uint32_t dst, const void* src, bool ok){
    int sz = ok ? 16 : 0;   // src-size 0 -> zero-fill 16B
    asm volatile("cp.async.cg.shared.global [%0], [%1], 16, %2;" :: "r"(dst), "l"(src), "r"(sz));
}
__device__ __forceinline__ void cp_commit(){ asm volatile("cp.async.commit_group;" ::: "memory"); }
template<int N> __device__ __forceinline__ void cp_wait(){ asm volatile("cp.async.wait_group %0;" :: "n"(N) : "memory"); }

__device__ __forceinline__ void ldsm4(uint32_t* r, uint32_t addr){
    asm volatile("ldmatrix.sync.aligned.m8n8.x4.shared.b16 {%0,%1,%2,%3}, [%4];"
        : "=r"(r[0]), "=r"(r[1]), "=r"(r[2]), "=r"(r[3]) : "r"(addr));
}
__device__ __forceinline__ void mma16(float* d, const uint32_t* a, uint32_t b0, uint32_t b1){
    asm volatile(
        "mma.sync.aligned.m16n8k16.row.col.f32.f16.f16.f32 "
        "{%0,%1,%2,%3}, {%4,%5,%6,%7}, {%8,%9}, {%0,%1,%2,%3};"
        : "+f"(d[0]), "+f"(d[1]), "+f"(d[2]), "+f"(d[3])
        : "r"(a[0]), "r"(a[1]), "r"(a[2]), "r"(a[3]), "r"(b0), "r"(b1));
}
__device__ __forceinline__ void split16(float v, __half& h, __half& l){
    h = __float2half_rn(v);
    l = __float2half_rn(v - __half2float(h));
}

// ---------------- fp16 3-term GEMM: C[M,N] = A[M,K] @ B[N,K]^T ---------------
// A, B given as separate hi/lo half planes. 128x128 CTA tile, BK=32, 8 warps.
enum { EP_BIASRELU = 0, EP_PAD = 1, EP_PLAIN = 2 };
#define SMEMSZ 65536   // 2 stages x 4 planes x 8KB

template<int EPI, bool ROWMASK>
__global__ void __launch_bounds__(256, 1) mma_gemm(
    const __half* __restrict__ Ah, const __half* __restrict__ Al,
    const __half* __restrict__ Bh, const __half* __restrict__ Bl,
    float* __restrict__ C, __half* __restrict__ Ch, __half* __restrict__ Cl,
    int lda, int ldb, int ldc, int K, int Nreal, int NBreal,
    const float* __restrict__ bias, const int* __restrict__ nvout)
{
    extern __shared__ char smem[];
    const int m0 = blockIdx.y * 128, n0 = blockIdx.x * 128;
    const int tid = threadIdx.x;
    if (ROWMASK){
        int nv = nvout[m0 >> 9];
        if ((m0 & 511) >= nv) return;   // invalid rows never read downstream
    }
    const uint32_t sb0 = smem_u32(smem);
    const int warp = tid >> 5, lane = tid & 31;
    const int wm = warp & 1, wn = warp >> 1;     // 2 x 4 warp grid, warp tile 64x32
    const int lr = lane >> 2, lc = lane & 3;

    float acc[4][4][4];
    #pragma unroll
    for (int i=0;i<4;i++)
        #pragma unroll
        for (int j=0;j<4;j++)
            #pragma unroll
            for (int q=0;q<4;q++) acc[i][j][q] = 0.f;

    // ldmatrix base offsets (stage 0, hi plane, ks=0); toggle ks via ^32, lo via +8192
    const int arl = (lane & 7) + ((lane >> 3) & 1) * 8;   // row-in-16
    const int acs = lane >> 4;                            // k-chunk select
    const int nrl = (lane & 7) + (lane >> 4) * 8;
    const int bcs = (lane >> 3) & 1;
    uint32_t aoff[4], boff[2];
    #pragma unroll
    for (int mt = 0; mt < 4; mt++){
        int r = wm*64 + mt*16 + arl;
        aoff[mt] = (uint32_t)(r*64) + (uint32_t)((acs ^ (r & 3) ^ ((r >> 2) & 1)) << 4);
    }
    #pragma unroll
    for (int nb = 0; nb < 2; nb++){
        int r = wn*32 + nb*16 + nrl;
        boff[nb] = 16384u + (uint32_t)(r*64) + (uint32_t)((bcs ^ (r & 3) ^ ((r >> 2) & 1)) << 4);
    }

    auto load_tile = [&](int kt, int s){
        const int k0 = kt * 32;
        const uint32_t sbs = sb0 + (uint32_t)s * 32768u;
        #pragma unroll
        for (int j = 0; j < 8; j++){
            int idx = tid + j*256;
            int pl  = idx >> 9;             // 0:Ah 1:Al 2:Bh 3:Bl
            int rem = idx & 511;
            int row = rem >> 2, c = rem & 3;
            int c2  = c ^ (row & 3) ^ ((row >> 2) & 1);
            uint32_t so = sbs + (uint32_t)(pl*8192 + row*64 + c2*16);
            if (pl < 2){
                const __half* src = (pl ? Al : Ah) + (size_t)(m0 + row)*lda + k0 + c*8;
                cp_async16(so, src, true);
            } else {
                bool ok = (n0 + row) < NBreal;
                const __half* base = (pl == 2) ? Bh : Bl;
                const __half* src = ok ? (base + (size_t)(n0 + row)*ldb + k0 + c*8) : base;
                cp_async16(so, src, ok);
            }
        }
        cp_commit();
    };

    const int nkt = K >> 5;
    load_tile(0, 0);
    for (int kt = 0; kt < nkt; kt++){
        const int s = kt & 1;
        if (kt + 1 < nkt){ load_tile(kt + 1, s ^ 1); cp_wait<1>(); }
        else cp_wait<0>();
        __syncthreads();
        const uint32_t sbs = sb0 + (uint32_t)s * 32768u;

        #pragma unroll
        for (int ks = 0; ks < 2; ks++){
            const uint32_t kx = (uint32_t)(ks << 5);
            uint32_t ah[4][4], al[4][4], bh[2][4], bl[2][4];
            #pragma unroll
            for (int mt = 0; mt < 4; mt++){
                uint32_t t = (sbs + aoff[mt]) ^ kx;
                ldsm4(ah[mt], t);
                ldsm4(al[mt], t + 8192);
            }
            #pragma unroll
            for (int nb = 0; nb < 2; nb++){
                uint32_t t = (sbs + boff[nb]) ^ kx;
                ldsm4(bh[nb], t);
                ldsm4(bl[nb], t + 8192);
            }
            #pragma unroll
            for (int mt = 0; mt < 4; mt++)
                #pragma unroll
                for (int nt = 0; nt < 4; nt++){
                    const int nb = nt >> 1, p = (nt & 1) * 2;
                    float* d = acc[mt][nt];
                    mma16(d, ah[mt], bh[nb][p], bh[nb][p+1]);   // hi*hi
                    mma16(d, ah[mt], bl[nb][p], bl[nb][p+1]);   // hi*lo
                    mma16(d, al[mt], bh[nb][p], bh[nb][p+1]);   // lo*hi
                }
        }
        __syncthreads();
    }

    // epilogue: registers -> gmem
    #pragma unroll
    for (int mt = 0; mt < 4; mt++){
        #pragma unroll
        for (int nt = 0; nt < 4; nt++){
            int row = m0 + wm*64 + mt*16 + lr;
            int col = n0 + wn*32 + nt*8 + lc*2;
            float* a = acc[mt][nt];
            if (EPI == EP_BIASRELU){
                float b0 = bias[col], b1 = bias[col+1];
                float v0 = a[0] + b0, v1 = a[1] + b1, v2 = a[2] + b0, v3 = a[3] + b1;
                v0 = v0 > 0.f ? v0 : 0.f; v1 = v1 > 0.f ? v1 : 0.f;
                v2 = v2 > 0.f ? v2 : 0.f; v3 = v3 > 0.f ? v3 : 0.f;
                *(float2*)&C[(size_t)row*ldc + col]     = make_float2(v0, v1);
                *(float2*)&C[(size_t)(row+8)*ldc + col] = make_float2(v2, v3);
            } else if (EPI == EP_PLAIN){
                *(float2*)&C[(size_t)row*ldc + col]     = make_float2(a[0], a[1]);
                *(float2*)&C[(size_t)(row+8)*ldc + col] = make_float2(a[2], a[3]);
            } else { // EP_PAD: half hi/lo planes, zero pad columns
                if (col + 2 <= ldc){
                    float v0 = (col   < Nreal) ? a[0] : 0.f;
                    float v1 = (col+1 < Nreal) ? a[1] : 0.f;
                    float v2 = (col   < Nreal) ? a[2] : 0.f;
                    float v3 = (col+1 < Nreal) ? a[3] : 0.f;
                    __half h0,l0,h1,l1,h2,l2,h3,l3;
                    split16(v0,h0,l0); split16(v1,h1,l1);
                    split16(v2,h2,l2); split16(v3,h3,l3);
                    *(__half2*)&Ch[(size_t)row*ldc + col]     = __halves2half2(h0, h1);
                    *(__half2*)&Cl[(size_t)row*ldc + col]     = __halves2half2(l0, l1);
                    *(__half2*)&Ch[(size_t)(row+8)*ldc + col] = __halves2half2(h2, h3);
                    *(__half2*)&Cl[(size_t)(row+8)*ldc + col] = __halves2half2(l2, l3);
                }
            }
        }
    }
}

// ---------------- fp32 -> fp16 hi/lo split ------------------------------------
__global__ void __launch_bounds__(256) split_kernel(
    const float* __restrict__ x, __half* __restrict__ h, __half* __restrict__ l, int n)
{
    int i = blockIdx.x*256 + threadIdx.x;
    if (i < n){ __half hv, lv; split16(x[i], hv, lv); h[i] = hv; l[i] = lv; }
}

// ---------------- 3-class head --------------------------------------------------
__global__ void __launch_bounds__(256) logits_kernel(
    const float* __restrict__ h, const float* __restrict__ W2,
    const float* __restrict__ b2, float* __restrict__ out0, int* __restrict__ pred)
{
    __shared__ float w2s[3*Hh];
    int tid = threadIdx.x;
    for (int i = tid; i < 3*Hh; i += 256) w2s[i] = W2[i];
    __syncthreads();
    int warp = tid >> 5, lane = tid & 31;
    int row = blockIdx.x*8 + warp;
    const float* hp = h + (size_t)row*Hh;
    float s0=0.f, s1=0.f, s2=0.f;
    for (int i = lane; i < Hh; i += 32){
        float hv = hp[i];
        s0 += hv*w2s[i]; s1 += hv*w2s[Hh+i]; s2 += hv*w2s[2*Hh+i];
    }
    #pragma unroll
    for (int off=16; off; off>>=1){
        s0 += __shfl_xor_sync(0xffffffffu, s0, off);
        s1 += __shfl_xor_sync(0xffffffffu, s1, off);
        s2 += __shfl_xor_sync(0xffffffffu, s2, off);
    }
    if (lane == 0){
        s0 += b2[0]; s1 += b2[1]; s2 += b2[2];
        float m = fmaxf(s0, fmaxf(s1, s2));
        float lse = m + logf(expf(s0-m)+expf(s1-m)+expf(s2-m));
        size_t o = (size_t)row*3;
        out0[o+0] = s0 - lse; out0[o+1] = s1 - lse; out0[o+2] = s2 - lse;
        int idx = 0; float best = s0;
        if (s1 > best){ best = s1; idx = 1; }
        if (s2 > best){ idx = 2; }
        pred[row] = idx;
    }
}

// ---------------- BIO segment scan (warp-parallel, ballot-based) ----------------
__global__ void scan_kernel(const int* __restrict__ labels,
                            int* __restrict__ rowinfo, int* __restrict__ nvraw,
                            int* __restrict__ rowvalid)
{
    __shared__ int pos[513];
    int b = blockIdx.x, lane = threadIdx.x;
    const int* lab = labels + b*Tt;
    int base = 0;
    int first1 = Tt;
    int any2 = 0;
    #pragma unroll 1
    for (int c = 0; c < Tt/32; c++){
        int l = lab[c*32 + lane];
        unsigned m1 = __ballot_sync(0xffffffffu, l == 1);
        unsigned m2 = __ballot_sync(0xffffffffu, l == 2);
        if (l == 1) pos[base + __popc(m1 & ((1u<<lane)-1))] = c*32 + lane;
        if (first1 == Tt){
            if (m1){
                int fl = __ffs(m1) - 1;
                first1 = c*32 + fl;
                any2 |= (m2 & ((1u<<fl)-1)) != 0;
            } else any2 |= (m2 != 0);
        }
        base += __popc(m1);
    }
    int m = base;
    int lead = any2;
    __syncwarp();
    if (lane == 0){
        pos[m] = Tt;
        if (lead) rowinfo[b*Tt] = (0<<16) | (m ? pos[0] : Tt);
        nvraw[b] = lead + m;
        rowvalid[b] = (lead + m) > 0;
    }
    __syncwarp();
    for (int j = lane; j < m; j += 32){
        int s = pos[j], e = pos[j+1];
        rowinfo[b*Tt + lead + j] = (s<<16) | e;
    }
}

__global__ void combine_kernel(const int* __restrict__ nvraw, const int* __restrict__ rowvalid,
                               int* __restrict__ dest, int* __restrict__ nvout)
{
    if (threadIdx.x || blockIdx.x) return;
    int cnt = 0;
    for (int b=0;b<Bb;b++) dest[b] = rowvalid[b] ? cnt++ : -1;
    for (int b=0;b<Bb;b++) nvout[b] = 0;
    for (int b=0;b<Bb;b++) if (dest[b] >= 0) nvout[dest[b]] = nvraw[b];
}

// ---------------- segment means -> compacted pooled rows (hi/lo half planes) ----
__global__ void __launch_bounds__(256) pool_kernel(
    const int* __restrict__ labels, const float* __restrict__ hidden,
    const int* __restrict__ rowinfo, const int* __restrict__ nvraw,
    const int* __restrict__ dest, __half* __restrict__ ph, __half* __restrict__ pl)
{
    int b = blockIdx.x;
    int d = dest[b];
    if (d < 0) return;
    int nv = nvraw[b];
    __shared__ int labs[Tt];
    int tid = threadIdx.x;
    for (int i=tid;i<Tt;i+=256) labs[i] = labels[b*Tt+i];
    __syncthreads();
    int r0 = blockIdx.y * 32;
    int r1 = min(r0+32, nv);
    for (int r=r0; r<r1; r++){
        int info = rowinfo[b*Tt + r];
        int s = info >> 16, e = info & 0xffff;
        float a0=0.f,a1=0.f,a2=0.f;
        int cnt = 0;
        for (int t=s;t<e;t++){
            if (labs[t] != 0){
                cnt++;
                const float* hp = hidden + ((size_t)(b*Tt)+t)*Hh;
                a0 += hp[tid]; a1 += hp[tid+256]; a2 += hp[tid+512];
            }
        }
        float inv = 1.0f / (float)cnt;
        size_t off = ((size_t)(d*Tt)+r)*Hh;
        __half hv, lv;
        split16(a0*inv, hv, lv); ph[off+tid]     = hv; pl[off+tid]     = lv;
        split16(a1*inv, hv, lv); ph[off+tid+256] = hv; pl[off+tid+256] = lv;
        split16(a2*inv, hv, lv); ph[off+tid+512] = hv; pl[off+tid+512] = lv;
    }
}

// ---------------- row log-softmax over sc ----------------------------------------
__global__ void __launch_bounds__(256) lsm_kernel(
    const float* __restrict__ sc, const int* __restrict__ nvout, float* __restrict__ out)
{
    int row = blockIdx.x*8 + (threadIdx.x >> 5);
    int lane = threadIdx.x & 31;
    int nv = nvout[row >> 9];
    float* op = out + (size_t)row*Nn;
    if ((row & 511) >= nv){
        const float CNEG = -7.6246189861593985f;   // -log(2048)
        float4 c4 = make_float4(CNEG,CNEG,CNEG,CNEG);
        for (int i=lane;i<Nn/4;i+=32) ((float4*)op)[i] = c4;
        return;
    }
    const float4* ip = (const float4*)(sc + (size_t)row*Nn);
    float4 v[16];
    float m = -3.4e38f;
    #pragma unroll
    for (int i=0;i<16;i++){
        v[i] = ip[lane + i*32];
        m = fmaxf(m, fmaxf(fmaxf(v[i].x,v[i].y), fmaxf(v[i].z,v[i].w)));
    }
    #pragma unroll
    for (int off=16;off;off>>=1) m = fmaxf(m, __shfl_xor_sync(0xffffffffu, m, off));
    float s = 0.f;
    #pragma unroll
    for (int i=0;i<16;i++)
        s += expf(v[i].x-m)+expf(v[i].y-m)+expf(v[i].z-m)+expf(v[i].w-m);
    #pragma unroll
    for (int off=16;off;off>>=1) s += __shfl_xor_sync(0xffffffffu, s, off);
    float corr = m + logf(s);
    #pragma unroll
    for (int i=0;i<16;i++){
        float4 o = v[i];
        o.x-=corr; o.y-=corr; o.z-=corr; o.w-=corr;
        ((float4*)op)[lane + i*32] = o;
    }
}

// ---------------- host -------------------------------------------------------------
extern "C" void kernel_launch(void* const* d_in, const int* in_sizes, int n_in,
                              void* d_out, int out_size)
{
    (void)in_sizes; (void)n_in; (void)out_size;
    const int*   labels = (const int*)  d_in[0];
    const float* hidden = (const float*)d_in[1];
    const float* ent    = (const float*)d_in[2];
    const float* W1     = (const float*)d_in[3];
    const float* b1     = (const float*)d_in[4];
    const float* W2     = (const float*)d_in[5];
    const float* b2     = (const float*)d_in[6];
    const float* Wm     = (const float*)d_in[7];
    const float* Wd     = (const float*)d_in[8];

    float* out0 = (float*)d_out;
    float* s1o  = out0 + (size_t)BT*3;
    float* s2o  = s1o  + (size_t)BT*Nn;

    __half *hidh,*hidl,*enth,*entl,*w1h,*w1l,*wmh,*wml,*wdh,*wdl;
    __half *poolh,*pooll,*pmh,*pml,*pdh,*pdl;
    float *h, *sc;
    int *pred, *rowinfo, *nvraw, *dest, *nvout, *rowvalid;
    cudaGetSymbolAddress((void**)&hidh, g_hid_h);  cudaGetSymbolAddress((void**)&hidl, g_hid_l);
    cudaGetSymbolAddress((void**)&enth, g_ent_h);  cudaGetSymbolAddress((void**)&entl, g_ent_l);
    cudaGetSymbolAddress((void**)&w1h,  g_W1_h);   cudaGetSymbolAddress((void**)&w1l,  g_W1_l);
    cudaGetSymbolAddress((void**)&wmh,  g_Wm_h);   cudaGetSymbolAddress((void**)&wml,  g_Wm_l);
    cudaGetSymbolAddress((void**)&wdh,  g_Wd_h);   cudaGetSymbolAddress((void**)&wdl,  g_Wd_l);
    cudaGetSymbolAddress((void**)&poolh,g_pool_h); cudaGetSymbolAddress((void**)&pooll,g_pool_l);
    cudaGetSymbolAddress((void**)&pmh,  g_pm_h);   cudaGetSymbolAddress((void**)&pml,  g_pm_l);
    cudaGetSymbolAddress((void**)&pdh,  g_pd_h);   cudaGetSymbolAddress((void**)&pdl,  g_pd_l);
    cudaGetSymbolAddress((void**)&h,    g_h);
    cudaGetSymbolAddress((void**)&sc,   g_sc);
    cudaGetSymbolAddress((void**)&pred, g_pred);
    cudaGetSymbolAddress((void**)&rowinfo, g_rowinfo);
    cudaGetSymbolAddress((void**)&nvraw,   g_nvraw);
    cudaGetSymbolAddress((void**)&dest,    g_dest);
    cudaGetSymbolAddress((void**)&nvout,   g_nvout);
    cudaGetSymbolAddress((void**)&rowvalid,g_rowvalid);

    cudaFuncSetAttribute((const void*)mma_gemm<EP_BIASRELU,false>, cudaFuncAttributeMaxDynamicSharedMemorySize, SMEMSZ);
    cudaFuncSetAttribute((const void*)mma_gemm<EP_PAD,false>,      cudaFuncAttributeMaxDynamicSharedMemorySize, SMEMSZ);
    cudaFuncSetAttribute((const void*)mma_gemm<EP_PAD,true>,       cudaFuncAttributeMaxDynamicSharedMemorySize, SMEMSZ);
    cudaFuncSetAttribute((const void*)mma_gemm<EP_PLAIN,true>,     cudaFuncAttributeMaxDynamicSharedMemorySize, SMEMSZ);

    // launches 1-3: splits needed by gemm1; launch 4 = gemm1 (ncu capture slot)
    split_kernel<<<(BT*Hh+255)/256, 256>>>(hidden, hidh, hidl, BT*Hh);
    split_kernel<<<(Hh*Hh+255)/256, 256>>>(W1, w1h, w1l, Hh*Hh);
    split_kernel<<<(Nn*Hh+255)/256, 256>>>(ent, enth, entl, Nn*Hh);

    // 1) h = relu(x @ W1^T + b1)
    mma_gemm<EP_BIASRELU,false><<<dim3(Hh/128, BT/128), 256, SMEMSZ>>>(
        hidh, hidl, w1h, w1l, h, nullptr, nullptr, Hh, Hh, Hh, Hh, Hh, Hh, b1, nullptr);

    split_kernel<<<(Pp*Hh+255)/256, 256>>>(Wm, wmh, wml, Pp*Hh);
    split_kernel<<<(Pp*Hh+255)/256, 256>>>(Wd, wdh, wdl, Pp*Hh);

    // 2) bio logits -> out0 + predicted labels
    logits_kernel<<<BT/8, 256>>>(h, W2, b2, out0, pred);

    // 3) pd = ent @ Wd^T -> half hi/lo planes, K-padded to KP
    mma_gemm<EP_PAD,false><<<dim3(3, Nn/128), 256, SMEMSZ>>>(
        enth, entl, wdh, wdl, nullptr, pdh, pdl, Hh, Hh, KP, Hh, Pp, Pp, nullptr, nullptr);

    // 4/5) two pooling passes: gold labels, then predicted
    for (int pass = 0; pass < 2; pass++){
        const int* lsrc = (pass == 0) ? labels : pred;
        float* so = (pass == 0) ? s1o : s2o;

        scan_kernel<<<Bb, 32>>>(lsrc, rowinfo, nvraw, rowvalid);
        combine_kernel<<<1, 1>>>(nvraw, rowvalid, dest, nvout);
        pool_kernel<<<dim3(Bb, 16), 256>>>(lsrc, hidden, rowinfo, nvraw, dest, poolh, pooll);

        mma_gemm<EP_PAD,true><<<dim3(3, BT/128), 256, SMEMSZ>>>(
            poolh, pooll, wmh, wml, nullptr, pmh, pml, Hh, Hh, KP, Hh, Pp, Pp, nullptr, nvout);

        mma_gemm<EP_PLAIN,true><<<dim3(Nn/128, BT/128), 256, SMEMSZ>>>(
            pmh, pml, pdh, pdl, sc, nullptr, nullptr, KP, KP, Nn, KP, Nn, Nn, nullptr, nvout);

        lsm_kernel<<<BT/8, 256>>>(sc, nvout, so);
    }
}

// round 7
// speedup vs baseline: 2.2718x; 1.0282x over previous
#include <cuda_runtime.h>
#include <cuda_fp16.h>
#include <math.h>
#include <stdint.h>

#define Bb 64
#define Tt 512
#define Hh 768
#define Nn 2048
#define Pp 300
#define KP 320
#define BT (Bb*Tt)

// ---------------- scratch (device globals; no allocation allowed) ----------
__device__ __half g_hid_h[(size_t)BT*Hh],  g_hid_l[(size_t)BT*Hh];
__device__ __half g_ent_h[(size_t)Nn*Hh],  g_ent_l[(size_t)Nn*Hh];
__device__ __half g_W1_h[Hh*Hh],           g_W1_l[Hh*Hh];
__device__ __half g_Wm_h[Pp*Hh],           g_Wm_l[Pp*Hh];
__device__ __half g_Wd_h[Pp*Hh],           g_Wd_l[Pp*Hh];
__device__ __half g_pool_h[(size_t)BT*Hh], g_pool_l[(size_t)BT*Hh];
__device__ __half g_pm_h[(size_t)BT*KP],   g_pm_l[(size_t)BT*KP];
__device__ __half g_pd_h[(size_t)Nn*KP],   g_pd_l[(size_t)Nn*KP];
__device__ float  g_h[(size_t)BT*Hh];
__device__ float  g_sc[(size_t)BT*Nn];
__device__ int    g_pred[BT];
__device__ int    g_rowinfo[BT];
__device__ int    g_nvraw[Bb];
__device__ int    g_dest[Bb];
__device__ int    g_nvout[Bb];
__device__ int    g_rowvalid[Bb];

// ---------------- helpers ----------------------------------------------------
__device__ __forceinline__ uint32_t smem_u32(const void* p){
    uint32_t a;
    asm("{ .reg .u64 t; cvta.to.shared.u64 t, %1; cvt.u32.u64 %0, t; }" : "=r"(a) : "l"(p));
    return a;
}
__device__ __forceinline__ void cp_async16(uint32_t dst, const void* src, bool ok){
    int sz = ok ? 16 : 0;   // src-size 0 -> zero-fill 16B
    asm volatile("cp.async.cg.shared.global [%0], [%1], 16, %2;" :: "r"(dst), "l"(src), "r"(sz));
}
__device__ __forceinline__ void cp_commit(){ asm volatile("cp.async.commit_group;" ::: "memory"); }
template<int N> __device__ __forceinline__ void cp_wait(){ asm volatile("cp.async.wait_group %0;" :: "n"(N) : "memory"); }

__device__ __forceinline__ void ldsm4(uint32_t* r, uint32_t addr){
    asm volatile("ldmatrix.sync.aligned.m8n8.x4.shared.b16 {%0,%1,%2,%3}, [%4];"
        : "=r"(r[0]), "=r"(r[1]), "=r"(r[2]), "=r"(r[3]) : "r"(addr));
}
__device__ __forceinline__ void mma16(float* d, const uint32_t* a, uint32_t b0, uint32_t b1){
    asm volatile(
        "mma.sync.aligned.m16n8k16.row.col.f32.f16.f16.f32 "
        "{%0,%1,%2,%3}, {%4,%5,%6,%7}, {%8,%9}, {%0,%1,%2,%3};"
        : "+f"(d[0]), "+f"(d[1]), "+f"(d[2]), "+f"(d[3])
        : "r"(a[0]), "r"(a[1]), "r"(a[2]), "r"(a[3]), "r"(b0), "r"(b1));
}
__device__ __forceinline__ void split16(float v, __half& h, __half& l){
    h = __float2half_rn(v);
    l = __float2half_rn(v - __half2float(h));
}

// ---------------- fp16 3-term GEMM: C[M,N] = A[M,K] @ B[N,K]^T ---------------
// CTA tile 256x128, BK=32, 8 warps (4m x 2n), warp tile 64x64, 3-stage cp.async.
enum { EP_BIASRELU = 0, EP_PAD = 1, EP_PLAIN = 2 };
#define ST_ALO 16384
#define ST_B   32768
#define ST_BLO 8192      // relative to ST_B
#define STAGE  49152
#define SMEMSZ (3*STAGE) // 147456

template<int EPI, bool ROWMASK>
__global__ void __launch_bounds__(256, 1) mma_gemm(
    const __half* __restrict__ Ah, const __half* __restrict__ Al,
    const __half* __restrict__ Bh, const __half* __restrict__ Bl,
    float* __restrict__ C, __half* __restrict__ Ch, __half* __restrict__ Cl,
    int lda, int ldb, int ldc, int K, int Nreal, int NBreal,
    const float* __restrict__ bias, const int* __restrict__ nvout)
{
    extern __shared__ char smem[];
    const int m0 = blockIdx.y * 256, n0 = blockIdx.x * 128;
    const int tid = threadIdx.x;
    if (ROWMASK){
        int nv = nvout[m0 >> 9];
        if ((m0 & 511) >= nv) return;   // invalid rows never read downstream
    }
    const uint32_t sb0 = smem_u32(smem);
    const int warp = tid >> 5, lane = tid & 31;
    const int wm = warp >> 1, wn = warp & 1;     // 4 x 2 warp grid, warp tile 64x64
    const int lr = lane >> 2, lc = lane & 3;

    float acc[4][8][4];
    #pragma unroll
    for (int i=0;i<4;i++)
        #pragma unroll
        for (int j=0;j<8;j++)
            #pragma unroll
            for (int q=0;q<4;q++) acc[i][j][q] = 0.f;

    // ldmatrix base offsets (stage-relative); toggle ks via ^32, lo plane via +offset
    const int arl = (lane & 7) + ((lane >> 3) & 1) * 8;
    const int acs = lane >> 4;
    const int nrl = (lane & 7) + (lane >> 4) * 8;
    const int bcs = (lane >> 3) & 1;
    uint32_t aoff[4], boff[4];
    #pragma unroll
    for (int mt = 0; mt < 4; mt++){
        int r = wm*64 + mt*16 + arl;
        aoff[mt] = (uint32_t)(r*64) + (uint32_t)((acs ^ (r & 3) ^ ((r >> 2) & 1)) << 4);
    }
    #pragma unroll
    for (int nb = 0; nb < 4; nb++){
        int r = wn*64 + nb*16 + nrl;
        boff[nb] = (uint32_t)ST_B + (uint32_t)(r*64) + (uint32_t)((bcs ^ (r & 3) ^ ((r >> 2) & 1)) << 4);
    }

    auto load_tile = [&](int kt, int s){
        const int k0 = kt * 32;
        const uint32_t sbs = sb0 + (uint32_t)s * STAGE;
        #pragma unroll
        for (int j = 0; j < 12; j++){
            int idx = tid + j*256;                 // 0..3071 16B-chunks
            if (idx < 2048){                        // A planes: 256 rows x 4 chunks x2
                int pl  = idx >> 10;
                int rem = idx & 1023;
                int row = rem >> 2, c = rem & 3;
                int c2  = c ^ (row & 3) ^ ((row >> 2) & 1);
                uint32_t so = sbs + (uint32_t)(pl*ST_ALO + row*64 + c2*16);
                const __half* src = (pl ? Al : Ah) + (size_t)(m0 + row)*lda + k0 + c*8;
                cp_async16(so, src, true);
            } else {                                // B planes: 128 rows x 4 chunks x2
                int b   = idx - 2048;
                int pl  = b >> 9;
                int rem = b & 511;
                int row = rem >> 2, c = rem & 3;
                int c2  = c ^ (row & 3) ^ ((row >> 2) & 1);
                uint32_t so = sbs + (uint32_t)(ST_B + pl*ST_BLO + row*64 + c2*16);
                bool ok = (n0 + row) < NBreal;
                const __half* base = pl ? Bl : Bh;
                const __half* src = ok ? (base + (size_t)(n0 + row)*ldb + k0 + c*8) : base;
                cp_async16(so, src, ok);
            }
        }
        cp_commit();
    };

    const int nkt = K >> 5;
    load_tile(0, 0);
    if (nkt > 1) load_tile(1, 1);
    for (int kt = 0; kt < nkt; kt++){
        const int s = kt % 3;
        if (kt + 1 < nkt) cp_wait<1>(); else cp_wait<0>();
        __syncthreads();
        if (kt + 2 < nkt) load_tile(kt + 2, (kt + 2) % 3);
        const uint32_t sbs = sb0 + (uint32_t)s * STAGE;

        #pragma unroll
        for (int ks = 0; ks < 2; ks++){
            const uint32_t kx = (uint32_t)(ks << 5);
            uint32_t bhf[4][4], blf[4][4];
            #pragma unroll
            for (int nb = 0; nb < 4; nb++){
                uint32_t t = (sbs + boff[nb]) ^ kx;
                ldsm4(bhf[nb], t);
                ldsm4(blf[nb], t + ST_BLO);
            }
            #pragma unroll
            for (int mt = 0; mt < 4; mt++){
                uint32_t ahf[4], alf[4];
                uint32_t t = (sbs + aoff[mt]) ^ kx;
                ldsm4(ahf, t);
                ldsm4(alf, t + ST_ALO);
                #pragma unroll
                for (int nt = 0; nt < 8; nt++){
                    const int nb = nt >> 1, p = (nt & 1) * 2;
                    float* d = acc[mt][nt];
                    mma16(d, ahf, bhf[nb][p], bhf[nb][p+1]);   // hi*hi
                    mma16(d, ahf, blf[nb][p], blf[nb][p+1]);   // hi*lo
                    mma16(d, alf, bhf[nb][p], bhf[nb][p+1]);   // lo*hi
                }
            }
        }
    }
    // no trailing barrier needed: each warp writes its own output fragment

    // epilogue: registers -> gmem
    #pragma unroll
    for (int mt = 0; mt < 4; mt++){
        #pragma unroll
        for (int nt = 0; nt < 8; nt++){
            int row = m0 + wm*64 + mt*16 + lr;
            int col = n0 + wn*64 + nt*8 + lc*2;
            float* a = acc[mt][nt];
            if (EPI == EP_BIASRELU){
                float b0 = bias[col], b1 = bias[col+1];
                float v0 = a[0] + b0, v1 = a[1] + b1, v2 = a[2] + b0, v3 = a[3] + b1;
                v0 = v0 > 0.f ? v0 : 0.f; v1 = v1 > 0.f ? v1 : 0.f;
                v2 = v2 > 0.f ? v2 : 0.f; v3 = v3 > 0.f ? v3 : 0.f;
                *(float2*)&C[(size_t)row*ldc + col]     = make_float2(v0, v1);
                *(float2*)&C[(size_t)(row+8)*ldc + col] = make_float2(v2, v3);
            } else if (EPI == EP_PLAIN){
                *(float2*)&C[(size_t)row*ldc + col]     = make_float2(a[0], a[1]);
                *(float2*)&C[(size_t)(row+8)*ldc + col] = make_float2(a[2], a[3]);
            } else { // EP_PAD: half hi/lo planes, zero pad columns
                if (col + 2 <= ldc){
                    float v0 = (col   < Nreal) ? a[0] : 0.f;
                    float v1 = (col+1 < Nreal) ? a[1] : 0.f;
                    float v2 = (col   < Nreal) ? a[2] : 0.f;
                    float v3 = (col+1 < Nreal) ? a[3] : 0.f;
                    __half h0,l0,h1,l1,h2,l2,h3,l3;
                    split16(v0,h0,l0); split16(v1,h1,l1);
                    split16(v2,h2,l2); split16(v3,h3,l3);
                    *(__half2*)&Ch[(size_t)row*ldc + col]     = __halves2half2(h0, h1);
                    *(__half2*)&Cl[(size_t)row*ldc + col]     = __halves2half2(l0, l1);
                    *(__half2*)&Ch[(size_t)(row+8)*ldc + col] = __halves2half2(h2, h3);
                    *(__half2*)&Cl[(size_t)(row+8)*ldc + col] = __halves2half2(l2, l3);
                }
            }
        }
    }
}

// ---------------- fp32 -> fp16 hi/lo split ------------------------------------
__global__ void __launch_bounds__(256) split_kernel(
    const float* __restrict__ x, __half* __restrict__ h, __half* __restrict__ l, int n)
{
    int i = blockIdx.x*256 + threadIdx.x;
    if (i < n){ __half hv, lv; split16(x[i], hv, lv); h[i] = hv; l[i] = lv; }
}

// ---------------- 3-class head --------------------------------------------------
__global__ void __launch_bounds__(256) logits_kernel(
    const float* __restrict__ h, const float* __restrict__ W2,
    const float* __restrict__ b2, float* __restrict__ out0, int* __restrict__ pred)
{
    __shared__ float w2s[3*Hh];
    int tid = threadIdx.x;
    for (int i = tid; i < 3*Hh; i += 256) w2s[i] = W2[i];
    __syncthreads();
    int warp = tid >> 5, lane = tid & 31;
    int row = blockIdx.x*8 + warp;
    const float* hp = h + (size_t)row*Hh;
    float s0=0.f, s1=0.f, s2=0.f;
    for (int i = lane; i < Hh; i += 32){
        float hv = hp[i];
        s0 += hv*w2s[i]; s1 += hv*w2s[Hh+i]; s2 += hv*w2s[2*Hh+i];
    }
    #pragma unroll
    for (int off=16; off; off>>=1){
        s0 += __shfl_xor_sync(0xffffffffu, s0, off);
        s1 += __shfl_xor_sync(0xffffffffu, s1, off);
        s2 += __shfl_xor_sync(0xffffffffu, s2, off);
    }
    if (lane == 0){
        s0 += b2[0]; s1 += b2[1]; s2 += b2[2];
        float m = fmaxf(s0, fmaxf(s1, s2));
        float lse = m + logf(expf(s0-m)+expf(s1-m)+expf(s2-m));
        size_t o = (size_t)row*3;
        out0[o+0] = s0 - lse; out0[o+1] = s1 - lse; out0[o+2] = s2 - lse;
        int idx = 0; float best = s0;
        if (s1 > best){ best = s1; idx = 1; }
        if (s2 > best){ idx = 2; }
        pred[row] = idx;
    }
}

// ---------------- BIO segment scan (warp-parallel, ballot-based) ----------------
__global__ void scan_kernel(const int* __restrict__ labels,
                            int* __restrict__ rowinfo, int* __restrict__ nvraw,
                            int* __restrict__ rowvalid)
{
    __shared__ int pos[513];
    int b = blockIdx.x, lane = threadIdx.x;
    const int* lab = labels + b*Tt;
    int base = 0;
    int first1 = Tt;
    int any2 = 0;
    #pragma unroll 1
    for (int c = 0; c < Tt/32; c++){
        int l = lab[c*32 + lane];
        unsigned m1 = __ballot_sync(0xffffffffu, l == 1);
        unsigned m2 = __ballot_sync(0xffffffffu, l == 2);
        if (l == 1) pos[base + __popc(m1 & ((1u<<lane)-1))] = c*32 + lane;
        if (first1 == Tt){
            if (m1){
                int fl = __ffs(m1) - 1;
                first1 = c*32 + fl;
                any2 |= (m2 & ((1u<<fl)-1)) != 0;
            } else any2 |= (m2 != 0);
        }
        base += __popc(m1);
    }
    int m = base;
    int lead = any2;
    __syncwarp();
    if (lane == 0){
        pos[m] = Tt;
        if (lead) rowinfo[b*Tt] = (0<<16) | (m ? pos[0] : Tt);
        nvraw[b] = lead + m;
        rowvalid[b] = (lead + m) > 0;
    }
    __syncwarp();
    for (int j = lane; j < m; j += 32){
        int s = pos[j], e = pos[j+1];
        rowinfo[b*Tt + lead + j] = (s<<16) | e;
    }
}

__global__ void combine_kernel(const int* __restrict__ nvraw, const int* __restrict__ rowvalid,
                               int* __restrict__ dest, int* __restrict__ nvout)
{
    if (threadIdx.x || blockIdx.x) return;
    int cnt = 0;
    for (int b=0;b<Bb;b++) dest[b] = rowvalid[b] ? cnt++ : -1;
    for (int b=0;b<Bb;b++) nvout[b] = 0;
    for (int b=0;b<Bb;b++) if (dest[b] >= 0) nvout[dest[b]] = nvraw[b];
}

// ---------------- segment means -> compacted pooled rows (hi/lo half planes) ----
__global__ void __launch_bounds__(256) pool_kernel(
    const int* __restrict__ labels, const float* __restrict__ hidden,
    const int* __restrict__ rowinfo, const int* __restrict__ nvraw,
    const int* __restrict__ dest, __half* __restrict__ ph, __half* __restrict__ pl)
{
    int b = blockIdx.x;
    int d = dest[b];
    if (d < 0) return;
    int nv = nvraw[b];
    __shared__ int labs[Tt];
    int tid = threadIdx.x;
    for (int i=tid;i<Tt;i+=256) labs[i] = labels[b*Tt+i];
    __syncthreads();
    int r0 = blockIdx.y * 32;
    int r1 = min(r0+32, nv);
    for (int r=r0; r<r1; r++){
        int info = rowinfo[b*Tt + r];
        int s = info >> 16, e = info & 0xffff;
        float a0=0.f,a1=0.f,a2=0.f;
        int cnt = 0;
        for (int t=s;t<e;t++){
            if (labs[t] != 0){
                cnt++;
                const float* hp = hidden + ((size_t)(b*Tt)+t)*Hh;
                a0 += hp[tid]; a1 += hp[tid+256]; a2 += hp[tid+512];
            }
        }
        float inv = 1.0f / (float)cnt;
        size_t off = ((size_t)(d*Tt)+r)*Hh;
        __half hv, lv;
        split16(a0*inv, hv, lv); ph[off+tid]     = hv; pl[off+tid]     = lv;
        split16(a1*inv, hv, lv); ph[off+tid+256] = hv; pl[off+tid+256] = lv;
        split16(a2*inv, hv, lv); ph[off+tid+512] = hv; pl[off+tid+512] = lv;
    }
}

// ---------------- row log-softmax over sc ----------------------------------------
__global__ void __launch_bounds__(256) lsm_kernel(
    const float* __restrict__ sc, const int* __restrict__ nvout, float* __restrict__ out)
{
    int row = blockIdx.x*8 + (threadIdx.x >> 5);
    int lane = threadIdx.x & 31;
    int nv = nvout[row >> 9];
    float* op = out + (size_t)row*Nn;
    if ((row & 511) >= nv){
        const float CNEG = -7.6246189861593985f;   // -log(2048)
        float4 c4 = make_float4(CNEG,CNEG,CNEG,CNEG);
        for (int i=lane;i<Nn/4;i+=32) ((float4*)op)[i] = c4;
        return;
    }
    const float4* ip = (const float4*)(sc + (size_t)row*Nn);
    float4 v[16];
    float m = -3.4e38f;
    #pragma unroll
    for (int i=0;i<16;i++){
        v[i] = ip[lane + i*32];
        m = fmaxf(m, fmaxf(fmaxf(v[i].x,v[i].y), fmaxf(v[i].z,v[i].w)));
    }
    #pragma unroll
    for (int off=16;off;off>>=1) m = fmaxf(m, __shfl_xor_sync(0xffffffffu, m, off));
    float s = 0.f;
    #pragma unroll
    for (int i=0;i<16;i++)
        s += expf(v[i].x-m)+expf(v[i].y-m)+expf(v[i].z-m)+expf(v[i].w-m);
    #pragma unroll
    for (int off=16;off;off>>=1) s += __shfl_xor_sync(0xffffffffu, s, off);
    float corr = m + logf(s);
    #pragma unroll
    for (int i=0;i<16;i++){
        float4 o = v[i];
        o.x-=corr; o.y-=corr; o.z-=corr; o.w-=corr;
        ((float4*)op)[lane + i*32] = o;
    }
}

// ---------------- host -------------------------------------------------------------
extern "C" void kernel_launch(void* const* d_in, const int* in_sizes, int n_in,
                              void* d_out, int out_size)
{
    (void)in_sizes; (void)n_in; (void)out_size;
    const int*   labels = (const int*)  d_in[0];
    const float* hidden = (const float*)d_in[1];
    const float* ent    = (const float*)d_in[2];
    const float* W1     = (const float*)d_in[3];
    const float* b1     = (const float*)d_in[4];
    const float* W2     = (const float*)d_in[5];
    const float* b2     = (const float*)d_in[6];
    const float* Wm     = (const float*)d_in[7];
    const float* Wd     = (const float*)d_in[8];

    float* out0 = (float*)d_out;
    float* s1o  = out0 + (size_t)BT*3;
    float* s2o  = s1o  + (size_t)BT*Nn;

    __half *hidh,*hidl,*enth,*entl,*w1h,*w1l,*wmh,*wml,*wdh,*wdl;
    __half *poolh,*pooll,*pmh,*pml,*pdh,*pdl;
    float *h, *sc;
    int *pred, *rowinfo, *nvraw, *dest, *nvout, *rowvalid;
    cudaGetSymbolAddress((void**)&hidh, g_hid_h);  cudaGetSymbolAddress((void**)&hidl, g_hid_l);
    cudaGetSymbolAddress((void**)&enth, g_ent_h);  cudaGetSymbolAddress((void**)&entl, g_ent_l);
    cudaGetSymbolAddress((void**)&w1h,  g_W1_h);   cudaGetSymbolAddress((void**)&w1l,  g_W1_l);
    cudaGetSymbolAddress((void**)&wmh,  g_Wm_h);   cudaGetSymbolAddress((void**)&wml,  g_Wm_l);
    cudaGetSymbolAddress((void**)&wdh,  g_Wd_h);   cudaGetSymbolAddress((void**)&wdl,  g_Wd_l);
    cudaGetSymbolAddress((void**)&poolh,g_pool_h); cudaGetSymbolAddress((void**)&pooll,g_pool_l);
    cudaGetSymbolAddress((void**)&pmh,  g_pm_h);   cudaGetSymbolAddress((void**)&pml,  g_pm_l);
    cudaGetSymbolAddress((void**)&pdh,  g_pd_h);   cudaGetSymbolAddress((void**)&pdl,  g_pd_l);
    cudaGetSymbolAddress((void**)&h,    g_h);
    cudaGetSymbolAddress((void**)&sc,   g_sc);
    cudaGetSymbolAddress((void**)&pred, g_pred);
    cudaGetSymbolAddress((void**)&rowinfo, g_rowinfo);
    cudaGetSymbolAddress((void**)&nvraw,   g_nvraw);
    cudaGetSymbolAddress((void**)&dest,    g_dest);
    cudaGetSymbolAddress((void**)&nvout,   g_nvout);
    cudaGetSymbolAddress((void**)&rowvalid,g_rowvalid);

    cudaFuncSetAttribute((const void*)mma_gemm<EP_BIASRELU,false>, cudaFuncAttributeMaxDynamicSharedMemorySize, SMEMSZ);
    cudaFuncSetAttribute((const void*)mma_gemm<EP_PAD,false>,      cudaFuncAttributeMaxDynamicSharedMemorySize, SMEMSZ);
    cudaFuncSetAttribute((const void*)mma_gemm<EP_PAD,true>,       cudaFuncAttributeMaxDynamicSharedMemorySize, SMEMSZ);
    cudaFuncSetAttribute((const void*)mma_gemm<EP_PLAIN,true>,     cudaFuncAttributeMaxDynamicSharedMemorySize, SMEMSZ);

    // launches 1-3: splits needed by gemm1; launch 4 = gemm1 (ncu capture slot)
    split_kernel<<<(BT*Hh+255)/256, 256>>>(hidden, hidh, hidl, BT*Hh);
    split_kernel<<<(Hh*Hh+255)/256, 256>>>(W1, w1h, w1l, Hh*Hh);
    split_kernel<<<(Nn*Hh+255)/256, 256>>>(ent, enth, entl, Nn*Hh);

    // 1) h = relu(x @ W1^T + b1)   grid (768/128, 32768/256)
    mma_gemm<EP_BIASRELU,false><<<dim3(Hh/128, BT/256), 256, SMEMSZ>>>(
        hidh, hidl, w1h, w1l, h, nullptr, nullptr, Hh, Hh, Hh, Hh, Hh, Hh, b1, nullptr);

    split_kernel<<<(Pp*Hh+255)/256, 256>>>(Wm, wmh, wml, Pp*Hh);
    split_kernel<<<(Pp*Hh+255)/256, 256>>>(Wd, wdh, wdl, Pp*Hh);

    // 2) bio logits -> out0 + predicted labels
    logits_kernel<<<BT/8, 256>>>(h, W2, b2, out0, pred);

    // 3) pd = ent @ Wd^T -> half hi/lo planes, K-padded to KP   grid (3, 2048/256)
    mma_gemm<EP_PAD,false><<<dim3(3, Nn/256), 256, SMEMSZ>>>(
        enth, entl, wdh, wdl, nullptr, pdh, pdl, Hh, Hh, KP, Hh, Pp, Pp, nullptr, nullptr);

    // 4/5) two pooling passes: gold labels, then predicted
    for (int pass = 0; pass < 2; pass++){
        const int* lsrc = (pass == 0) ? labels : pred;
        float* so = (pass == 0) ? s1o : s2o;

        scan_kernel<<<Bb, 32>>>(lsrc, rowinfo, nvraw, rowvalid);
        combine_kernel<<<1, 1>>>(nvraw, rowvalid, dest, nvout);
        pool_kernel<<<dim3(Bb, 16), 256>>>(lsrc, hidden, rowinfo, nvraw, dest, poolh, pooll);

        mma_gemm<EP_PAD,true><<<dim3(3, BT/256), 256, SMEMSZ>>>(
            poolh, pooll, wmh, wml, nullptr, pmh, pml, Hh, Hh, KP, Hh, Pp, Pp, nullptr, nvout);

        mma_gemm<EP_PLAIN,true><<<dim3(Nn/128, BT/256), 256, SMEMSZ>>>(
            pmh, pml, pdh, pdl, sc, nullptr, nullptr, KP, KP, Nn, KP, Nn, Nn, nullptr, nvout);

        lsm_kernel<<<BT/8, 256>>>(sc, nvout, so);
    }
}

// round 8
// speedup vs baseline: 2.3576x; 1.0378x over previous
#include <cuda_runtime.h>
#include <cuda_fp16.h>
#include <math.h>
#include <stdint.h>

#define Bb 64
#define Tt 512
#define Hh 768
#define Nn 2048
#define Pp 300
#define KP 320
#define BT (Bb*Tt)

// ---------------- scratch (device globals; no allocation allowed) ----------
__device__ __half g_hid_h[(size_t)BT*Hh],  g_hid_l[(size_t)BT*Hh];
__device__ __half g_ent_h[(size_t)Nn*Hh],  g_ent_l[(size_t)Nn*Hh];
__device__ __half g_W1_h[Hh*Hh],           g_W1_l[Hh*Hh];
__device__ __half g_Wm_h[Pp*Hh],           g_Wm_l[Pp*Hh];
__device__ __half g_Wd_h[Pp*Hh],           g_Wd_l[Pp*Hh];
__device__ __half g_pool_h[(size_t)BT*Hh], g_pool_l[(size_t)BT*Hh];
__device__ __half g_pm_h[(size_t)BT*KP],   g_pm_l[(size_t)BT*KP];
__device__ __half g_pd_h[(size_t)Nn*KP],   g_pd_l[(size_t)Nn*KP];
__device__ float  g_h[(size_t)BT*Hh];
__device__ float  g_sc[(size_t)BT*Nn];
__device__ int    g_pred[BT];
__device__ int    g_rowinfo[BT];
__device__ int    g_nvraw[Bb];
__device__ int    g_dest[Bb];
__device__ int    g_nvout[Bb];
__device__ int    g_rowvalid[Bb];

// ---------------- helpers ----------------------------------------------------
__device__ __forceinline__ uint32_t smem_u32(const void* p){
    uint32_t a;
    asm("{ .reg .u64 t; cvta.to.shared.u64 t, %1; cvt.u32.u64 %0, t; }" : "=r"(a) : "l"(p));
    return a;
}
__device__ __forceinline__ void cp_async16(uint32_t dst, const void* src, bool ok){
    int sz = ok ? 16 : 0;   // src-size 0 -> zero-fill 16B
    asm volatile("cp.async.cg.shared.global [%0], [%1], 16, %2;" :: "r"(dst), "l"(src), "r"(sz));
}
__device__ __forceinline__ void cp_commit(){ asm volatile("cp.async.commit_group;" ::: "memory"); }
template<int N> __device__ __forceinline__ void cp_wait(){ asm volatile("cp.async.wait_group %0;" :: "n"(N) : "memory"); }

__device__ __forceinline__ void ldsm4(uint32_t* r, uint32_t addr){
    asm volatile("ldmatrix.sync.aligned.m8n8.x4.shared.b16 {%0,%1,%2,%3}, [%4];"
        : "=r"(r[0]), "=r"(r[1]), "=r"(r[2]), "=r"(r[3]) : "r"(addr));
}
__device__ __forceinline__ void mma16(float* d, const uint32_t* a, uint32_t b0, uint32_t b1){
    asm volatile(
        "mma.sync.aligned.m16n8k16.row.col.f32.f16.f16.f32 "
        "{%0,%1,%2,%3}, {%4,%5,%6,%7}, {%8,%9}, {%0,%1,%2,%3};"
        : "+f"(d[0]), "+f"(d[1]), "+f"(d[2]), "+f"(d[3])
        : "r"(a[0]), "r"(a[1]), "r"(a[2]), "r"(a[3]), "r"(b0), "r"(b1));
}
__device__ __forceinline__ void split16(float v, __half& h, __half& l){
    h = __float2half_rn(v);
    l = __float2half_rn(v - __half2float(h));
}

// ---------------- fp16 3-term GEMM: C[M,N] = A[M,K] @ B[N,K]^T ---------------
// CTA tile 256x128, BK=32, 16 warps (4m x 4n), warp tile 64x32, 3-stage cp.async.
enum { EP_BIASRELU = 0, EP_PAD = 1, EP_PLAIN = 2 };
#define ST_ALO 16384
#define ST_B   32768
#define ST_BLO 8192      // relative to ST_B
#define STAGE  49152
#define SMEMSZ (3*STAGE) // 147456
#define NTHR 512

template<int EPI, bool ROWMASK>
__global__ void __launch_bounds__(NTHR, 1) mma_gemm(
    const __half* __restrict__ Ah, const __half* __restrict__ Al,
    const __half* __restrict__ Bh, const __half* __restrict__ Bl,
    float* __restrict__ C, __half* __restrict__ Ch, __half* __restrict__ Cl,
    int lda, int ldb, int ldc, int K, int Nreal, int NBreal,
    const float* __restrict__ bias, const int* __restrict__ nvout)
{
    extern __shared__ char smem[];
    const int m0 = blockIdx.y * 256, n0 = blockIdx.x * 128;
    const int tid = threadIdx.x;
    if (ROWMASK){
        int nv = nvout[m0 >> 9];
        if ((m0 & 511) >= nv) return;   // invalid rows never read downstream
    }
    const uint32_t sb0 = smem_u32(smem);
    const int warp = tid >> 5, lane = tid & 31;
    const int wm = warp >> 2, wn = warp & 3;     // 4 x 4 warp grid, warp tile 64x32
    const int lr = lane >> 2, lc = lane & 3;

    float acc[4][4][4];
    #pragma unroll
    for (int i=0;i<4;i++)
        #pragma unroll
        for (int j=0;j<4;j++)
            #pragma unroll
            for (int q=0;q<4;q++) acc[i][j][q] = 0.f;

    // ldmatrix base offsets (stage-relative); toggle ks via ^32, lo plane via +offset
    const int arl = (lane & 7) + ((lane >> 3) & 1) * 8;
    const int acs = lane >> 4;
    const int nrl = (lane & 7) + (lane >> 4) * 8;
    const int bcs = (lane >> 3) & 1;
    uint32_t aoff[4], boff[2];
    #pragma unroll
    for (int mt = 0; mt < 4; mt++){
        int r = wm*64 + mt*16 + arl;
        aoff[mt] = (uint32_t)(r*64) + (uint32_t)((acs ^ (r & 3) ^ ((r >> 2) & 1)) << 4);
    }
    #pragma unroll
    for (int nb = 0; nb < 2; nb++){
        int r = wn*32 + nb*16 + nrl;
        boff[nb] = (uint32_t)ST_B + (uint32_t)(r*64) + (uint32_t)((bcs ^ (r & 3) ^ ((r >> 2) & 1)) << 4);
    }

    auto load_tile = [&](int kt, int s){
        const int k0 = kt * 32;
        const uint32_t sbs = sb0 + (uint32_t)s * STAGE;
        #pragma unroll
        for (int j = 0; j < 6; j++){
            int idx = tid + j*NTHR;                // 0..3071 16B-chunks
            if (idx < 2048){                        // A planes: 256 rows x 4 chunks x2
                int pl  = idx >> 10;
                int rem = idx & 1023;
                int row = rem >> 2, c = rem & 3;
                int c2  = c ^ (row & 3) ^ ((row >> 2) & 1);
                uint32_t so = sbs + (uint32_t)(pl*ST_ALO + row*64 + c2*16);
                const __half* src = (pl ? Al : Ah) + (size_t)(m0 + row)*lda + k0 + c*8;
                cp_async16(so, src, true);
            } else {                                // B planes: 128 rows x 4 chunks x2
                int b   = idx - 2048;
                int pl  = b >> 9;
                int rem = b & 511;
                int row = rem >> 2, c = rem & 3;
                int c2  = c ^ (row & 3) ^ ((row >> 2) & 1);
                uint32_t so = sbs + (uint32_t)(ST_B + pl*ST_BLO + row*64 + c2*16);
                bool ok = (n0 + row) < NBreal;
                const __half* base = pl ? Bl : Bh;
                const __half* src = ok ? (base + (size_t)(n0 + row)*ldb + k0 + c*8) : base;
                cp_async16(so, src, ok);
            }
        }
        cp_commit();
    };

    const int nkt = K >> 5;
    load_tile(0, 0);
    if (nkt > 1) load_tile(1, 1);
    for (int kt = 0; kt < nkt; kt++){
        const int s = kt % 3;
        if (kt + 1 < nkt) cp_wait<1>(); else cp_wait<0>();
        __syncthreads();
        if (kt + 2 < nkt) load_tile(kt + 2, (kt + 2) % 3);
        const uint32_t sbs = sb0 + (uint32_t)s * STAGE;

        #pragma unroll
        for (int ks = 0; ks < 2; ks++){
            const uint32_t kx = (uint32_t)(ks << 5);
            uint32_t bhf[2][4], blf[2][4];
            #pragma unroll
            for (int nb = 0; nb < 2; nb++){
                uint32_t t = (sbs + boff[nb]) ^ kx;
                ldsm4(bhf[nb], t);
                ldsm4(blf[nb], t + ST_BLO);
            }
            #pragma unroll
            for (int mt = 0; mt < 4; mt++){
                uint32_t ahf[4], alf[4];
                uint32_t t = (sbs + aoff[mt]) ^ kx;
                ldsm4(ahf, t);
                ldsm4(alf, t + ST_ALO);
                #pragma unroll
                for (int nt = 0; nt < 4; nt++){
                    const int nb = nt >> 1, p = (nt & 1) * 2;
                    float* d = acc[mt][nt];
                    mma16(d, ahf, bhf[nb][p], bhf[nb][p+1]);   // hi*hi
                    mma16(d, ahf, blf[nb][p], blf[nb][p+1]);   // hi*lo
                    mma16(d, alf, bhf[nb][p], bhf[nb][p+1]);   // lo*hi
                }
            }
        }
    }

    // epilogue: registers -> gmem
    #pragma unroll
    for (int mt = 0; mt < 4; mt++){
        #pragma unroll
        for (int nt = 0; nt < 4; nt++){
            int row = m0 + wm*64 + mt*16 + lr;
            int col = n0 + wn*32 + nt*8 + lc*2;
            float* a = acc[mt][nt];
            if (EPI == EP_BIASRELU){
                float b0 = bias[col], b1 = bias[col+1];
                float v0 = a[0] + b0, v1 = a[1] + b1, v2 = a[2] + b0, v3 = a[3] + b1;
                v0 = v0 > 0.f ? v0 : 0.f; v1 = v1 > 0.f ? v1 : 0.f;
                v2 = v2 > 0.f ? v2 : 0.f; v3 = v3 > 0.f ? v3 : 0.f;
                *(float2*)&C[(size_t)row*ldc + col]     = make_float2(v0, v1);
                *(float2*)&C[(size_t)(row+8)*ldc + col] = make_float2(v2, v3);
            } else if (EPI == EP_PLAIN){
                *(float2*)&C[(size_t)row*ldc + col]     = make_float2(a[0], a[1]);
                *(float2*)&C[(size_t)(row+8)*ldc + col] = make_float2(a[2], a[3]);
            } else { // EP_PAD: half hi/lo planes, zero pad columns
                if (col + 2 <= ldc){
                    float v0 = (col   < Nreal) ? a[0] : 0.f;
                    float v1 = (col+1 < Nreal) ? a[1] : 0.f;
                    float v2 = (col   < Nreal) ? a[2] : 0.f;
                    float v3 = (col+1 < Nreal) ? a[3] : 0.f;
                    __half h0,l0,h1,l1,h2,l2,h3,l3;
                    split16(v0,h0,l0); split16(v1,h1,l1);
                    split16(v2,h2,l2); split16(v3,h3,l3);
                    *(__half2*)&Ch[(size_t)row*ldc + col]     = __halves2half2(h0, h1);
                    *(__half2*)&Cl[(size_t)row*ldc + col]     = __halves2half2(l0, l1);
                    *(__half2*)&Ch[(size_t)(row+8)*ldc + col] = __halves2half2(h2, h3);
                    *(__half2*)&Cl[(size_t)(row+8)*ldc + col] = __halves2half2(l2, l3);
                }
            }
        }
    }
}

// ---------------- fp32 -> fp16 hi/lo split ------------------------------------
__global__ void __launch_bounds__(256) split_kernel(
    const float* __restrict__ x, __half* __restrict__ h, __half* __restrict__ l, int n)
{
    int i = blockIdx.x*256 + threadIdx.x;
    if (i < n){ __half hv, lv; split16(x[i], hv, lv); h[i] = hv; l[i] = lv; }
}

// ---------------- 3-class head --------------------------------------------------
__global__ void __launch_bounds__(256) logits_kernel(
    const float* __restrict__ h, const float* __restrict__ W2,
    const float* __restrict__ b2, float* __restrict__ out0, int* __restrict__ pred)
{
    __shared__ float w2s[3*Hh];
    int tid = threadIdx.x;
    for (int i = tid; i < 3*Hh; i += 256) w2s[i] = W2[i];
    __syncthreads();
    int warp = tid >> 5, lane = tid & 31;
    int row = blockIdx.x*8 + warp;
    const float* hp = h + (size_t)row*Hh;
    float s0=0.f, s1=0.f, s2=0.f;
    for (int i = lane; i < Hh; i += 32){
        float hv = hp[i];
        s0 += hv*w2s[i]; s1 += hv*w2s[Hh+i]; s2 += hv*w2s[2*Hh+i];
    }
    #pragma unroll
    for (int off=16; off; off>>=1){
        s0 += __shfl_xor_sync(0xffffffffu, s0, off);
        s1 += __shfl_xor_sync(0xffffffffu, s1, off);
        s2 += __shfl_xor_sync(0xffffffffu, s2, off);
    }
    if (lane == 0){
        s0 += b2[0]; s1 += b2[1]; s2 += b2[2];
        float m = fmaxf(s0, fmaxf(s1, s2));
        float lse = m + logf(expf(s0-m)+expf(s1-m)+expf(s2-m));
        size_t o = (size_t)row*3;
        out0[o+0] = s0 - lse; out0[o+1] = s1 - lse; out0[o+2] = s2 - lse;
        int idx = 0; float best = s0;
        if (s1 > best){ best = s1; idx = 1; }
        if (s2 > best){ idx = 2; }
        pred[row] = idx;
    }
}

// ---------------- BIO segment scan (warp-parallel, ballot-based) ----------------
__global__ void scan_kernel(const int* __restrict__ labels,
                            int* __restrict__ rowinfo, int* __restrict__ nvraw,
                            int* __restrict__ rowvalid)
{
    __shared__ int pos[513];
    int b = blockIdx.x, lane = threadIdx.x;
    const int* lab = labels + b*Tt;
    int base = 0;
    int first1 = Tt;
    int any2 = 0;
    #pragma unroll 1
    for (int c = 0; c < Tt/32; c++){
        int l = lab[c*32 + lane];
        unsigned m1 = __ballot_sync(0xffffffffu, l == 1);
        unsigned m2 = __ballot_sync(0xffffffffu, l == 2);
        if (l == 1) pos[base + __popc(m1 & ((1u<<lane)-1))] = c*32 + lane;
        if (first1 == Tt){
            if (m1){
                int fl = __ffs(m1) - 1;
                first1 = c*32 + fl;
                any2 |= (m2 & ((1u<<fl)-1)) != 0;
            } else any2 |= (m2 != 0);
        }
        base += __popc(m1);
    }
    int m = base;
    int lead = any2;
    __syncwarp();
    if (lane == 0){
        pos[m] = Tt;
        if (lead) rowinfo[b*Tt] = (0<<16) | (m ? pos[0] : Tt);
        nvraw[b] = lead + m;
        rowvalid[b] = (lead + m) > 0;
    }
    __syncwarp();
    for (int j = lane; j < m; j += 32){
        int s = pos[j], e = pos[j+1];
        rowinfo[b*Tt + lead + j] = (s<<16) | e;
    }
}

__global__ void combine_kernel(const int* __restrict__ nvraw, const int* __restrict__ rowvalid,
                               int* __restrict__ dest, int* __restrict__ nvout)
{
    if (threadIdx.x || blockIdx.x) return;
    int cnt = 0;
    for (int b=0;b<Bb;b++) dest[b] = rowvalid[b] ? cnt++ : -1;
    for (int b=0;b<Bb;b++) nvout[b] = 0;
    for (int b=0;b<Bb;b++) if (dest[b] >= 0) nvout[dest[b]] = nvraw[b];
}

// ---------------- segment means -> compacted pooled rows (hi/lo half planes) ----
__global__ void __launch_bounds__(256) pool_kernel(
    const int* __restrict__ labels, const float* __restrict__ hidden,
    const int* __restrict__ rowinfo, const int* __restrict__ nvraw,
    const int* __restrict__ dest, __half* __restrict__ ph, __half* __restrict__ pl)
{
    int b = blockIdx.x;
    int d = dest[b];
    if (d < 0) return;
    int nv = nvraw[b];
    __shared__ int labs[Tt];
    int tid = threadIdx.x;
    for (int i=tid;i<Tt;i+=256) labs[i] = labels[b*Tt+i];
    __syncthreads();
    int r0 = blockIdx.y * 32;
    int r1 = min(r0+32, nv);
    for (int r=r0; r<r1; r++){
        int info = rowinfo[b*Tt + r];
        int s = info >> 16, e = info & 0xffff;
        float a0=0.f,a1=0.f,a2=0.f;
        int cnt = 0;
        for (int t=s;t<e;t++){
            if (labs[t] != 0){
                cnt++;
                const float* hp = hidden + ((size_t)(b*Tt)+t)*Hh;
                a0 += hp[tid]; a1 += hp[tid+256]; a2 += hp[tid+512];
            }
        }
        float inv = 1.0f / (float)cnt;
        size_t off = ((size_t)(d*Tt)+r)*Hh;
        __half hv, lv;
        split16(a0*inv, hv, lv); ph[off+tid]     = hv; pl[off+tid]     = lv;
        split16(a1*inv, hv, lv); ph[off+tid+256] = hv; pl[off+tid+256] = lv;
        split16(a2*inv, hv, lv); ph[off+tid+512] = hv; pl[off+tid+512] = lv;
    }
}

// ---------------- row log-softmax over sc ----------------------------------------
__global__ void __launch_bounds__(256) lsm_kernel(
    const float* __restrict__ sc, const int* __restrict__ nvout, float* __restrict__ out)
{
    int row = blockIdx.x*8 + (threadIdx.x >> 5);
    int lane = threadIdx.x & 31;
    int nv = nvout[row >> 9];
    float* op = out + (size_t)row*Nn;
    if ((row & 511) >= nv){
        const float CNEG = -7.6246189861593985f;   // -log(2048)
        float4 c4 = make_float4(CNEG,CNEG,CNEG,CNEG);
        for (int i=lane;i<Nn/4;i+=32) ((float4*)op)[i] = c4;
        return;
    }
    const float4* ip = (const float4*)(sc + (size_t)row*Nn);
    float4 v[16];
    float m = -3.4e38f;
    #pragma unroll
    for (int i=0;i<16;i++){
        v[i] = ip[lane + i*32];
        m = fmaxf(m, fmaxf(fmaxf(v[i].x,v[i].y), fmaxf(v[i].z,v[i].w)));
    }
    #pragma unroll
    for (int off=16;off;off>>=1) m = fmaxf(m, __shfl_xor_sync(0xffffffffu, m, off));
    float s = 0.f;
    #pragma unroll
    for (int i=0;i<16;i++)
        s += expf(v[i].x-m)+expf(v[i].y-m)+expf(v[i].z-m)+expf(v[i].w-m);
    #pragma unroll
    for (int off=16;off;off>>=1) s += __shfl_xor_sync(0xffffffffu, s, off);
    float corr = m + logf(s);
    #pragma unroll
    for (int i=0;i<16;i++){
        float4 o = v[i];
        o.x-=corr; o.y-=corr; o.z-=corr; o.w-=corr;
        ((float4*)op)[lane + i*32] = o;
    }
}

// ---------------- host -------------------------------------------------------------
extern "C" void kernel_launch(void* const* d_in, const int* in_sizes, int n_in,
                              void* d_out, int out_size)
{
    (void)in_sizes; (void)n_in; (void)out_size;
    const int*   labels = (const int*)  d_in[0];
    const float* hidden = (const float*)d_in[1];
    const float* ent    = (const float*)d_in[2];
    const float* W1     = (const float*)d_in[3];
    const float* b1     = (const float*)d_in[4];
    const float* W2     = (const float*)d_in[5];
    const float* b2     = (const float*)d_in[6];
    const float* Wm     = (const float*)d_in[7];
    const float* Wd     = (const float*)d_in[8];

    float* out0 = (float*)d_out;
    float* s1o  = out0 + (size_t)BT*3;
    float* s2o  = s1o  + (size_t)BT*Nn;

    __half *hidh,*hidl,*enth,*entl,*w1h,*w1l,*wmh,*wml,*wdh,*wdl;
    __half *poolh,*pooll,*pmh,*pml,*pdh,*pdl;
    float *h, *sc;
    int *pred, *rowinfo, *nvraw, *dest, *nvout, *rowvalid;
    cudaGetSymbolAddress((void**)&hidh, g_hid_h);  cudaGetSymbolAddress((void**)&hidl, g_hid_l);
    cudaGetSymbolAddress((void**)&enth, g_ent_h);  cudaGetSymbolAddress((void**)&entl, g_ent_l);
    cudaGetSymbolAddress((void**)&w1h,  g_W1_h);   cudaGetSymbolAddress((void**)&w1l,  g_W1_l);
    cudaGetSymbolAddress((void**)&wmh,  g_Wm_h);   cudaGetSymbolAddress((void**)&wml,  g_Wm_l);
    cudaGetSymbolAddress((void**)&wdh,  g_Wd_h);   cudaGetSymbolAddress((void**)&wdl,  g_Wd_l);
    cudaGetSymbolAddress((void**)&poolh,g_pool_h); cudaGetSymbolAddress((void**)&pooll,g_pool_l);
    cudaGetSymbolAddress((void**)&pmh,  g_pm_h);   cudaGetSymbolAddress((void**)&pml,  g_pm_l);
    cudaGetSymbolAddress((void**)&pdh,  g_pd_h);   cudaGetSymbolAddress((void**)&pdl,  g_pd_l);
    cudaGetSymbolAddress((void**)&h,    g_h);
    cudaGetSymbolAddress((void**)&sc,   g_sc);
    cudaGetSymbolAddress((void**)&pred, g_pred);
    cudaGetSymbolAddress((void**)&rowinfo, g_rowinfo);
    cudaGetSymbolAddress((void**)&nvraw,   g_nvraw);
    cudaGetSymbolAddress((void**)&dest,    g_dest);
    cudaGetSymbolAddress((void**)&nvout,   g_nvout);
    cudaGetSymbolAddress((void**)&rowvalid,g_rowvalid);

    cudaFuncSetAttribute((const void*)mma_gemm<EP_BIASRELU,false>, cudaFuncAttributeMaxDynamicSharedMemorySize, SMEMSZ);
    cudaFuncSetAttribute((const void*)mma_gemm<EP_PAD,false>,      cudaFuncAttributeMaxDynamicSharedMemorySize, SMEMSZ);
    cudaFuncSetAttribute((const void*)mma_gemm<EP_PAD,true>,       cudaFuncAttributeMaxDynamicSharedMemorySize, SMEMSZ);
    cudaFuncSetAttribute((const void*)mma_gemm<EP_PLAIN,true>,     cudaFuncAttributeMaxDynamicSharedMemorySize, SMEMSZ);

    // launches 1-3: splits needed by gemm1; launch 4 = gemm1 (ncu capture slot)
    split_kernel<<<(BT*Hh+255)/256, 256>>>(hidden, hidh, hidl, BT*Hh);
    split_kernel<<<(Hh*Hh+255)/256, 256>>>(W1, w1h, w1l, Hh*Hh);
    split_kernel<<<(Nn*Hh+255)/256, 256>>>(ent, enth, entl, Nn*Hh);

    // 1) h = relu(x @ W1^T + b1)   grid (768/128, 32768/256)
    mma_gemm<EP_BIASRELU,false><<<dim3(Hh/128, BT/256), NTHR, SMEMSZ>>>(
        hidh, hidl, w1h, w1l, h, nullptr, nullptr, Hh, Hh, Hh, Hh, Hh, Hh, b1, nullptr);

    split_kernel<<<(Pp*Hh+255)/256, 256>>>(Wm, wmh, wml, Pp*Hh);
    split_kernel<<<(Pp*Hh+255)/256, 256>>>(Wd, wdh, wdl, Pp*Hh);

    // 2) bio logits -> out0 + predicted labels
    logits_kernel<<<BT/8, 256>>>(h, W2, b2, out0, pred);

    // 3) pd = ent @ Wd^T -> half hi/lo planes, K-padded to KP
    mma_gemm<EP_PAD,false><<<dim3(3, Nn/256), NTHR, SMEMSZ>>>(
        enth, entl, wdh, wdl, nullptr, pdh, pdl, Hh, Hh, KP, Hh, Pp, Pp, nullptr, nullptr);

    // 4/5) two pooling passes: gold labels, then predicted
    for (int pass = 0; pass < 2; pass++){
        const int* lsrc = (pass == 0) ? labels : pred;
        float* so = (pass == 0) ? s1o : s2o;

        scan_kernel<<<Bb, 32>>>(lsrc, rowinfo, nvraw, rowvalid);
        combine_kernel<<<1, 1>>>(nvraw, rowvalid, dest, nvout);
        pool_kernel<<<dim3(Bb, 16), 256>>>(lsrc, hidden, rowinfo, nvraw, dest, poolh, pooll);

        mma_gemm<EP_PAD,true><<<dim3(3, BT/256), NTHR, SMEMSZ>>>(
            poolh, pooll, wmh, wml, nullptr, pmh, pml, Hh, Hh, KP, Hh, Pp, Pp, nullptr, nvout);

        mma_gemm<EP_PLAIN,true><<<dim3(Nn/128, BT/256), NTHR, SMEMSZ>>>(
            pmh, pml, pdh, pdl, sc, nullptr, nullptr, KP, KP, Nn, KP, Nn, Nn, nullptr, nvout);

        lsm_kernel<<<BT/8, 256>>>(sc, nvout, so);
    }
}

// round 9
// speedup vs baseline: 2.7775x; 1.1781x over previous
#include <cuda_runtime.h>
#include <cuda_fp16.h>
#include <math.h>
#include <stdint.h>

#define Bb 64
#define Tt 512
#define Hh 768
#define Nn 2048
#define Pp 300
#define KP 320
#define BT (Bb*Tt)
#define BT2 (2*BT)

// ---------------- scratch (device globals; no allocation allowed) ----------
__device__ __half g_hid_h[(size_t)BT*Hh],   g_hid_l[(size_t)BT*Hh];
__device__ __half g_ent_h[(size_t)Nn*Hh],   g_ent_l[(size_t)Nn*Hh];
__device__ __half g_W1_h[Hh*Hh],            g_W1_l[Hh*Hh];
__device__ __half g_Wm_h[Pp*Hh],            g_Wm_l[Pp*Hh];
__device__ __half g_Wd_h[Pp*Hh],            g_Wd_l[Pp*Hh];
__device__ __half g_pool_h[(size_t)BT2*Hh], g_pool_l[(size_t)BT2*Hh];
__device__ __half g_pm_h[(size_t)BT2*KP],   g_pm_l[(size_t)BT2*KP];
__device__ __half g_pd_h[(size_t)Nn*KP],    g_pd_l[(size_t)Nn*KP];
__device__ float  g_h[(size_t)BT*Hh];
__device__ float  g_sc[(size_t)BT2*Nn];
__device__ int    g_pred[BT];
__device__ int    g_rowinfo0[BT], g_rowinfo1[BT];
__device__ int    g_nvraw0[Bb],  g_nvraw1[Bb];
__device__ int    g_base0[Bb],   g_base1[Bb];     // pooled base row per src batch (-1 invalid)
__device__ int    g_lsm_nv[2*Bb], g_lsm_base[2*Bb]; // indexed by output (pass, compacted batch)
__device__ int    g_Rtot[4];                     // [0]=Rpad  [1]=R
// ---------------- helpers ----------------------------------------------------
__device__ __forceinline__ uint32_t smem_u32(const void* p){
    uint32_t a;
    asm("{ .reg .u64 t; cvta.to.shared.u64 t, %1; cvt.u32.u64 %0, t; }" : "=r"(a) : "l"(p));
    return a;
}
__device__ __forceinline__ void cp_async16(uint32_t dst, const void* src, bool ok){
    int sz = ok ? 16 : 0;   // src-size 0 -> zero-fill 16B
    asm volatile("cp.async.cg.shared.global [%0], [%1], 16, %2;" :: "r"(dst), "l"(src), "r"(sz));
}
__device__ __forceinline__ void cp_commit(){ asm volatile("cp.async.commit_group;" ::: "memory"); }
template<int N> __device__ __forceinline__ void cp_wait(){ asm volatile("cp.async.wait_group %0;" :: "n"(N) : "memory"); }

__device__ __forceinline__ void ldsm4(uint32_t* r, uint32_t addr){
    asm volatile("ldmatrix.sync.aligned.m8n8.x4.shared.b16 {%0,%1,%2,%3}, [%4];"
        : "=r"(r[0]), "=r"(r[1]), "=r"(r[2]), "=r"(r[3]) : "r"(addr));
}
__device__ __forceinline__ void mma16(float* d, const uint32_t* a, uint32_t b0, uint32_t b1){
    asm volatile(
        "mma.sync.aligned.m16n8k16.row.col.f32.f16.f16.f32 "
        "{%0,%1,%2,%3}, {%4,%5,%6,%7}, {%8,%9}, {%0,%1,%2,%3};"
        : "+f"(d[0]), "+f"(d[1]), "+f"(d[2]), "+f"(d[3])
        : "r"(a[0]), "r"(a[1]), "r"(a[2]), "r"(a[3]), "r"(b0), "r"(b1));
}
__device__ __forceinline__ void split16(float v, __half& h, __half& l){
    h = __float2half_rn(v);
    l = __float2half_rn(v - __half2float(h));
}

// ---------------- fp16 3-term GEMM: C[M,N] = A[M,K] @ B[N,K]^T ---------------
// CTA tile 256x128, BK=32, 16 warps (4m x 4n), warp tile 64x32, 3-stage cp.async.
// ROWMASK: skip tiles with m0 >= Rpad (rtot[0]); pooled pad rows are zeroed.
enum { EP_BIASRELU = 0, EP_PAD = 1, EP_PLAIN = 2 };
#define ST_ALO 16384
#define ST_B   32768
#define ST_BLO 8192      // relative to ST_B
#define STAGE  49152
#define SMEMSZ (3*STAGE) // 147456
#define NTHR 512

template<int EPI, bool ROWMASK>
__global__ void __launch_bounds__(NTHR, 1) mma_gemm(
    const __half* __restrict__ Ah, const __half* __restrict__ Al,
    const __half* __restrict__ Bh, const __half* __restrict__ Bl,
    float* __restrict__ C, __half* __restrict__ Ch, __half* __restrict__ Cl,
    int lda, int ldb, int ldc, int K, int Nreal, int NBreal,
    const float* __restrict__ bias, const int* __restrict__ rtot)
{
    extern __shared__ char smem[];
    const int m0 = blockIdx.y * 256, n0 = blockIdx.x * 128;
    const int tid = threadIdx.x;
    if (ROWMASK){
        if (m0 >= rtot[0]) return;     // beyond compacted rows
    }
    const uint32_t sb0 = smem_u32(smem);
    const int warp = tid >> 5, lane = tid & 31;
    const int wm = warp >> 2, wn = warp & 3;     // 4 x 4 warp grid, warp tile 64x32
    const int lr = lane >> 2, lc = lane & 3;

    float acc[4][4][4];
    #pragma unroll
    for (int i=0;i<4;i++)
        #pragma unroll
        for (int j=0;j<4;j++)
            #pragma unroll
            for (int q=0;q<4;q++) acc[i][j][q] = 0.f;

    const int arl = (lane & 7) + ((lane >> 3) & 1) * 8;
    const int acs = lane >> 4;
    const int nrl = (lane & 7) + (lane >> 4) * 8;
    const int bcs = (lane >> 3) & 1;
    uint32_t aoff[4], boff[2];
    #pragma unroll
    for (int mt = 0; mt < 4; mt++){
        int r = wm*64 + mt*16 + arl;
        aoff[mt] = (uint32_t)(r*64) + (uint32_t)((acs ^ (r & 3) ^ ((r >> 2) & 1)) << 4);
    }
    #pragma unroll
    for (int nb = 0; nb < 2; nb++){
        int r = wn*32 + nb*16 + nrl;
        boff[nb] = (uint32_t)ST_B + (uint32_t)(r*64) + (uint32_t)((bcs ^ (r & 3) ^ ((r >> 2) & 1)) << 4);
    }

    auto load_tile = [&](int kt, int s){
        const int k0 = kt * 32;
        const uint32_t sbs = sb0 + (uint32_t)s * STAGE;
        #pragma unroll
        for (int j = 0; j < 6; j++){
            int idx = tid + j*NTHR;
            if (idx < 2048){
                int pl  = idx >> 10;
                int rem = idx & 1023;
                int row = rem >> 2, c = rem & 3;
                int c2  = c ^ (row & 3) ^ ((row >> 2) & 1);
                uint32_t so = sbs + (uint32_t)(pl*ST_ALO + row*64 + c2*16);
                const __half* src = (pl ? Al : Ah) + (size_t)(m0 + row)*lda + k0 + c*8;
                cp_async16(so, src, true);
            } else {
                int b   = idx - 2048;
                int pl  = b >> 9;
                int rem = b & 511;
                int row = rem >> 2, c = rem & 3;
                int c2  = c ^ (row & 3) ^ ((row >> 2) & 1);
                uint32_t so = sbs + (uint32_t)(ST_B + pl*ST_BLO + row*64 + c2*16);
                bool ok = (n0 + row) < NBreal;
                const __half* base = pl ? Bl : Bh;
                const __half* src = ok ? (base + (size_t)(n0 + row)*ldb + k0 + c*8) : base;
                cp_async16(so, src, ok);
            }
        }
        cp_commit();
    };

    const int nkt = K >> 5;
    load_tile(0, 0);
    if (nkt > 1) load_tile(1, 1);
    for (int kt = 0; kt < nkt; kt++){
        const int s = kt % 3;
        if (kt + 1 < nkt) cp_wait<1>(); else cp_wait<0>();
        __syncthreads();
        if (kt + 2 < nkt) load_tile(kt + 2, (kt + 2) % 3);
        const uint32_t sbs = sb0 + (uint32_t)s * STAGE;

        #pragma unroll
        for (int ks = 0; ks < 2; ks++){
            const uint32_t kx = (uint32_t)(ks << 5);
            uint32_t bhf[2][4], blf[2][4];
            #pragma unroll
            for (int nb = 0; nb < 2; nb++){
                uint32_t t = (sbs + boff[nb]) ^ kx;
                ldsm4(bhf[nb], t);
                ldsm4(blf[nb], t + ST_BLO);
            }
            #pragma unroll
            for (int mt = 0; mt < 4; mt++){
                uint32_t ahf[4], alf[4];
                uint32_t t = (sbs + aoff[mt]) ^ kx;
                ldsm4(ahf, t);
                ldsm4(alf, t + ST_ALO);
                #pragma unroll
                for (int nt = 0; nt < 4; nt++){
                    const int nb = nt >> 1, p = (nt & 1) * 2;
                    float* d = acc[mt][nt];
                    mma16(d, ahf, bhf[nb][p], bhf[nb][p+1]);   // hi*hi
                    mma16(d, ahf, blf[nb][p], blf[nb][p+1]);   // hi*lo
                    mma16(d, alf, bhf[nb][p], bhf[nb][p+1]);   // lo*hi
                }
            }
        }
    }

    // epilogue: registers -> gmem
    #pragma unroll
    for (int mt = 0; mt < 4; mt++){
        #pragma unroll
        for (int nt = 0; nt < 4; nt++){
            int row = m0 + wm*64 + mt*16 + lr;
            int col = n0 + wn*32 + nt*8 + lc*2;
            float* a = acc[mt][nt];
            if (EPI == EP_BIASRELU){
                float b0 = bias[col], b1 = bias[col+1];
                float v0 = a[0] + b0, v1 = a[1] + b1, v2 = a[2] + b0, v3 = a[3] + b1;
                v0 = v0 > 0.f ? v0 : 0.f; v1 = v1 > 0.f ? v1 : 0.f;
                v2 = v2 > 0.f ? v2 : 0.f; v3 = v3 > 0.f ? v3 : 0.f;
                *(float2*)&C[(size_t)row*ldc + col]     = make_float2(v0, v1);
                *(float2*)&C[(size_t)(row+8)*ldc + col] = make_float2(v2, v3);
            } else if (EPI == EP_PLAIN){
                *(float2*)&C[(size_t)row*ldc + col]     = make_float2(a[0], a[1]);
                *(float2*)&C[(size_t)(row+8)*ldc + col] = make_float2(a[2], a[3]);
            } else { // EP_PAD: half hi/lo planes, zero pad columns
                if (col + 2 <= ldc){
                    float v0 = (col   < Nreal) ? a[0] : 0.f;
                    float v1 = (col+1 < Nreal) ? a[1] : 0.f;
                    float v2 = (col   < Nreal) ? a[2] : 0.f;
                    float v3 = (col+1 < Nreal) ? a[3] : 0.f;
                    __half h0,l0,h1,l1,h2,l2,h3,l3;
                    split16(v0,h0,l0); split16(v1,h1,l1);
                    split16(v2,h2,l2); split16(v3,h3,l3);
                    *(__half2*)&Ch[(size_t)row*ldc + col]     = __halves2half2(h0, h1);
                    *(__half2*)&Cl[(size_t)row*ldc + col]     = __halves2half2(l0, l1);
                    *(__half2*)&Ch[(size_t)(row+8)*ldc + col] = __halves2half2(h2, h3);
                    *(__half2*)&Cl[(size_t)(row+8)*ldc + col] = __halves2half2(l2, l3);
                }
            }
        }
    }
}

// ---------------- fp32 -> fp16 hi/lo split ------------------------------------
__global__ void __launch_bounds__(256) split_kernel(
    const float* __restrict__ x, __half* __restrict__ h, __half* __restrict__ l, int n)
{
    int i = blockIdx.x*256 + threadIdx.x;
    if (i < n){ __half hv, lv; split16(x[i], hv, lv); h[i] = hv; l[i] = lv; }
}

// ---------------- 3-class head --------------------------------------------------
__global__ void __launch_bounds__(256) logits_kernel(
    const float* __restrict__ h, const float* __restrict__ W2,
    const float* __restrict__ b2, float* __restrict__ out0, int* __restrict__ pred)
{
    __shared__ float w2s[3*Hh];
    int tid = threadIdx.x;
    for (int i = tid; i < 3*Hh; i += 256) w2s[i] = W2[i];
    __syncthreads();
    int warp = tid >> 5, lane = tid & 31;
    int row = blockIdx.x*8 + warp;
    const float* hp = h + (size_t)row*Hh;
    float s0=0.f, s1=0.f, s2=0.f;
    for (int i = lane; i < Hh; i += 32){
        float hv = hp[i];
        s0 += hv*w2s[i]; s1 += hv*w2s[Hh+i]; s2 += hv*w2s[2*Hh+i];
    }
    #pragma unroll
    for (int off=16; off; off>>=1){
        s0 += __shfl_xor_sync(0xffffffffu, s0, off);
        s1 += __shfl_xor_sync(0xffffffffu, s1, off);
        s2 += __shfl_xor_sync(0xffffffffu, s2, off);
    }
    if (lane == 0){
        s0 += b2[0]; s1 += b2[1]; s2 += b2[2];
        float m = fmaxf(s0, fmaxf(s1, s2));
        float lse = m + logf(expf(s0-m)+expf(s1-m)+expf(s2-m));
        size_t o = (size_t)row*3;
        out0[o+0] = s0 - lse; out0[o+1] = s1 - lse; out0[o+2] = s2 - lse;
        int idx = 0; float best = s0;
        if (s1 > best){ best = s1; idx = 1; }
        if (s2 > best){ idx = 2; }
        pred[row] = idx;
    }
}

// ---------------- BIO segment scan (warp-parallel, ballot-based) ----------------
__global__ void scan_kernel(const int* __restrict__ labels,
                            int* __restrict__ rowinfo, int* __restrict__ nvraw)
{
    __shared__ int pos[513];
    int b = blockIdx.x, lane = threadIdx.x;
    const int* lab = labels + b*Tt;
    int base = 0;
    int first1 = Tt;
    int any2 = 0;
    #pragma unroll 1
    for (int c = 0; c < Tt/32; c++){
        int l = lab[c*32 + lane];
        unsigned m1 = __ballot_sync(0xffffffffu, l == 1);
        unsigned m2 = __ballot_sync(0xffffffffu, l == 2);
        if (l == 1) pos[base + __popc(m1 & ((1u<<lane)-1))] = c*32 + lane;
        if (first1 == Tt){
            if (m1){
                int fl = __ffs(m1) - 1;
                first1 = c*32 + fl;
                any2 |= (m2 & ((1u<<fl)-1)) != 0;
            } else any2 |= (m2 != 0);
        }
        base += __popc(m1);
    }
    int m = base;
    int lead = any2;
    __syncwarp();
    if (lane == 0){
        pos[m] = Tt;
        if (lead) rowinfo[b*Tt] = (0<<16) | (m ? pos[0] : Tt);
        nvraw[b] = lead + m;
    }
    __syncwarp();
    for (int j = lane; j < m; j += 32){
        int s = pos[j], e = pos[j+1];
        rowinfo[b*Tt + lead + j] = (s<<16) | e;
    }
}

// ---------------- global compaction bookkeeping ---------------------------------
__global__ void combine2_kernel(const int* __restrict__ nvraw0, const int* __restrict__ nvraw1,
                                int* __restrict__ base0, int* __restrict__ base1,
                                int* __restrict__ lsm_nv, int* __restrict__ lsm_base,
                                int* __restrict__ rtot)
{
    if (threadIdx.x || blockIdx.x) return;
    int off = 0;
    int cnt = 0;
    for (int b=0;b<Bb;b++){
        int nv = nvraw0[b];
        if (nv > 0){ base0[b] = off; lsm_base[cnt] = off; lsm_nv[cnt] = nv; cnt++; off += nv; }
        else base0[b] = -1;
    }
    for (int k=cnt;k<Bb;k++) lsm_nv[k] = 0;
    cnt = 0;
    for (int b=0;b<Bb;b++){
        int nv = nvraw1[b];
        if (nv > 0){ base1[b] = off; lsm_base[Bb+cnt] = off; lsm_nv[Bb+cnt] = nv; cnt++; off += nv; }
        else base1[b] = -1;
    }
    for (int k=cnt;k<Bb;k++) lsm_nv[Bb+k] = 0;
    rtot[1] = off;
    rtot[0] = (off + 255) & ~255;   // Rpad
}

// ---------------- zero pooled pad rows [R, Rpad) --------------------------------
__global__ void __launch_bounds__(256) padzero_kernel(
    const int* __restrict__ rtot, __half* __restrict__ ph, __half* __restrict__ pl)
{
    int row = rtot[1] + blockIdx.x;
    if (row >= rtot[0]) return;
    size_t off = (size_t)row*Hh;
    __half z = __float2half(0.f);
    for (int i = threadIdx.x; i < Hh; i += 256){ ph[off+i] = z; pl[off+i] = z; }
}

// ---------------- segment means -> globally compacted pooled rows ---------------
__global__ void __launch_bounds__(256) pool_kernel(
    const int* __restrict__ labels, const float* __restrict__ hidden,
    const int* __restrict__ rowinfo, const int* __restrict__ nvraw,
    const int* __restrict__ basearr, __half* __restrict__ ph, __half* __restrict__ pl)
{
    int b = blockIdx.x;
    int d = basearr[b];
    if (d < 0) return;
    int nv = nvraw[b];
    __shared__ int labs[Tt];
    int tid = threadIdx.x;
    for (int i=tid;i<Tt;i+=256) labs[i] = labels[b*Tt+i];
    __syncthreads();
    int r0 = blockIdx.y * 32;
    int r1 = min(r0+32, nv);
    for (int r=r0; r<r1; r++){
        int info = rowinfo[b*Tt + r];
        int s = info >> 16, e = info & 0xffff;
        float a0=0.f,a1=0.f,a2=0.f;
        int cnt = 0;
        for (int t=s;t<e;t++){
            if (labs[t] != 0){
                cnt++;
                const float* hp = hidden + ((size_t)(b*Tt)+t)*Hh;
                a0 += hp[tid]; a1 += hp[tid+256]; a2 += hp[tid+512];
            }
        }
        float inv = 1.0f / (float)cnt;
        size_t off = ((size_t)(d + r))*Hh;
        __half hv, lv;
        split16(a0*inv, hv, lv); ph[off+tid]     = hv; pl[off+tid]     = lv;
        split16(a1*inv, hv, lv); ph[off+tid+256] = hv; pl[off+tid+256] = lv;
        split16(a2*inv, hv, lv); ph[off+tid+512] = hv; pl[off+tid+512] = lv;
    }
}

// ---------------- row log-softmax over compacted sc ------------------------------
__global__ void __launch_bounds__(256) lsm_kernel(
    const float* __restrict__ sc, const int* __restrict__ lsm_nv,
    const int* __restrict__ lsm_base, float* __restrict__ out1, float* __restrict__ out2)
{
    int row = blockIdx.x*8 + (threadIdx.x >> 5);  // output row within a pass
    int p   = blockIdx.y;
    int lane = threadIdx.x & 31;
    int bb = row >> 9, t = row & 511;
    int nv = lsm_nv[p*Bb + bb];
    float* op = (p ? out2 : out1) + (size_t)row*Nn;
    if (t >= nv){
        const float CNEG = -7.6246189861593985f;   // -log(2048)
        float4 c4 = make_float4(CNEG,CNEG,CNEG,CNEG);
        for (int i=lane;i<Nn/4;i+=32) ((float4*)op)[i] = c4;
        return;
    }
    int srow = lsm_base[p*Bb + bb] + t;
    const float4* ip = (const float4*)(sc + (size_t)srow*Nn);
    float4 v[16];
    float m = -3.4e38f;
    #pragma unroll
    for (int i=0;i<16;i++){
        v[i] = ip[lane + i*32];
        m = fmaxf(m, fmaxf(fmaxf(v[i].x,v[i].y), fmaxf(v[i].z,v[i].w)));
    }
    #pragma unroll
    for (int off=16;off;off>>=1) m = fmaxf(m, __shfl_xor_sync(0xffffffffu, m, off));
    float s = 0.f;
    #pragma unroll
    for (int i=0;i<16;i++)
        s += expf(v[i].x-m)+expf(v[i].y-m)+expf(v[i].z-m)+expf(v[i].w-m);
    #pragma unroll
    for (int off=16;off;off>>=1) s += __shfl_xor_sync(0xffffffffu, s, off);
    float corr = m + logf(s);
    #pragma unroll
    for (int i=0;i<16;i++){
        float4 o = v[i];
        o.x-=corr; o.y-=corr; o.z-=corr; o.w-=corr;
        ((float4*)op)[lane + i*32] = o;
    }
}

// ---------------- host -------------------------------------------------------------
extern "C" void kernel_launch(void* const* d_in, const int* in_sizes, int n_in,
                              void* d_out, int out_size)
{
    (void)in_sizes; (void)n_in; (void)out_size;
    const int*   labels = (const int*)  d_in[0];
    const float* hidden = (const float*)d_in[1];
    const float* ent    = (const float*)d_in[2];
    const float* W1     = (const float*)d_in[3];
    const float* b1     = (const float*)d_in[4];
    const float* W2     = (const float*)d_in[5];
    const float* b2     = (const float*)d_in[6];
    const float* Wm     = (const float*)d_in[7];
    const float* Wd     = (const float*)d_in[8];

    float* out0 = (float*)d_out;
    float* s1o  = out0 + (size_t)BT*3;
    float* s2o  = s1o  + (size_t)BT*Nn;

    __half *hidh,*hidl,*enth,*entl,*w1h,*w1l,*wmh,*wml,*wdh,*wdl;
    __half *poolh,*pooll,*pmh,*pml,*pdh,*pdl;
    float *h, *sc;
    int *pred, *ri0, *ri1, *nv0, *nv1, *b0, *b1a, *lnv, *lbs, *rtot;
    cudaGetSymbolAddress((void**)&hidh, g_hid_h);  cudaGetSymbolAddress((void**)&hidl, g_hid_l);
    cudaGetSymbolAddress((void**)&enth, g_ent_h);  cudaGetSymbolAddress((void**)&entl, g_ent_l);
    cudaGetSymbolAddress((void**)&w1h,  g_W1_h);   cudaGetSymbolAddress((void**)&w1l,  g_W1_l);
    cudaGetSymbolAddress((void**)&wmh,  g_Wm_h);   cudaGetSymbolAddress((void**)&wml,  g_Wm_l);
    cudaGetSymbolAddress((void**)&wdh,  g_Wd_h);   cudaGetSymbolAddress((void**)&wdl,  g_Wd_l);
    cudaGetSymbolAddress((void**)&poolh,g_pool_h); cudaGetSymbolAddress((void**)&pooll,g_pool_l);
    cudaGetSymbolAddress((void**)&pmh,  g_pm_h);   cudaGetSymbolAddress((void**)&pml,  g_pm_l);
    cudaGetSymbolAddress((void**)&pdh,  g_pd_h);   cudaGetSymbolAddress((void**)&pdl,  g_pd_l);
    cudaGetSymbolAddress((void**)&h,    g_h);
    cudaGetSymbolAddress((void**)&sc,   g_sc);
    cudaGetSymbolAddress((void**)&pred, g_pred);
    cudaGetSymbolAddress((void**)&ri0,  g_rowinfo0);
    cudaGetSymbolAddress((void**)&ri1,  g_rowinfo1);
    cudaGetSymbolAddress((void**)&nv0,  g_nvraw0);
    cudaGetSymbolAddress((void**)&nv1,  g_nvraw1);
    cudaGetSymbolAddress((void**)&b0,   g_base0);
    cudaGetSymbolAddress((void**)&b1a,  g_base1);
    cudaGetSymbolAddress((void**)&lnv,  g_lsm_nv);
    cudaGetSymbolAddress((void**)&lbs,  g_lsm_base);
    cudaGetSymbolAddress((void**)&rtot, g_Rtot);

    cudaFuncSetAttribute((const void*)mma_gemm<EP_BIASRELU,false>, cudaFuncAttributeMaxDynamicSharedMemorySize, SMEMSZ);
    cudaFuncSetAttribute((const void*)mma_gemm<EP_PAD,false>,      cudaFuncAttributeMaxDynamicSharedMemorySize, SMEMSZ);
    cudaFuncSetAttribute((const void*)mma_gemm<EP_PAD,true>,       cudaFuncAttributeMaxDynamicSharedMemorySize, SMEMSZ);
    cudaFuncSetAttribute((const void*)mma_gemm<EP_PLAIN,true>,     cudaFuncAttributeMaxDynamicSharedMemorySize, SMEMSZ);

    // launches 1-3: splits needed by gemm1; launch 4 = gemm1 (ncu capture slot)
    split_kernel<<<(BT*Hh+255)/256, 256>>>(hidden, hidh, hidl, BT*Hh);
    split_kernel<<<(Hh*Hh+255)/256, 256>>>(W1, w1h, w1l, Hh*Hh);
    split_kernel<<<(Nn*Hh+255)/256, 256>>>(ent, enth, entl, Nn*Hh);

    // 1) h = relu(x @ W1^T + b1)
    mma_gemm<EP_BIASRELU,false><<<dim3(Hh/128, BT/256), NTHR, SMEMSZ>>>(
        hidh, hidl, w1h, w1l, h, nullptr, nullptr, Hh, Hh, Hh, Hh, Hh, Hh, b1, nullptr);

    split_kernel<<<(Pp*Hh+255)/256, 256>>>(Wm, wmh, wml, Pp*Hh);
    split_kernel<<<(Pp*Hh+255)/256, 256>>>(Wd, wdh, wdl, Pp*Hh);

    // 2) bio logits -> out0 + predicted labels
    logits_kernel<<<BT/8, 256>>>(h, W2, b2, out0, pred);

    // 3) pd = ent @ Wd^T -> half hi/lo planes, K-padded to KP
    mma_gemm<EP_PAD,false><<<dim3(3, Nn/256), NTHR, SMEMSZ>>>(
        enth, entl, wdh, wdl, nullptr, pdh, pdl, Hh, Hh, KP, Hh, Pp, Pp, nullptr, nullptr);

    // 4) both pooling passes, globally compacted
    scan_kernel<<<Bb, 32>>>(labels, ri0, nv0);
    scan_kernel<<<Bb, 32>>>(pred,   ri1, nv1);
    combine2_kernel<<<1, 1>>>(nv0, nv1, b0, b1a, lnv, lbs, rtot);
    pool_kernel<<<dim3(Bb, 16), 256>>>(labels, hidden, ri0, nv0, b0,  poolh, pooll);
    pool_kernel<<<dim3(Bb, 16), 256>>>(pred,   hidden, ri1, nv1, b1a, poolh, pooll);
    padzero_kernel<<<256, 256>>>(rtot, poolh, pooll);

    // 5) pm = pooled @ Wm^T over compacted rows (single launch, both passes)
    mma_gemm<EP_PAD,true><<<dim3(3, BT2/256), NTHR, SMEMSZ>>>(
        poolh, pooll, wmh, wml, nullptr, pmh, pml, Hh, Hh, KP, Hh, Pp, Pp, nullptr, rtot);

    // 6) sc = pm @ pd^T over compacted rows (single launch)
    mma_gemm<EP_PLAIN,true><<<dim3(Nn/128, BT2/256), NTHR, SMEMSZ>>>(
        pmh, pml, pdh, pdl, sc, nullptr, nullptr, KP, KP, Nn, KP, Nn, Nn, nullptr, rtot);

    // 7) log-softmax scatter to both outputs
    lsm_kernel<<<dim3(BT/8, 2), 256>>>(sc, lnv, lbs, s1o, s2o);
}

// round 10
// speedup vs baseline: 2.9653x; 1.0676x over previous
#include <cuda_runtime.h>
#include <cuda_fp16.h>
#include <math.h>
#include <stdint.h>

#define Bb 64
#define Tt 512
#define Hh 768
#define Nn 2048
#define Pp 300
#define KP 320
#define BT (Bb*Tt)
#define BT2 (2*BT)

// ---------------- scratch (device globals; no allocation allowed) ----------
__device__ __half g_hid_h[(size_t)BT*Hh],   g_hid_l[(size_t)BT*Hh];
__device__ __half g_ent_h[(size_t)Nn*Hh],   g_ent_l[(size_t)Nn*Hh];
__device__ __half g_W1_h[Hh*Hh],            g_W1_l[Hh*Hh];
__device__ __half g_Wm_h[Pp*Hh],            g_Wm_l[Pp*Hh];
__device__ __half g_Wd_h[Pp*Hh],            g_Wd_l[Pp*Hh];
__device__ __half g_pool_h[(size_t)BT2*Hh], g_pool_l[(size_t)BT2*Hh];
__device__ __half g_pm_h[(size_t)BT2*KP],   g_pm_l[(size_t)BT2*KP];
__device__ __half g_pd_h[(size_t)Nn*KP],    g_pd_l[(size_t)Nn*KP];
__device__ float  g_h[(size_t)BT*Hh];
__device__ float  g_sc[(size_t)BT2*Nn];
__device__ int    g_pred[BT];
__device__ int    g_rowinfo0[BT], g_rowinfo1[BT];
__device__ int    g_nvraw0[Bb],  g_nvraw1[Bb];
__device__ int    g_base0[Bb],   g_base1[Bb];
__device__ int    g_lsm_nv[2*Bb], g_lsm_base[2*Bb];
__device__ int    g_Rtot[4];                     // [0]=Rpad  [1]=R

// ---------------- helpers ----------------------------------------------------
__device__ __forceinline__ uint32_t smem_u32(const void* p){
    uint32_t a;
    asm("{ .reg .u64 t; cvta.to.shared.u64 t, %1; cvt.u32.u64 %0, t; }" : "=r"(a) : "l"(p));
    return a;
}
__device__ __forceinline__ void cp_async16(uint32_t dst, const void* src, bool ok){
    int sz = ok ? 16 : 0;   // src-size 0 -> zero-fill 16B
    asm volatile("cp.async.cg.shared.global [%0], [%1], 16, %2;" :: "r"(dst), "l"(src), "r"(sz));
}
__device__ __forceinline__ void cp_commit(){ asm volatile("cp.async.commit_group;" ::: "memory"); }
template<int N> __device__ __forceinline__ void cp_wait(){ asm volatile("cp.async.wait_group %0;" :: "n"(N) : "memory"); }

__device__ __forceinline__ void ldsm4(uint32_t* r, uint32_t addr){
    asm volatile("ldmatrix.sync.aligned.m8n8.x4.shared.b16 {%0,%1,%2,%3}, [%4];"
        : "=r"(r[0]), "=r"(r[1]), "=r"(r[2]), "=r"(r[3]) : "r"(addr));
}
__device__ __forceinline__ void mma16(float* d, const uint32_t* a, uint32_t b0, uint32_t b1){
    asm volatile(
        "mma.sync.aligned.m16n8k16.row.col.f32.f16.f16.f32 "
        "{%0,%1,%2,%3}, {%4,%5,%6,%7}, {%8,%9}, {%0,%1,%2,%3};"
        : "+f"(d[0]), "+f"(d[1]), "+f"(d[2]), "+f"(d[3])
        : "r"(a[0]), "r"(a[1]), "r"(a[2]), "r"(a[3]), "r"(b0), "r"(b1));
}
__device__ __forceinline__ void split16(float v, __half& h, __half& l){
    h = __float2half_rn(v);
    l = __float2half_rn(v - __half2float(h));
}

// ---------------- fp16 3-term GEMM: C[M,N] = A[M,K] @ B[N,K]^T ---------------
// CTA tile 128x128, BK=32, 8 warps (2m x 4n), warp tile 64x32, 3-stage cp.async,
// __launch_bounds__(256,2) -> <=128 regs -> 2 CTAs/SM (barriers overlap).
enum { EP_BIASRELU = 0, EP_PAD = 1, EP_PLAIN = 2 };
#define ST_ALO 8192
#define ST_B   16384
#define ST_BLO 8192      // relative to ST_B
#define STAGE  32768
#define SMEMSZ (3*STAGE) // 98304 per CTA -> 2 CTAs = 192K < 228K
#define NTHR 256

template<int EPI, bool ROWMASK>
__global__ void __launch_bounds__(NTHR, 2) mma_gemm(
    const __half* __restrict__ Ah, const __half* __restrict__ Al,
    const __half* __restrict__ Bh, const __half* __restrict__ Bl,
    float* __restrict__ C, __half* __restrict__ Ch, __half* __restrict__ Cl,
    int lda, int ldb, int ldc, int K, int Nreal, int NBreal,
    const float* __restrict__ bias, const int* __restrict__ rtot)
{
    extern __shared__ char smem[];
    const int m0 = blockIdx.y * 128, n0 = blockIdx.x * 128;
    const int tid = threadIdx.x;
    if (ROWMASK){
        if (m0 >= rtot[0]) return;     // beyond compacted rows
    }
    const uint32_t sb0 = smem_u32(smem);
    const int warp = tid >> 5, lane = tid & 31;
    const int wm = warp >> 2, wn = warp & 3;     // 2 x 4 warp grid, warp tile 64x32
    const int lr = lane >> 2, lc = lane & 3;

    float acc[4][4][4];
    #pragma unroll
    for (int i=0;i<4;i++)
        #pragma unroll
        for (int j=0;j<4;j++)
            #pragma unroll
            for (int q=0;q<4;q++) acc[i][j][q] = 0.f;

    const int arl = (lane & 7) + ((lane >> 3) & 1) * 8;
    const int acs = lane >> 4;
    const int nrl = (lane & 7) + (lane >> 4) * 8;
    const int bcs = (lane >> 3) & 1;
    uint32_t aoff[4], boff[2];
    #pragma unroll
    for (int mt = 0; mt < 4; mt++){
        int r = wm*64 + mt*16 + arl;
        aoff[mt] = (uint32_t)(r*64) + (uint32_t)((acs ^ (r & 3) ^ ((r >> 2) & 1)) << 4);
    }
    #pragma unroll
    for (int nb = 0; nb < 2; nb++){
        int r = wn*32 + nb*16 + nrl;
        boff[nb] = (uint32_t)ST_B + (uint32_t)(r*64) + (uint32_t)((bcs ^ (r & 3) ^ ((r >> 2) & 1)) << 4);
    }

    auto load_tile = [&](int kt, int s){
        const int k0 = kt * 32;
        const uint32_t sbs = sb0 + (uint32_t)s * STAGE;
        #pragma unroll
        for (int j = 0; j < 8; j++){
            int idx = tid + j*NTHR;                 // 0..2047 16B-chunks
            if (idx < 1024){                        // A planes: 128 rows x 4 chunks x2
                int pl  = idx >> 9;
                int rem = idx & 511;
                int row = rem >> 2, c = rem & 3;
                int c2  = c ^ (row & 3) ^ ((row >> 2) & 1);
                uint32_t so = sbs + (uint32_t)(pl*ST_ALO + row*64 + c2*16);
                const __half* src = (pl ? Al : Ah) + (size_t)(m0 + row)*lda + k0 + c*8;
                cp_async16(so, src, true);
            } else {                                // B planes: 128 rows x 4 chunks x2
                int b   = idx - 1024;
                int pl  = b >> 9;
                int rem = b & 511;
                int row = rem >> 2, c = rem & 3;
                int c2  = c ^ (row & 3) ^ ((row >> 2) & 1);
                uint32_t so = sbs + (uint32_t)(ST_B + pl*ST_BLO + row*64 + c2*16);
                bool ok = (n0 + row) < NBreal;
                const __half* base = pl ? Bl : Bh;
                const __half* src = ok ? (base + (size_t)(n0 + row)*ldb + k0 + c*8) : base;
                cp_async16(so, src, ok);
            }
        }
        cp_commit();
    };

    const int nkt = K >> 5;
    load_tile(0, 0);
    if (nkt > 1) load_tile(1, 1);
    for (int kt = 0; kt < nkt; kt++){
        const int s = kt % 3;
        if (kt + 1 < nkt) cp_wait<1>(); else cp_wait<0>();
        __syncthreads();
        if (kt + 2 < nkt) load_tile(kt + 2, (kt + 2) % 3);
        const uint32_t sbs = sb0 + (uint32_t)s * STAGE;

        #pragma unroll
        for (int ks = 0; ks < 2; ks++){
            const uint32_t kx = (uint32_t)(ks << 5);
            uint32_t bhf[2][4], blf[2][4];
            #pragma unroll
            for (int nb = 0; nb < 2; nb++){
                uint32_t t = (sbs + boff[nb]) ^ kx;
                ldsm4(bhf[nb], t);
                ldsm4(blf[nb], t + ST_BLO);
            }
            #pragma unroll
            for (int mt = 0; mt < 4; mt++){
                uint32_t ahf[4], alf[4];
                uint32_t t = (sbs + aoff[mt]) ^ kx;
                ldsm4(ahf, t);
                ldsm4(alf, t + ST_ALO);
                #pragma unroll
                for (int nt = 0; nt < 4; nt++){
                    const int nb = nt >> 1, p = (nt & 1) * 2;
                    float* d = acc[mt][nt];
                    mma16(d, ahf, bhf[nb][p], bhf[nb][p+1]);   // hi*hi
                    mma16(d, ahf, blf[nb][p], blf[nb][p+1]);   // hi*lo
                    mma16(d, alf, bhf[nb][p], bhf[nb][p+1]);   // lo*hi
                }
            }
        }
    }

    // epilogue: registers -> gmem
    #pragma unroll
    for (int mt = 0; mt < 4; mt++){
        #pragma unroll
        for (int nt = 0; nt < 4; nt++){
            int row = m0 + wm*64 + mt*16 + lr;
            int col = n0 + wn*32 + nt*8 + lc*2;
            float* a = acc[mt][nt];
            if (EPI == EP_BIASRELU){
                float b0 = bias[col], b1 = bias[col+1];
                float v0 = a[0] + b0, v1 = a[1] + b1, v2 = a[2] + b0, v3 = a[3] + b1;
                v0 = v0 > 0.f ? v0 : 0.f; v1 = v1 > 0.f ? v1 : 0.f;
                v2 = v2 > 0.f ? v2 : 0.f; v3 = v3 > 0.f ? v3 : 0.f;
                *(float2*)&C[(size_t)row*ldc + col]     = make_float2(v0, v1);
                *(float2*)&C[(size_t)(row+8)*ldc + col] = make_float2(v2, v3);
            } else if (EPI == EP_PLAIN){
                *(float2*)&C[(size_t)row*ldc + col]     = make_float2(a[0], a[1]);
                *(float2*)&C[(size_t)(row+8)*ldc + col] = make_float2(a[2], a[3]);
            } else { // EP_PAD: half hi/lo planes, zero pad columns
                if (col + 2 <= ldc){
                    float v0 = (col   < Nreal) ? a[0] : 0.f;
                    float v1 = (col+1 < Nreal) ? a[1] : 0.f;
                    float v2 = (col   < Nreal) ? a[2] : 0.f;
                    float v3 = (col+1 < Nreal) ? a[3] : 0.f;
                    __half h0,l0,h1,l1,h2,l2,h3,l3;
                    split16(v0,h0,l0); split16(v1,h1,l1);
                    split16(v2,h2,l2); split16(v3,h3,l3);
                    *(__half2*)&Ch[(size_t)row*ldc + col]     = __halves2half2(h0, h1);
                    *(__half2*)&Cl[(size_t)row*ldc + col]     = __halves2half2(l0, l1);
                    *(__half2*)&Ch[(size_t)(row+8)*ldc + col] = __halves2half2(h2, h3);
                    *(__half2*)&Cl[(size_t)(row+8)*ldc + col] = __halves2half2(l2, l3);
                }
            }
        }
    }
}

// ---------------- fp32 -> fp16 hi/lo split ------------------------------------
__global__ void __launch_bounds__(256) split_kernel(
    const float* __restrict__ x, __half* __restrict__ h, __half* __restrict__ l, int n)
{
    int i = blockIdx.x*256 + threadIdx.x;
    if (i < n){ __half hv, lv; split16(x[i], hv, lv); h[i] = hv; l[i] = lv; }
}

// ---------------- 3-class head --------------------------------------------------
__global__ void __launch_bounds__(256) logits_kernel(
    const float* __restrict__ h, const float* __restrict__ W2,
    const float* __restrict__ b2, float* __restrict__ out0, int* __restrict__ pred)
{
    __shared__ float w2s[3*Hh];
    int tid = threadIdx.x;
    for (int i = tid; i < 3*Hh; i += 256) w2s[i] = W2[i];
    __syncthreads();
    int warp = tid >> 5, lane = tid & 31;
    int row = blockIdx.x*8 + warp;
    const float* hp = h + (size_t)row*Hh;
    float s0=0.f, s1=0.f, s2=0.f;
    for (int i = lane; i < Hh; i += 32){
        float hv = hp[i];
        s0 += hv*w2s[i]; s1 += hv*w2s[Hh+i]; s2 += hv*w2s[2*Hh+i];
    }
    #pragma unroll
    for (int off=16; off; off>>=1){
        s0 += __shfl_xor_sync(0xffffffffu, s0, off);
        s1 += __shfl_xor_sync(0xffffffffu, s1, off);
        s2 += __shfl_xor_sync(0xffffffffu, s2, off);
    }
    if (lane == 0){
        s0 += b2[0]; s1 += b2[1]; s2 += b2[2];
        float m = fmaxf(s0, fmaxf(s1, s2));
        float lse = m + logf(expf(s0-m)+expf(s1-m)+expf(s2-m));
        size_t o = (size_t)row*3;
        out0[o+0] = s0 - lse; out0[o+1] = s1 - lse; out0[o+2] = s2 - lse;
        int idx = 0; float best = s0;
        if (s1 > best){ best = s1; idx = 1; }
        if (s2 > best){ idx = 2; }
        pred[row] = idx;
    }
}

// ---------------- BIO segment scan (warp-parallel, ballot-based) ----------------
__global__ void scan_kernel(const int* __restrict__ labels,
                            int* __restrict__ rowinfo, int* __restrict__ nvraw)
{
    __shared__ int pos[513];
    int b = blockIdx.x, lane = threadIdx.x;
    const int* lab = labels + b*Tt;
    int base = 0;
    int first1 = Tt;
    int any2 = 0;
    #pragma unroll 1
    for (int c = 0; c < Tt/32; c++){
        int l = lab[c*32 + lane];
        unsigned m1 = __ballot_sync(0xffffffffu, l == 1);
        unsigned m2 = __ballot_sync(0xffffffffu, l == 2);
        if (l == 1) pos[base + __popc(m1 & ((1u<<lane)-1))] = c*32 + lane;
        if (first1 == Tt){
            if (m1){
                int fl = __ffs(m1) - 1;
                first1 = c*32 + fl;
                any2 |= (m2 & ((1u<<fl)-1)) != 0;
            } else any2 |= (m2 != 0);
        }
        base += __popc(m1);
    }
    int m = base;
    int lead = any2;
    __syncwarp();
    if (lane == 0){
        pos[m] = Tt;
        if (lead) rowinfo[b*Tt] = (0<<16) | (m ? pos[0] : Tt);
        nvraw[b] = lead + m;
    }
    __syncwarp();
    for (int j = lane; j < m; j += 32){
        int s = pos[j], e = pos[j+1];
        rowinfo[b*Tt + lead + j] = (s<<16) | e;
    }
}

// ---------------- global compaction bookkeeping ---------------------------------
__global__ void combine2_kernel(const int* __restrict__ nvraw0, const int* __restrict__ nvraw1,
                                int* __restrict__ base0, int* __restrict__ base1,
                                int* __restrict__ lsm_nv, int* __restrict__ lsm_base,
                                int* __restrict__ rtot)
{
    if (threadIdx.x || blockIdx.x) return;
    int off = 0;
    int cnt = 0;
    for (int b=0;b<Bb;b++){
        int nv = nvraw0[b];
        if (nv > 0){ base0[b] = off; lsm_base[cnt] = off; lsm_nv[cnt] = nv; cnt++; off += nv; }
        else base0[b] = -1;
    }
    for (int k=cnt;k<Bb;k++) lsm_nv[k] = 0;
    cnt = 0;
    for (int b=0;b<Bb;b++){
        int nv = nvraw1[b];
        if (nv > 0){ base1[b] = off; lsm_base[Bb+cnt] = off; lsm_nv[Bb+cnt] = nv; cnt++; off += nv; }
        else base1[b] = -1;
    }
    for (int k=cnt;k<Bb;k++) lsm_nv[Bb+k] = 0;
    rtot[1] = off;
    rtot[0] = (off + 127) & ~127;   // Rpad (128-row tiles)
}

// ---------------- zero pooled pad rows [R, Rpad) --------------------------------
__global__ void __launch_bounds__(256) padzero_kernel(
    const int* __restrict__ rtot, __half* __restrict__ ph, __half* __restrict__ pl)
{
    int row = rtot[1] + blockIdx.x;
    if (row >= rtot[0]) return;
    size_t off = (size_t)row*Hh;
    __half z = __float2half(0.f);
    for (int i = threadIdx.x; i < Hh; i += 256){ ph[off+i] = z; pl[off+i] = z; }
}

// ---------------- segment means -> globally compacted pooled rows ---------------
__global__ void __launch_bounds__(256) pool_kernel(
    const int* __restrict__ labels, const float* __restrict__ hidden,
    const int* __restrict__ rowinfo, const int* __restrict__ nvraw,
    const int* __restrict__ basearr, __half* __restrict__ ph, __half* __restrict__ pl)
{
    int b = blockIdx.x;
    int d = basearr[b];
    if (d < 0) return;
    int nv = nvraw[b];
    __shared__ int labs[Tt];
    int tid = threadIdx.x;
    for (int i=tid;i<Tt;i+=256) labs[i] = labels[b*Tt+i];
    __syncthreads();
    int r0 = blockIdx.y * 32;
    int r1 = min(r0+32, nv);
    for (int r=r0; r<r1; r++){
        int info = rowinfo[b*Tt + r];
        int s = info >> 16, e = info & 0xffff;
        float a0=0.f,a1=0.f,a2=0.f;
        int cnt = 0;
        for (int t=s;t<e;t++){
            if (labs[t] != 0){
                cnt++;
                const float* hp = hidden + ((size_t)(b*Tt)+t)*Hh;
                a0 += hp[tid]; a1 += hp[tid+256]; a2 += hp[tid+512];
            }
        }
        float inv = 1.0f / (float)cnt;
        size_t off = ((size_t)(d + r))*Hh;
        __half hv, lv;
        split16(a0*inv, hv, lv); ph[off+tid]     = hv; pl[off+tid]     = lv;
        split16(a1*inv, hv, lv); ph[off+tid+256] = hv; pl[off+tid+256] = lv;
        split16(a2*inv, hv, lv); ph[off+tid+512] = hv; pl[off+tid+512] = lv;
    }
}

// ---------------- row log-softmax over compacted sc ------------------------------
__global__ void __launch_bounds__(256) lsm_kernel(
    const float* __restrict__ sc, const int* __restrict__ lsm_nv,
    const int* __restrict__ lsm_base, float* __restrict__ out1, float* __restrict__ out2)
{
    int row = blockIdx.x*8 + (threadIdx.x >> 5);  // output row within a pass
    int p   = blockIdx.y;
    int lane = threadIdx.x & 31;
    int bb = row >> 9, t = row & 511;
    int nv = lsm_nv[p*Bb + bb];
    float* op = (p ? out2 : out1) + (size_t)row*Nn;
    if (t >= nv){
        const float CNEG = -7.6246189861593985f;   // -log(2048)
        float4 c4 = make_float4(CNEG,CNEG,CNEG,CNEG);
        for (int i=lane;i<Nn/4;i+=32) ((float4*)op)[i] = c4;
        return;
    }
    int srow = lsm_base[p*Bb + bb] + t;
    const float4* ip = (const float4*)(sc + (size_t)srow*Nn);
    float4 v[16];
    float m = -3.4e38f;
    #pragma unroll
    for (int i=0;i<16;i++){
        v[i] = ip[lane + i*32];
        m = fmaxf(m, fmaxf(fmaxf(v[i].x,v[i].y), fmaxf(v[i].z,v[i].w)));
    }
    #pragma unroll
    for (int off=16;off;off>>=1) m = fmaxf(m, __shfl_xor_sync(0xffffffffu, m, off));
    float s = 0.f;
    #pragma unroll
    for (int i=0;i<16;i++)
        s += expf(v[i].x-m)+expf(v[i].y-m)+expf(v[i].z-m)+expf(v[i].w-m);
    #pragma unroll
    for (int off=16;off;off>>=1) s += __shfl_xor_sync(0xffffffffu, s, off);
    float corr = m + logf(s);
    #pragma unroll
    for (int i=0;i<16;i++){
        float4 o = v[i];
        o.x-=corr; o.y-=corr; o.z-=corr; o.w-=corr;
        ((float4*)op)[lane + i*32] = o;
    }
}

// ---------------- host -------------------------------------------------------------
extern "C" void kernel_launch(void* const* d_in, const int* in_sizes, int n_in,
                              void* d_out, int out_size)
{
    (void)in_sizes; (void)n_in; (void)out_size;
    const int*   labels = (const int*)  d_in[0];
    const float* hidden = (const float*)d_in[1];
    const float* ent    = (const float*)d_in[2];
    const float* W1     = (const float*)d_in[3];
    const float* b1     = (const float*)d_in[4];
    const float* W2     = (const float*)d_in[5];
    const float* b2     = (const float*)d_in[6];
    const float* Wm     = (const float*)d_in[7];
    const float* Wd     = (const float*)d_in[8];

    float* out0 = (float*)d_out;
    float* s1o  = out0 + (size_t)BT*3;
    float* s2o  = s1o  + (size_t)BT*Nn;

    __half *hidh,*hidl,*enth,*entl,*w1h,*w1l,*wmh,*wml,*wdh,*wdl;
    __half *poolh,*pooll,*pmh,*pml,*pdh,*pdl;
    float *h, *sc;
    int *pred, *ri0, *ri1, *nv0, *nv1, *b0, *b1a, *lnv, *lbs, *rtot;
    cudaGetSymbolAddress((void**)&hidh, g_hid_h);  cudaGetSymbolAddress((void**)&hidl, g_hid_l);
    cudaGetSymbolAddress((void**)&enth, g_ent_h);  cudaGetSymbolAddress((void**)&entl, g_ent_l);
    cudaGetSymbolAddress((void**)&w1h,  g_W1_h);   cudaGetSymbolAddress((void**)&w1l,  g_W1_l);
    cudaGetSymbolAddress((void**)&wmh,  g_Wm_h);   cudaGetSymbolAddress((void**)&wml,  g_Wm_l);
    cudaGetSymbolAddress((void**)&wdh,  g_Wd_h);   cudaGetSymbolAddress((void**)&wdl,  g_Wd_l);
    cudaGetSymbolAddress((void**)&poolh,g_pool_h); cudaGetSymbolAddress((void**)&pooll,g_pool_l);
    cudaGetSymbolAddress((void**)&pmh,  g_pm_h);   cudaGetSymbolAddress((void**)&pml,  g_pm_l);
    cudaGetSymbolAddress((void**)&pdh,  g_pd_h);   cudaGetSymbolAddress((void**)&pdl,  g_pd_l);
    cudaGetSymbolAddress((void**)&h,    g_h);
    cudaGetSymbolAddress((void**)&sc,   g_sc);
    cudaGetSymbolAddress((void**)&pred, g_pred);
    cudaGetSymbolAddress((void**)&ri0,  g_rowinfo0);
    cudaGetSymbolAddress((void**)&ri1,  g_rowinfo1);
    cudaGetSymbolAddress((void**)&nv0,  g_nvraw0);
    cudaGetSymbolAddress((void**)&nv1,  g_nvraw1);
    cudaGetSymbolAddress((void**)&b0,   g_base0);
    cudaGetSymbolAddress((void**)&b1a,  g_base1);
    cudaGetSymbolAddress((void**)&lnv,  g_lsm_nv);
    cudaGetSymbolAddress((void**)&lbs,  g_lsm_base);
    cudaGetSymbolAddress((void**)&rtot, g_Rtot);

    cudaFuncSetAttribute((const void*)mma_gemm<EP_BIASRELU,false>, cudaFuncAttributeMaxDynamicSharedMemorySize, SMEMSZ);
    cudaFuncSetAttribute((const void*)mma_gemm<EP_PAD,false>,      cudaFuncAttributeMaxDynamicSharedMemorySize, SMEMSZ);
    cudaFuncSetAttribute((const void*)mma_gemm<EP_PAD,true>,       cudaFuncAttributeMaxDynamicSharedMemorySize, SMEMSZ);
    cudaFuncSetAttribute((const void*)mma_gemm<EP_PLAIN,true>,     cudaFuncAttributeMaxDynamicSharedMemorySize, SMEMSZ);

    // launches 1-3: splits needed by gemm1; launch 4 = gemm1 (ncu capture slot)
    split_kernel<<<(BT*Hh+255)/256, 256>>>(hidden, hidh, hidl, BT*Hh);
    split_kernel<<<(Hh*Hh+255)/256, 256>>>(W1, w1h, w1l, Hh*Hh);
    split_kernel<<<(Nn*Hh+255)/256, 256>>>(ent, enth, entl, Nn*Hh);

    // 1) h = relu(x @ W1^T + b1)
    mma_gemm<EP_BIASRELU,false><<<dim3(Hh/128, BT/128), NTHR, SMEMSZ>>>(
        hidh, hidl, w1h, w1l, h, nullptr, nullptr, Hh, Hh, Hh, Hh, Hh, Hh, b1, nullptr);

    split_kernel<<<(Pp*Hh+255)/256, 256>>>(Wm, wmh, wml, Pp*Hh);
    split_kernel<<<(Pp*Hh+255)/256, 256>>>(Wd, wdh, wdl, Pp*Hh);

    // 2) bio logits -> out0 + predicted labels
    logits_kernel<<<BT/8, 256>>>(h, W2, b2, out0, pred);

    // 3) pd = ent @ Wd^T -> half hi/lo planes, K-padded to KP
    mma_gemm<EP_PAD,false><<<dim3(3, Nn/128), NTHR, SMEMSZ>>>(
        enth, entl, wdh, wdl, nullptr, pdh, pdl, Hh, Hh, KP, Hh, Pp, Pp, nullptr, nullptr);

    // 4) both pooling passes, globally compacted
    scan_kernel<<<Bb, 32>>>(labels, ri0, nv0);
    scan_kernel<<<Bb, 32>>>(pred,   ri1, nv1);
    combine2_kernel<<<1, 1>>>(nv0, nv1, b0, b1a, lnv, lbs, rtot);
    pool_kernel<<<dim3(Bb, 16), 256>>>(labels, hidden, ri0, nv0, b0,  poolh, pooll);
    pool_kernel<<<dim3(Bb, 16), 256>>>(pred,   hidden, ri1, nv1, b1a, poolh, pooll);
    padzero_kernel<<<128, 256>>>(rtot, poolh, pooll);

    // 5) pm = pooled @ Wm^T over compacted rows (single launch, both passes)
    mma_gemm<EP_PAD,true><<<dim3(3, BT2/128), NTHR, SMEMSZ>>>(
        poolh, pooll, wmh, wml, nullptr, pmh, pml, Hh, Hh, KP, Hh, Pp, Pp, nullptr, rtot);

    // 6) sc = pm @ pd^T over compacted rows (single launch)
    mma_gemm<EP_PLAIN,true><<<dim3(Nn/128, BT2/128), NTHR, SMEMSZ>>>(
        pmh, pml, pdh, pdl, sc, nullptr, nullptr, KP, KP, Nn, KP, Nn, Nn, nullptr, rtot);

    // 7) log-softmax scatter to both outputs
    lsm_kernel<<<dim3(BT/8, 2), 256>>>(sc, lnv, lbs, s1o, s2o);
}

// round 11
// speedup vs baseline: 3.3798x; 1.1398x over previous
#include <cuda_runtime.h>
#include <cuda_fp16.h>
#include <math.h>
#include <stdint.h>

#define Bb 64
#define Tt 512
#define Hh 768
#define Nn 2048
#define Pp 300
#define KP 320
#define BT (Bb*Tt)
#define BT2 (2*BT)

// ---------------- scratch (device globals; no allocation allowed) ----------
__device__ __half g_hid_h[(size_t)BT*Hh],   g_hid_l[(size_t)BT*Hh];
__device__ __half g_ent_h[(size_t)Nn*Hh],   g_ent_l[(size_t)Nn*Hh];
__device__ __half g_W1_h[Hh*Hh],            g_W1_l[Hh*Hh];
__device__ __half g_Wm_h[Pp*Hh],            g_Wm_l[Pp*Hh];
__device__ __half g_Wd_h[Pp*Hh],            g_Wd_l[Pp*Hh];
__device__ __half g_pool_h[(size_t)BT2*Hh], g_pool_l[(size_t)BT2*Hh];
__device__ __half g_pm_h[(size_t)BT2*KP],   g_pm_l[(size_t)BT2*KP];
__device__ __half g_pd_h[(size_t)Nn*KP],    g_pd_l[(size_t)Nn*KP];
__device__ float  g_h[(size_t)BT*Hh];
__device__ float  g_sc[(size_t)BT2*Nn];
__device__ int    g_pred[BT];
__device__ int    g_rowinfo0[BT], g_rowinfo1[BT];
__device__ int    g_nvraw0[Bb],  g_nvraw1[Bb];
__device__ int    g_base0[Bb],   g_base1[Bb];
__device__ int    g_lsm_nv[2*Bb], g_lsm_base[2*Bb];
__device__ int    g_Rtot[4];                     // [0]=Rpad  [1]=R

// ---------------- helpers ----------------------------------------------------
__device__ __forceinline__ uint32_t smem_u32(const void* p){
    uint32_t a;
    asm("{ .reg .u64 t; cvta.to.shared.u64 t, %1; cvt.u32.u64 %0, t; }" : "=r"(a) : "l"(p));
    return a;
}
__device__ __forceinline__ void cp_async16(uint32_t dst, const void* src, bool ok){
    int sz = ok ? 16 : 0;   // src-size 0 -> zero-fill 16B
    asm volatile("cp.async.cg.shared.global [%0], [%1], 16, %2;" :: "r"(dst), "l"(src), "r"(sz));
}
__device__ __forceinline__ void cp_commit(){ asm volatile("cp.async.commit_group;" ::: "memory"); }
template<int N> __device__ __forceinline__ void cp_wait(){ asm volatile("cp.async.wait_group %0;" :: "n"(N) : "memory"); }

__device__ __forceinline__ void ldsm4(uint32_t* r, uint32_t addr){
    asm volatile("ldmatrix.sync.aligned.m8n8.x4.shared.b16 {%0,%1,%2,%3}, [%4];"
        : "=r"(r[0]), "=r"(r[1]), "=r"(r[2]), "=r"(r[3]) : "r"(addr));
}
__device__ __forceinline__ void mma16(float* d, const uint32_t* a, uint32_t b0, uint32_t b1){
    asm volatile(
        "mma.sync.aligned.m16n8k16.row.col.f32.f16.f16.f32 "
        "{%0,%1,%2,%3}, {%4,%5,%6,%7}, {%8,%9}, {%0,%1,%2,%3};"
        : "+f"(d[0]), "+f"(d[1]), "+f"(d[2]), "+f"(d[3])
        : "r"(a[0]), "r"(a[1]), "r"(a[2]), "r"(a[3]), "r"(b0), "r"(b1));
}
__device__ __forceinline__ void split16(float v, __half& h, __half& l){
    h = __float2half_rn(v);
    l = __float2half_rn(v - __half2float(h));
}

// ---------------- fp16 GEMM: C[M,N] = A[M,K] @ B[N,K]^T ----------------------
// CTA tile 128x128, BK=32, 8 warps (2m x 4n), warp tile 64x32, 3-stage cp.async,
// __launch_bounds__(256,2) -> <=128 regs -> 2 CTAs/SM (barriers overlap).
// TERMS=3: hi*hi + hi*lo + lo*hi (full Markidis).  TERMS=2: hi*hi + hi*lo_B
// (A lo plane neither loaded nor multiplied; ~2^-11 cross-term error — only used
// on the smooth pm/score path, never on the argmax path).
enum { EP_BIASRELU = 0, EP_PAD = 1, EP_PLAIN = 2 };
#define ST_ALO 8192
#define ST_B   16384
#define ST_BLO 8192      // relative to ST_B
#define STAGE  32768
#define SMEMSZ (3*STAGE) // 98304 per CTA -> 2 CTAs = 192K < 228K
#define NTHR 256

template<int EPI, bool ROWMASK, int TERMS>
__global__ void __launch_bounds__(NTHR, 2) mma_gemm(
    const __half* __restrict__ Ah, const __half* __restrict__ Al,
    const __half* __restrict__ Bh, const __half* __restrict__ Bl,
    float* __restrict__ C, __half* __restrict__ Ch, __half* __restrict__ Cl,
    int lda, int ldb, int ldc, int K, int Nreal, int NBreal,
    const float* __restrict__ bias, const int* __restrict__ rtot)
{
    extern __shared__ char smem[];
    const int m0 = blockIdx.y * 128, n0 = blockIdx.x * 128;
    const int tid = threadIdx.x;
    if (ROWMASK){
        if (m0 >= rtot[0]) return;     // beyond compacted rows
    }
    const uint32_t sb0 = smem_u32(smem);
    const int warp = tid >> 5, lane = tid & 31;
    const int wm = warp >> 2, wn = warp & 3;     // 2 x 4 warp grid, warp tile 64x32
    const int lr = lane >> 2, lc = lane & 3;

    float acc[4][4][4];
    #pragma unroll
    for (int i=0;i<4;i++)
        #pragma unroll
        for (int j=0;j<4;j++)
            #pragma unroll
            for (int q=0;q<4;q++) acc[i][j][q] = 0.f;

    const int arl = (lane & 7) + ((lane >> 3) & 1) * 8;
    const int acs = lane >> 4;
    const int nrl = (lane & 7) + (lane >> 4) * 8;
    const int bcs = (lane >> 3) & 1;
    uint32_t aoff[4], boff[2];
    #pragma unroll
    for (int mt = 0; mt < 4; mt++){
        int r = wm*64 + mt*16 + arl;
        aoff[mt] = (uint32_t)(r*64) + (uint32_t)((acs ^ (r & 3) ^ ((r >> 2) & 1)) << 4);
    }
    #pragma unroll
    for (int nb = 0; nb < 2; nb++){
        int r = wn*32 + nb*16 + nrl;
        boff[nb] = (uint32_t)ST_B + (uint32_t)(r*64) + (uint32_t)((bcs ^ (r & 3) ^ ((r >> 2) & 1)) << 4);
    }

    auto load_tile = [&](int kt, int s){
        const int k0 = kt * 32;
        const uint32_t sbs = sb0 + (uint32_t)s * STAGE;
        if (TERMS == 3){
            #pragma unroll
            for (int j = 0; j < 8; j++){
                int idx = tid + j*NTHR;                 // 0..2047 16B-chunks
                if (idx < 1024){                        // A planes: Ah, Al
                    int pl  = idx >> 9;
                    int rem = idx & 511;
                    int row = rem >> 2, c = rem & 3;
                    int c2  = c ^ (row & 3) ^ ((row >> 2) & 1);
                    uint32_t so = sbs + (uint32_t)(pl*ST_ALO + row*64 + c2*16);
                    const __half* src = (pl ? Al : Ah) + (size_t)(m0 + row)*lda + k0 + c*8;
                    cp_async16(so, src, true);
                } else {                                // B planes: Bh, Bl
                    int b   = idx - 1024;
                    int pl  = b >> 9;
                    int rem = b & 511;
                    int row = rem >> 2, c = rem & 3;
                    int c2  = c ^ (row & 3) ^ ((row >> 2) & 1);
                    uint32_t so = sbs + (uint32_t)(ST_B + pl*ST_BLO + row*64 + c2*16);
                    bool ok = (n0 + row) < NBreal;
                    const __half* base = pl ? Bl : Bh;
                    const __half* src = ok ? (base + (size_t)(n0 + row)*ldb + k0 + c*8) : base;
                    cp_async16(so, src, ok);
                }
            }
        } else {   // TERMS == 2: planes Ah, Bh, Bl only (1536 chunks)
            #pragma unroll
            for (int j = 0; j < 6; j++){
                int idx = tid + j*NTHR;
                if (idx < 512){                          // Ah
                    int row = idx >> 2, c = idx & 3;
                    int c2  = c ^ (row & 3) ^ ((row >> 2) & 1);
                    uint32_t so = sbs + (uint32_t)(row*64 + c2*16);
                    cp_async16(so, Ah + (size_t)(m0 + row)*lda + k0 + c*8, true);
                } else {                                 // Bh, Bl
                    int b   = idx - 512;
                    int pl  = b >> 9;
                    int rem = b & 511;
                    int row = rem >> 2, c = rem & 3;
                    int c2  = c ^ (row & 3) ^ ((row >> 2) & 1);
                    uint32_t so = sbs + (uint32_t)(ST_B + pl*ST_BLO + row*64 + c2*16);
                    bool ok = (n0 + row) < NBreal;
                    const __half* base = pl ? Bl : Bh;
                    const __half* src = ok ? (base + (size_t)(n0 + row)*ldb + k0 + c*8) : base;
                    cp_async16(so, src, ok);
                }
            }
        }
        cp_commit();
    };

    const int nkt = K >> 5;
    load_tile(0, 0);
    if (nkt > 1) load_tile(1, 1);
    for (int kt = 0; kt < nkt; kt++){
        const int s = kt % 3;
        if (kt + 1 < nkt) cp_wait<1>(); else cp_wait<0>();
        __syncthreads();
        if (kt + 2 < nkt) load_tile(kt + 2, (kt + 2) % 3);
        const uint32_t sbs = sb0 + (uint32_t)s * STAGE;

        #pragma unroll
        for (int ks = 0; ks < 2; ks++){
            const uint32_t kx = (uint32_t)(ks << 5);
            uint32_t bhf[2][4], blf[2][4];
            #pragma unroll
            for (int nb = 0; nb < 2; nb++){
                uint32_t t = (sbs + boff[nb]) ^ kx;
                ldsm4(bhf[nb], t);
                ldsm4(blf[nb], t + ST_BLO);
            }
            #pragma unroll
            for (int mt = 0; mt < 4; mt++){
                uint32_t ahf[4], alf[4];
                uint32_t t = (sbs + aoff[mt]) ^ kx;
                ldsm4(ahf, t);
                if (TERMS == 3) ldsm4(alf, t + ST_ALO);
                #pragma unroll
                for (int nt = 0; nt < 4; nt++){
                    const int nb = nt >> 1, p = (nt & 1) * 2;
                    float* d = acc[mt][nt];
                    mma16(d, ahf, bhf[nb][p], bhf[nb][p+1]);       // hi*hi
                    mma16(d, ahf, blf[nb][p], blf[nb][p+1]);       // hi*lo
                    if (TERMS == 3)
                        mma16(d, alf, bhf[nb][p], bhf[nb][p+1]);   // lo*hi
                }
            }
        }
    }

    // epilogue: registers -> gmem
    #pragma unroll
    for (int mt = 0; mt < 4; mt++){
        #pragma unroll
        for (int nt = 0; nt < 4; nt++){
            int row = m0 + wm*64 + mt*16 + lr;
            int col = n0 + wn*32 + nt*8 + lc*2;
            float* a = acc[mt][nt];
            if (EPI == EP_BIASRELU){
                float b0 = bias[col], b1 = bias[col+1];
                float v0 = a[0] + b0, v1 = a[1] + b1, v2 = a[2] + b0, v3 = a[3] + b1;
                v0 = v0 > 0.f ? v0 : 0.f; v1 = v1 > 0.f ? v1 : 0.f;
                v2 = v2 > 0.f ? v2 : 0.f; v3 = v3 > 0.f ? v3 : 0.f;
                *(float2*)&C[(size_t)row*ldc + col]     = make_float2(v0, v1);
                *(float2*)&C[(size_t)(row+8)*ldc + col] = make_float2(v2, v3);
            } else if (EPI == EP_PLAIN){
                *(float2*)&C[(size_t)row*ldc + col]     = make_float2(a[0], a[1]);
                *(float2*)&C[(size_t)(row+8)*ldc + col] = make_float2(a[2], a[3]);
            } else { // EP_PAD: half hi/lo planes, zero pad columns
                if (col + 2 <= ldc){
                    float v0 = (col   < Nreal) ? a[0] : 0.f;
                    float v1 = (col+1 < Nreal) ? a[1] : 0.f;
                    float v2 = (col   < Nreal) ? a[2] : 0.f;
                    float v3 = (col+1 < Nreal) ? a[3] : 0.f;
                    __half h0,l0,h1,l1,h2,l2,h3,l3;
                    split16(v0,h0,l0); split16(v1,h1,l1);
                    split16(v2,h2,l2); split16(v3,h3,l3);
                    *(__half2*)&Ch[(size_t)row*ldc + col]     = __halves2half2(h0, h1);
                    *(__half2*)&Cl[(size_t)row*ldc + col]     = __halves2half2(l0, l1);
                    *(__half2*)&Ch[(size_t)(row+8)*ldc + col] = __halves2half2(h2, h3);
                    *(__half2*)&Cl[(size_t)(row+8)*ldc + col] = __halves2half2(l2, l3);
                }
            }
        }
    }
}

// ---------------- fp32 -> fp16 hi/lo split ------------------------------------
__global__ void __launch_bounds__(256) split_kernel(
    const float* __restrict__ x, __half* __restrict__ h, __half* __restrict__ l, int n)
{
    int i = blockIdx.x*256 + threadIdx.x;
    if (i < n){ __half hv, lv; split16(x[i], hv, lv); h[i] = hv; l[i] = lv; }
}

// ---------------- 3-class head --------------------------------------------------
__global__ void __launch_bounds__(256) logits_kernel(
    const float* __restrict__ h, const float* __restrict__ W2,
    const float* __restrict__ b2, float* __restrict__ out0, int* __restrict__ pred)
{
    __shared__ float w2s[3*Hh];
    int tid = threadIdx.x;
    for (int i = tid; i < 3*Hh; i += 256) w2s[i] = W2[i];
    __syncthreads();
    int warp = tid >> 5, lane = tid & 31;
    int row = blockIdx.x*8 + warp;
    const float* hp = h + (size_t)row*Hh;
    float s0=0.f, s1=0.f, s2=0.f;
    for (int i = lane; i < Hh; i += 32){
        float hv = hp[i];
        s0 += hv*w2s[i]; s1 += hv*w2s[Hh+i]; s2 += hv*w2s[2*Hh+i];
    }
    #pragma unroll
    for (int off=16; off; off>>=1){
        s0 += __shfl_xor_sync(0xffffffffu, s0, off);
        s1 += __shfl_xor_sync(0xffffffffu, s1, off);
        s2 += __shfl_xor_sync(0xffffffffu, s2, off);
    }
    if (lane == 0){
        s0 += b2[0]; s1 += b2[1]; s2 += b2[2];
        float m = fmaxf(s0, fmaxf(s1, s2));
        float lse = m + logf(expf(s0-m)+expf(s1-m)+expf(s2-m));
        size_t o = (size_t)row*3;
        out0[o+0] = s0 - lse; out0[o+1] = s1 - lse; out0[o+2] = s2 - lse;
        int idx = 0; float best = s0;
        if (s1 > best){ best = s1; idx = 1; }
        if (s2 > best){ idx = 2; }
        pred[row] = idx;
    }
}

// ---------------- BIO segment scan (warp-parallel, ballot-based) ----------------
__global__ void scan_kernel(const int* __restrict__ labels,
                            int* __restrict__ rowinfo, int* __restrict__ nvraw)
{
    __shared__ int pos[513];
    int b = blockIdx.x, lane = threadIdx.x;
    const int* lab = labels + b*Tt;
    int base = 0;
    int first1 = Tt;
    int any2 = 0;
    #pragma unroll 1
    for (int c = 0; c < Tt/32; c++){
        int l = lab[c*32 + lane];
        unsigned m1 = __ballot_sync(0xffffffffu, l == 1);
        unsigned m2 = __ballot_sync(0xffffffffu, l == 2);
        if (l == 1) pos[base + __popc(m1 & ((1u<<lane)-1))] = c*32 + lane;
        if (first1 == Tt){
            if (m1){
                int fl = __ffs(m1) - 1;
                first1 = c*32 + fl;
                any2 |= (m2 & ((1u<<fl)-1)) != 0;
            } else any2 |= (m2 != 0);
        }
        base += __popc(m1);
    }
    int m = base;
    int lead = any2;
    __syncwarp();
    if (lane == 0){
        pos[m] = Tt;
        if (lead) rowinfo[b*Tt] = (0<<16) | (m ? pos[0] : Tt);
        nvraw[b] = lead + m;
    }
    __syncwarp();
    for (int j = lane; j < m; j += 32){
        int s = pos[j], e = pos[j+1];
        rowinfo[b*Tt + lead + j] = (s<<16) | e;
    }
}

// ---------------- global compaction bookkeeping ---------------------------------
__global__ void combine2_kernel(const int* __restrict__ nvraw0, const int* __restrict__ nvraw1,
                                int* __restrict__ base0, int* __restrict__ base1,
                                int* __restrict__ lsm_nv, int* __restrict__ lsm_base,
                                int* __restrict__ rtot)
{
    if (threadIdx.x || blockIdx.x) return;
    int off = 0;
    int cnt = 0;
    for (int b=0;b<Bb;b++){
        int nv = nvraw0[b];
        if (nv > 0){ base0[b] = off; lsm_base[cnt] = off; lsm_nv[cnt] = nv; cnt++; off += nv; }
        else base0[b] = -1;
    }
    for (int k=cnt;k<Bb;k++) lsm_nv[k] = 0;
    cnt = 0;
    for (int b=0;b<Bb;b++){
        int nv = nvraw1[b];
        if (nv > 0){ base1[b] = off; lsm_base[Bb+cnt] = off; lsm_nv[Bb+cnt] = nv; cnt++; off += nv; }
        else base1[b] = -1;
    }
    for (int k=cnt;k<Bb;k++) lsm_nv[Bb+k] = 0;
    rtot[1] = off;
    rtot[0] = (off + 127) & ~127;   // Rpad (128-row tiles)
}

// ---------------- zero pooled pad rows [R, Rpad) --------------------------------
__global__ void __launch_bounds__(256) padzero_kernel(
    const int* __restrict__ rtot, __half* __restrict__ ph, __half* __restrict__ pl)
{
    int row = rtot[1] + blockIdx.x;
    if (row >= rtot[0]) return;
    size_t off = (size_t)row*Hh;
    __half z = __float2half(0.f);
    for (int i = threadIdx.x; i < Hh; i += 256){ ph[off+i] = z; pl[off+i] = z; }
}

// ---------------- segment means -> globally compacted pooled rows ---------------
__global__ void __launch_bounds__(256) pool_kernel(
    const int* __restrict__ labels, const float* __restrict__ hidden,
    const int* __restrict__ rowinfo, const int* __restrict__ nvraw,
    const int* __restrict__ basearr, __half* __restrict__ ph, __half* __restrict__ pl)
{
    int b = blockIdx.x;
    int d = basearr[b];
    if (d < 0) return;
    int nv = nvraw[b];
    __shared__ int labs[Tt];
    int tid = threadIdx.x;
    for (int i=tid;i<Tt;i+=256) labs[i] = labels[b*Tt+i];
    __syncthreads();
    int r0 = blockIdx.y * 32;
    int r1 = min(r0+32, nv);
    for (int r=r0; r<r1; r++){
        int info = rowinfo[b*Tt + r];
        int s = info >> 16, e = info & 0xffff;
        float a0=0.f,a1=0.f,a2=0.f;
        int cnt = 0;
        for (int t=s;t<e;t++){
            if (labs[t] != 0){
                cnt++;
                const float* hp = hidden + ((size_t)(b*Tt)+t)*Hh;
                a0 += hp[tid]; a1 += hp[tid+256]; a2 += hp[tid+512];
            }
        }
        float inv = 1.0f / (float)cnt;
        size_t off = ((size_t)(d + r))*Hh;
        __half hv, lv;
        split16(a0*inv, hv, lv); ph[off+tid]     = hv; pl[off+tid]     = lv;
        split16(a1*inv, hv, lv); ph[off+tid+256] = hv; pl[off+tid+256] = lv;
        split16(a2*inv, hv, lv); ph[off+tid+512] = hv; pl[off+tid+512] = lv;
    }
}

// ---------------- row log-softmax over compacted sc ------------------------------
__global__ void __launch_bounds__(256) lsm_kernel(
    const float* __restrict__ sc, const int* __restrict__ lsm_nv,
    const int* __restrict__ lsm_base, float* __restrict__ out1, float* __restrict__ out2)
{
    int row = blockIdx.x*8 + (threadIdx.x >> 5);  // output row within a pass
    int p   = blockIdx.y;
    int lane = threadIdx.x & 31;
    int bb = row >> 9, t = row & 511;
    int nv = lsm_nv[p*Bb + bb];
    float* op = (p ? out2 : out1) + (size_t)row*Nn;
    if (t >= nv){
        const float CNEG = -7.6246189861593985f;   // -log(2048)
        float4 c4 = make_float4(CNEG,CNEG,CNEG,CNEG);
        for (int i=lane;i<Nn/4;i+=32) ((float4*)op)[i] = c4;
        return;
    }
    int srow = lsm_base[p*Bb + bb] + t;
    const float4* ip = (const float4*)(sc + (size_t)srow*Nn);
    float4 v[16];
    float m = -3.4e38f;
    #pragma unroll
    for (int i=0;i<16;i++){
        v[i] = ip[lane + i*32];
        m = fmaxf(m, fmaxf(fmaxf(v[i].x,v[i].y), fmaxf(v[i].z,v[i].w)));
    }
    #pragma unroll
    for (int off=16;off;off>>=1) m = fmaxf(m, __shfl_xor_sync(0xffffffffu, m, off));
    float s = 0.f;
    #pragma unroll
    for (int i=0;i<16;i++)
        s += expf(v[i].x-m)+expf(v[i].y-m)+expf(v[i].z-m)+expf(v[i].w-m);
    #pragma unroll
    for (int off=16;off;off>>=1) s += __shfl_xor_sync(0xffffffffu, s, off);
    float corr = m + logf(s);
    #pragma unroll
    for (int i=0;i<16;i++){
        float4 o = v[i];
        o.x-=corr; o.y-=corr; o.z-=corr; o.w-=corr;
        ((float4*)op)[lane + i*32] = o;
    }
}

// ---------------- host -------------------------------------------------------------
extern "C" void kernel_launch(void* const* d_in, const int* in_sizes, int n_in,
                              void* d_out, int out_size)
{
    (void)in_sizes; (void)n_in; (void)out_size;
    const int*   labels = (const int*)  d_in[0];
    const float* hidden = (const float*)d_in[1];
    const float* ent    = (const float*)d_in[2];
    const float* W1     = (const float*)d_in[3];
    const float* b1     = (const float*)d_in[4];
    const float* W2     = (const float*)d_in[5];
    const float* b2     = (const float*)d_in[6];
    const float* Wm     = (const float*)d_in[7];
    const float* Wd     = (const float*)d_in[8];

    float* out0 = (float*)d_out;
    float* s1o  = out0 + (size_t)BT*3;
    float* s2o  = s1o  + (size_t)BT*Nn;

    __half *hidh,*hidl,*enth,*entl,*w1h,*w1l,*wmh,*wml,*wdh,*wdl;
    __half *poolh,*pooll,*pmh,*pml,*pdh,*pdl;
    float *h, *sc;
    int *pred, *ri0, *ri1, *nv0, *nv1, *b0, *b1a, *lnv, *lbs, *rtot;
    cudaGetSymbolAddress((void**)&hidh, g_hid_h);  cudaGetSymbolAddress((void**)&hidl, g_hid_l);
    cudaGetSymbolAddress((void**)&enth, g_ent_h);  cudaGetSymbolAddress((void**)&entl, g_ent_l);
    cudaGetSymbolAddress((void**)&w1h,  g_W1_h);   cudaGetSymbolAddress((void**)&w1l,  g_W1_l);
    cudaGetSymbolAddress((void**)&wmh,  g_Wm_h);   cudaGetSymbolAddress((void**)&wml,  g_Wm_l);
    cudaGetSymbolAddress((void**)&wdh,  g_Wd_h);   cudaGetSymbolAddress((void**)&wdl,  g_Wd_l);
    cudaGetSymbolAddress((void**)&poolh,g_pool_h); cudaGetSymbolAddress((void**)&pooll,g_pool_l);
    cudaGetSymbolAddress((void**)&pmh,  g_pm_h);   cudaGetSymbolAddress((void**)&pml,  g_pm_l);
    cudaGetSymbolAddress((void**)&pdh,  g_pd_h);   cudaGetSymbolAddress((void**)&pdl,  g_pd_l);
    cudaGetSymbolAddress((void**)&h,    g_h);
    cudaGetSymbolAddress((void**)&sc,   g_sc);
    cudaGetSymbolAddress((void**)&pred, g_pred);
    cudaGetSymbolAddress((void**)&ri0,  g_rowinfo0);
    cudaGetSymbolAddress((void**)&ri1,  g_rowinfo1);
    cudaGetSymbolAddress((void**)&nv0,  g_nvraw0);
    cudaGetSymbolAddress((void**)&nv1,  g_nvraw1);
    cudaGetSymbolAddress((void**)&b0,   g_base0);
    cudaGetSymbolAddress((void**)&b1a,  g_base1);
    cudaGetSymbolAddress((void**)&lnv,  g_lsm_nv);
    cudaGetSymbolAddress((void**)&lbs,  g_lsm_base);
    cudaGetSymbolAddress((void**)&rtot, g_Rtot);

    cudaFuncSetAttribute((const void*)mma_gemm<EP_BIASRELU,false,3>, cudaFuncAttributeMaxDynamicSharedMemorySize, SMEMSZ);
    cudaFuncSetAttribute((const void*)mma_gemm<EP_PAD,false,3>,      cudaFuncAttributeMaxDynamicSharedMemorySize, SMEMSZ);
    cudaFuncSetAttribute((const void*)mma_gemm<EP_PAD,true,2>,       cudaFuncAttributeMaxDynamicSharedMemorySize, SMEMSZ);
    cudaFuncSetAttribute((const void*)mma_gemm<EP_PLAIN,true,2>,     cudaFuncAttributeMaxDynamicSharedMemorySize, SMEMSZ);

    // launches 1-3: splits needed by gemm1; launch 4 = gemm1 (ncu capture slot)
    split_kernel<<<(BT*Hh+255)/256, 256>>>(hidden, hidh, hidl, BT*Hh);
    split_kernel<<<(Hh*Hh+255)/256, 256>>>(W1, w1h, w1l, Hh*Hh);
    split_kernel<<<(Nn*Hh+255)/256, 256>>>(ent, enth, entl, Nn*Hh);

    // 1) h = relu(x @ W1^T + b1) — full 3-term (argmax-sensitive path)
    mma_gemm<EP_BIASRELU,false,3><<<dim3(Hh/128, BT/128), NTHR, SMEMSZ>>>(
        hidh, hidl, w1h, w1l, h, nullptr, nullptr, Hh, Hh, Hh, Hh, Hh, Hh, b1, nullptr);

    split_kernel<<<(Pp*Hh+255)/256, 256>>>(Wm, wmh, wml, Pp*Hh);
    split_kernel<<<(Pp*Hh+255)/256, 256>>>(Wd, wdh, wdl, Pp*Hh);

    // 2) bio logits -> out0 + predicted labels (fp32)
    logits_kernel<<<BT/8, 256>>>(h, W2, b2, out0, pred);

    // 3) pd = ent @ Wd^T -> half hi/lo planes, K-padded to KP (3-term, cheap)
    mma_gemm<EP_PAD,false,3><<<dim3(3, Nn/128), NTHR, SMEMSZ>>>(
        enth, entl, wdh, wdl, nullptr, pdh, pdl, Hh, Hh, KP, Hh, Pp, Pp, nullptr, nullptr);

    // 4) both pooling passes, globally compacted
    scan_kernel<<<Bb, 32>>>(labels, ri0, nv0);
    scan_kernel<<<Bb, 32>>>(pred,   ri1, nv1);
    combine2_kernel<<<1, 1>>>(nv0, nv1, b0, b1a, lnv, lbs, rtot);
    pool_kernel<<<dim3(Bb, 16), 256>>>(labels, hidden, ri0, nv0, b0,  poolh, pooll);
    pool_kernel<<<dim3(Bb, 16), 256>>>(pred,   hidden, ri1, nv1, b1a, poolh, pooll);
    padzero_kernel<<<128, 256>>>(rtot, poolh, pooll);

    // 5) pm = pooled @ Wm^T over compacted rows — 2-term (smooth path)
    mma_gemm<EP_PAD,true,2><<<dim3(3, BT2/128), NTHR, SMEMSZ>>>(
        poolh, pooll, wmh, wml, nullptr, pmh, pml, Hh, Hh, KP, Hh, Pp, Pp, nullptr, rtot);

    // 6) sc = pm @ pd^T over compacted rows — 2-term (smooth path)
    mma_gemm<EP_PLAIN,true,2><<<dim3(Nn/128, BT2/128), NTHR, SMEMSZ>>>(
        pmh, pml, pdh, pdl, sc, nullptr, nullptr, KP, KP, Nn, KP, Nn, Nn, nullptr, rtot);

    // 7) log-softmax scatter to both outputs
    lsm_kernel<<<dim3(BT/8, 2), 256>>>(sc, lnv, lbs, s1o, s2o);
}

// round 12
// speedup vs baseline: 3.5258x; 1.0432x over previous
#include <cuda_runtime.h>
#include <cuda_fp16.h>
#include <math.h>
#include <stdint.h>

#define Bb 64
#define Tt 512
#define Hh 768
#define Nn 2048
#define Pp 300
#define KP 320
#define BT (Bb*Tt)
#define BT2 (2*BT)

// ---------------- scratch (device globals; no allocation allowed) ----------
__device__ __half g_hid_h[(size_t)BT*Hh],   g_hid_l[(size_t)BT*Hh];
__device__ __half g_ent_h[(size_t)Nn*Hh],   g_ent_l[(size_t)Nn*Hh];
__device__ __half g_W1_h[Hh*Hh],            g_W1_l[Hh*Hh];
__device__ __half g_Wm_h[Pp*Hh],            g_Wm_l[Pp*Hh];
__device__ __half g_Wd_h[Pp*Hh],            g_Wd_l[Pp*Hh];
__device__ __half g_pool_h[(size_t)BT2*Hh], g_pool_l[(size_t)BT2*Hh];
__device__ __half g_pm_h[(size_t)BT2*KP],   g_pm_l[(size_t)BT2*KP];
__device__ __half g_pd_h[(size_t)Nn*KP],    g_pd_l[(size_t)Nn*KP];
__device__ float  g_part[(size_t)6*BT*3];   // logits partials per col-tile
__device__ float  g_sc[(size_t)BT2*Nn];
__device__ int    g_pred[BT];
__device__ int    g_rowinfo0[BT], g_rowinfo1[BT];
__device__ int    g_nvraw0[Bb],  g_nvraw1[Bb];
__device__ int    g_base0[Bb],   g_base1[Bb];
__device__ int    g_lsm_nv[2*Bb], g_lsm_base[2*Bb];
__device__ int    g_Rtot[4];                     // [0]=Rpad  [1]=R

// ---------------- helpers ----------------------------------------------------
__device__ __forceinline__ uint32_t smem_u32(const void* p){
    uint32_t a;
    asm("{ .reg .u64 t; cvta.to.shared.u64 t, %1; cvt.u32.u64 %0, t; }" : "=r"(a) : "l"(p));
    return a;
}
__device__ __forceinline__ void cp_async16(uint32_t dst, const void* src, bool ok){
    int sz = ok ? 16 : 0;   // src-size 0 -> zero-fill 16B
    asm volatile("cp.async.cg.shared.global [%0], [%1], 16, %2;" :: "r"(dst), "l"(src), "r"(sz));
}
__device__ __forceinline__ void cp_commit(){ asm volatile("cp.async.commit_group;" ::: "memory"); }
template<int N> __device__ __forceinline__ void cp_wait(){ asm volatile("cp.async.wait_group %0;" :: "n"(N) : "memory"); }

__device__ __forceinline__ void ldsm4(uint32_t* r, uint32_t addr){
    asm volatile("ldmatrix.sync.aligned.m8n8.x4.shared.b16 {%0,%1,%2,%3}, [%4];"
        : "=r"(r[0]), "=r"(r[1]), "=r"(r[2]), "=r"(r[3]) : "r"(addr));
}
__device__ __forceinline__ void mma16(float* d, const uint32_t* a, uint32_t b0, uint32_t b1){
    asm volatile(
        "mma.sync.aligned.m16n8k16.row.col.f32.f16.f16.f32 "
        "{%0,%1,%2,%3}, {%4,%5,%6,%7}, {%8,%9}, {%0,%1,%2,%3};"
        : "+f"(d[0]), "+f"(d[1]), "+f"(d[2]), "+f"(d[3])
        : "r"(a[0]), "r"(a[1]), "r"(a[2]), "r"(a[3]), "r"(b0), "r"(b1));
}
__device__ __forceinline__ void split16(float v, __half& h, __half& l){
    h = __float2half_rn(v);
    l = __float2half_rn(v - __half2float(h));
}

// ---------------- fp16 GEMM: C[M,N] = A[M,K] @ B[N,K]^T ----------------------
// CTA tile 128x128, BK=32, 8 warps (2m x 4n), warp tile 64x32, 3-stage cp.async,
// __launch_bounds__(256,2) -> <=128 regs -> 2 CTAs/SM.
// EP_LOGITS: fused relu(h)+W2 projection -> per-col-tile partials (h never stored).
enum { EP_LOGITS = 0, EP_PAD = 1, EP_PLAIN = 2 };
#define ST_ALO 8192
#define ST_B   16384
#define ST_BLO 8192      // relative to ST_B
#define STAGE  32768
#define SMEM_GEMM (3*STAGE)              // 98304
#define SMEM_LOG  (3*STAGE + 6144 + 1536) // + psum[4][128][3] + w2s[3][128]
#define NTHR 256

template<int EPI, bool ROWMASK, int TERMS>
__global__ void __launch_bounds__(NTHR, 2) mma_gemm(
    const __half* __restrict__ Ah, const __half* __restrict__ Al,
    const __half* __restrict__ Bh, const __half* __restrict__ Bl,
    float* __restrict__ C, __half* __restrict__ Ch, __half* __restrict__ Cl,
    int lda, int ldb, int ldc, int K, int Nreal, int NBreal,
    const float* __restrict__ bias, const int* __restrict__ rtot,
    const float* __restrict__ w2)
{
    extern __shared__ char smem[];
    const int m0 = blockIdx.y * 128, n0 = blockIdx.x * 128;
    const int tid = threadIdx.x;
    if (ROWMASK){
        if (m0 >= rtot[0]) return;     // beyond compacted rows
    }
    const uint32_t sb0 = smem_u32(smem);
    const int warp = tid >> 5, lane = tid & 31;
    const int wm = warp >> 2, wn = warp & 3;     // 2 x 4 warp grid, warp tile 64x32
    const int lr = lane >> 2, lc = lane & 3;

    float* psum = (float*)(smem + 3*STAGE);          // [4][128][3]
    float* w2s  = (float*)(smem + 3*STAGE + 6144);   // [3][128]
    if (EPI == EP_LOGITS && tid < 128){
        #pragma unroll
        for (int c = 0; c < 3; c++) w2s[c*128 + tid] = w2[c*Hh + n0 + tid];
    }

    float acc[4][4][4];
    #pragma unroll
    for (int i=0;i<4;i++)
        #pragma unroll
        for (int j=0;j<4;j++)
            #pragma unroll
            for (int q=0;q<4;q++) acc[i][j][q] = 0.f;

    const int arl = (lane & 7) + ((lane >> 3) & 1) * 8;
    const int acs = lane >> 4;
    const int nrl = (lane & 7) + (lane >> 4) * 8;
    const int bcs = (lane >> 3) & 1;
    uint32_t aoff[4], boff[2];
    #pragma unroll
    for (int mt = 0; mt < 4; mt++){
        int r = wm*64 + mt*16 + arl;
        aoff[mt] = (uint32_t)(r*64) + (uint32_t)((acs ^ (r & 3) ^ ((r >> 2) & 1)) << 4);
    }
    #pragma unroll
    for (int nb = 0; nb < 2; nb++){
        int r = wn*32 + nb*16 + nrl;
        boff[nb] = (uint32_t)ST_B + (uint32_t)(r*64) + (uint32_t)((bcs ^ (r & 3) ^ ((r >> 2) & 1)) << 4);
    }

    auto load_tile = [&](int kt, int s){
        const int k0 = kt * 32;
        const uint32_t sbs = sb0 + (uint32_t)s * STAGE;
        if (TERMS == 3){
            #pragma unroll
            for (int j = 0; j < 8; j++){
                int idx = tid + j*NTHR;                 // 0..2047 16B-chunks
                if (idx < 1024){                        // A planes: Ah, Al
                    int pl  = idx >> 9;
                    int rem = idx & 511;
                    int row = rem >> 2, c = rem & 3;
                    int c2  = c ^ (row & 3) ^ ((row >> 2) & 1);
                    uint32_t so = sbs + (uint32_t)(pl*ST_ALO + row*64 + c2*16);
                    const __half* src = (pl ? Al : Ah) + (size_t)(m0 + row)*lda + k0 + c*8;
                    cp_async16(so, src, true);
                } else {                                // B planes: Bh, Bl
                    int b   = idx - 1024;
                    int pl  = b >> 9;
                    int rem = b & 511;
                    int row = rem >> 2, c = rem & 3;
                    int c2  = c ^ (row & 3) ^ ((row >> 2) & 1);
                    uint32_t so = sbs + (uint32_t)(ST_B + pl*ST_BLO + row*64 + c2*16);
                    bool ok = (n0 + row) < NBreal;
                    const __half* base = pl ? Bl : Bh;
                    const __half* src = ok ? (base + (size_t)(n0 + row)*ldb + k0 + c*8) : base;
                    cp_async16(so, src, ok);
                }
            }
        } else {   // TERMS == 2: planes Ah, Bh, Bl only
            #pragma unroll
            for (int j = 0; j < 6; j++){
                int idx = tid + j*NTHR;
                if (idx < 512){                          // Ah
                    int row = idx >> 2, c = idx & 3;
                    int c2  = c ^ (row & 3) ^ ((row >> 2) & 1);
                    uint32_t so = sbs + (uint32_t)(row*64 + c2*16);
                    cp_async16(so, Ah + (size_t)(m0 + row)*lda + k0 + c*8, true);
                } else {                                 // Bh, Bl
                    int b   = idx - 512;
                    int pl  = b >> 9;
                    int rem = b & 511;
                    int row = rem >> 2, c = rem & 3;
                    int c2  = c ^ (row & 3) ^ ((row >> 2) & 1);
                    uint32_t so = sbs + (uint32_t)(ST_B + pl*ST_BLO + row*64 + c2*16);
                    bool ok = (n0 + row) < NBreal;
                    const __half* base = pl ? Bl : Bh;
                    const __half* src = ok ? (base + (size_t)(n0 + row)*ldb + k0 + c*8) : base;
                    cp_async16(so, src, ok);
                }
            }
        }
        cp_commit();
    };

    const int nkt = K >> 5;
    load_tile(0, 0);
    if (nkt > 1) load_tile(1, 1);
    for (int kt = 0; kt < nkt; kt++){
        const int s = kt % 3;
        if (kt + 1 < nkt) cp_wait<1>(); else cp_wait<0>();
        __syncthreads();
        if (kt + 2 < nkt) load_tile(kt + 2, (kt + 2) % 3);
        const uint32_t sbs = sb0 + (uint32_t)s * STAGE;

        #pragma unroll
        for (int ks = 0; ks < 2; ks++){
            const uint32_t kx = (uint32_t)(ks << 5);
            uint32_t bhf[2][4], blf[2][4];
            #pragma unroll
            for (int nb = 0; nb < 2; nb++){
                uint32_t t = (sbs + boff[nb]) ^ kx;
                ldsm4(bhf[nb], t);
                ldsm4(blf[nb], t + ST_BLO);
            }
            #pragma unroll
            for (int mt = 0; mt < 4; mt++){
                uint32_t ahf[4], alf[4];
                uint32_t t = (sbs + aoff[mt]) ^ kx;
                ldsm4(ahf, t);
                if (TERMS == 3) ldsm4(alf, t + ST_ALO);
                #pragma unroll
                for (int nt = 0; nt < 4; nt++){
                    const int nb = nt >> 1, p = (nt & 1) * 2;
                    float* d = acc[mt][nt];
                    mma16(d, ahf, bhf[nb][p], bhf[nb][p+1]);       // hi*hi
                    mma16(d, ahf, blf[nb][p], blf[nb][p+1]);       // hi*lo
                    if (TERMS == 3)
                        mma16(d, alf, bhf[nb][p], bhf[nb][p+1]);   // lo*hi
                }
            }
        }
    }

    if (EPI == EP_LOGITS){
        // fused: v = relu(acc + b1); partial[c] = sum_col v * W2[c][col]
        float w2v[4][2][3];
        float bv[4][2];
        #pragma unroll
        for (int nt = 0; nt < 4; nt++){
            int colL = wn*32 + nt*8 + lc*2;
            #pragma unroll
            for (int j = 0; j < 2; j++){
                bv[nt][j] = bias[n0 + colL + j];
                #pragma unroll
                for (int c = 0; c < 3; c++) w2v[nt][j][c] = w2s[c*128 + colL + j];
            }
        }
        #pragma unroll
        for (int mt = 0; mt < 4; mt++){
            float pA[3] = {0.f,0.f,0.f}, pB[3] = {0.f,0.f,0.f};
            #pragma unroll
            for (int nt = 0; nt < 4; nt++){
                float* a = acc[mt][nt];
                float v0 = a[0] + bv[nt][0]; v0 = v0 > 0.f ? v0 : 0.f;
                float v1 = a[1] + bv[nt][1]; v1 = v1 > 0.f ? v1 : 0.f;
                float v2 = a[2] + bv[nt][0]; v2 = v2 > 0.f ? v2 : 0.f;
                float v3 = a[3] + bv[nt][1]; v3 = v3 > 0.f ? v3 : 0.f;
                #pragma unroll
                for (int c = 0; c < 3; c++){
                    pA[c] += v0*w2v[nt][0][c] + v1*w2v[nt][1][c];
                    pB[c] += v2*w2v[nt][0][c] + v3*w2v[nt][1][c];
                }
            }
            #pragma unroll
            for (int off = 1; off <= 2; off <<= 1){
                #pragma unroll
                for (int c = 0; c < 3; c++){
                    pA[c] += __shfl_xor_sync(0xffffffffu, pA[c], off);
                    pB[c] += __shfl_xor_sync(0xffffffffu, pB[c], off);
                }
            }
            if (lc == 0){
                int rA = wm*64 + mt*16 + lr;
                #pragma unroll
                for (int c = 0; c < 3; c++){
                    psum[(wn*128 + rA)*3 + c]     = pA[c];
                    psum[(wn*128 + rA + 8)*3 + c] = pB[c];
                }
            }
        }
        __syncthreads();
        for (int r = tid; r < 128; r += NTHR){
            #pragma unroll
            for (int c = 0; c < 3; c++){
                float g = psum[(0*128 + r)*3 + c];
                g += psum[(1*128 + r)*3 + c];
                g += psum[(2*128 + r)*3 + c];
                g += psum[(3*128 + r)*3 + c];
                C[((size_t)blockIdx.x*BT + (m0 + r))*3 + c] = g;
            }
        }
        return;
    }

    // epilogue: registers -> gmem
    #pragma unroll
    for (int mt = 0; mt < 4; mt++){
        #pragma unroll
        for (int nt = 0; nt < 4; nt++){
            int row = m0 + wm*64 + mt*16 + lr;
            int col = n0 + wn*32 + nt*8 + lc*2;
            float* a = acc[mt][nt];
            if (EPI == EP_PLAIN){
                *(float2*)&C[(size_t)row*ldc + col]     = make_float2(a[0], a[1]);
                *(float2*)&C[(size_t)(row+8)*ldc + col] = make_float2(a[2], a[3]);
            } else { // EP_PAD: half hi/lo planes, zero pad columns
                if (col + 2 <= ldc){
                    float v0 = (col   < Nreal) ? a[0] : 0.f;
                    float v1 = (col+1 < Nreal) ? a[1] : 0.f;
                    float v2 = (col   < Nreal) ? a[2] : 0.f;
                    float v3 = (col+1 < Nreal) ? a[3] : 0.f;
                    __half h0,l0,h1,l1,h2,l2,h3,l3;
                    split16(v0,h0,l0); split16(v1,h1,l1);
                    split16(v2,h2,l2); split16(v3,h3,l3);
                    *(__half2*)&Ch[(size_t)row*ldc + col]     = __halves2half2(h0, h1);
                    *(__half2*)&Cl[(size_t)row*ldc + col]     = __halves2half2(l0, l1);
                    *(__half2*)&Ch[(size_t)(row+8)*ldc + col] = __halves2half2(h2, h3);
                    *(__half2*)&Cl[(size_t)(row+8)*ldc + col] = __halves2half2(l2, l3);
                }
            }
        }
    }
}

// ---------------- fp32 -> fp16 hi/lo split ------------------------------------
__global__ void __launch_bounds__(256) split_kernel(
    const float* __restrict__ x, __half* __restrict__ h, __half* __restrict__ l, int n)
{
    int i = blockIdx.x*256 + threadIdx.x;
    if (i < n){ __half hv, lv; split16(x[i], hv, lv); h[i] = hv; l[i] = lv; }
}

// ---------------- final 3-class head: sum partials + log_softmax + argmax -------
__global__ void __launch_bounds__(256) logits2_kernel(
    const float* __restrict__ gpart, const float* __restrict__ b2,
    float* __restrict__ out0, int* __restrict__ pred)
{
    int row = blockIdx.x*256 + threadIdx.x;
    float s[3];
    #pragma unroll
    for (int c = 0; c < 3; c++) s[c] = b2[c];
    #pragma unroll
    for (int k = 0; k < 6; k++)
        #pragma unroll
        for (int c = 0; c < 3; c++)
            s[c] += gpart[((size_t)k*BT + row)*3 + c];
    float m = fmaxf(s[0], fmaxf(s[1], s[2]));
    float lse = m + logf(expf(s[0]-m)+expf(s[1]-m)+expf(s[2]-m));
    size_t o = (size_t)row*3;
    out0[o+0] = s[0] - lse; out0[o+1] = s[1] - lse; out0[o+2] = s[2] - lse;
    int idx = 0; float best = s[0];
    if (s[1] > best){ best = s[1]; idx = 1; }
    if (s[2] > best){ idx = 2; }
    pred[row] = idx;
}

// ---------------- BIO segment scan (warp-parallel, ballot-based) ----------------
__global__ void scan_kernel(const int* __restrict__ labels,
                            int* __restrict__ rowinfo, int* __restrict__ nvraw)
{
    __shared__ int pos[513];
    int b = blockIdx.x, lane = threadIdx.x;
    const int* lab = labels + b*Tt;
    int base = 0;
    int first1 = Tt;
    int any2 = 0;
    #pragma unroll 1
    for (int c = 0; c < Tt/32; c++){
        int l = lab[c*32 + lane];
        unsigned m1 = __ballot_sync(0xffffffffu, l == 1);
        unsigned m2 = __ballot_sync(0xffffffffu, l == 2);
        if (l == 1) pos[base + __popc(m1 & ((1u<<lane)-1))] = c*32 + lane;
        if (first1 == Tt){
            if (m1){
                int fl = __ffs(m1) - 1;
                first1 = c*32 + fl;
                any2 |= (m2 & ((1u<<fl)-1)) != 0;
            } else any2 |= (m2 != 0);
        }
        base += __popc(m1);
    }
    int m = base;
    int lead = any2;
    __syncwarp();
    if (lane == 0){
        pos[m] = Tt;
        if (lead) rowinfo[b*Tt] = (0<<16) | (m ? pos[0] : Tt);
        nvraw[b] = lead + m;
    }
    __syncwarp();
    for (int j = lane; j < m; j += 32){
        int s = pos[j], e = pos[j+1];
        rowinfo[b*Tt + lead + j] = (s<<16) | e;
    }
}

// ---------------- global compaction bookkeeping ---------------------------------
__global__ void combine2_kernel(const int* __restrict__ nvraw0, const int* __restrict__ nvraw1,
                                int* __restrict__ base0, int* __restrict__ base1,
                                int* __restrict__ lsm_nv, int* __restrict__ lsm_base,
                                int* __restrict__ rtot)
{
    if (threadIdx.x || blockIdx.x) return;
    int off = 0;
    int cnt = 0;
    for (int b=0;b<Bb;b++){
        int nv = nvraw0[b];
        if (nv > 0){ base0[b] = off; lsm_base[cnt] = off; lsm_nv[cnt] = nv; cnt++; off += nv; }
        else base0[b] = -1;
    }
    for (int k=cnt;k<Bb;k++) lsm_nv[k] = 0;
    cnt = 0;
    for (int b=0;b<Bb;b++){
        int nv = nvraw1[b];
        if (nv > 0){ base1[b] = off; lsm_base[Bb+cnt] = off; lsm_nv[Bb+cnt] = nv; cnt++; off += nv; }
        else base1[b] = -1;
    }
    for (int k=cnt;k<Bb;k++) lsm_nv[Bb+k] = 0;
    rtot[1] = off;
    rtot[0] = (off + 127) & ~127;   // Rpad (128-row tiles)
}

// ---------------- zero pooled pad rows [R, Rpad) --------------------------------
__global__ void __launch_bounds__(256) padzero_kernel(
    const int* __restrict__ rtot, __half* __restrict__ ph, __half* __restrict__ pl)
{
    int row = rtot[1] + blockIdx.x;
    if (row >= rtot[0]) return;
    size_t off = (size_t)row*Hh;
    __half z = __float2half(0.f);
    for (int i = threadIdx.x; i < Hh; i += 256){ ph[off+i] = z; pl[off+i] = z; }
}

// ---------------- segment means -> globally compacted pooled rows ---------------
__global__ void __launch_bounds__(256) pool_kernel(
    const int* __restrict__ labels, const float* __restrict__ hidden,
    const int* __restrict__ rowinfo, const int* __restrict__ nvraw,
    const int* __restrict__ basearr, __half* __restrict__ ph, __half* __restrict__ pl)
{
    int b = blockIdx.x;
    int d = basearr[b];
    if (d < 0) return;
    int nv = nvraw[b];
    __shared__ int labs[Tt];
    int tid = threadIdx.x;
    for (int i=tid;i<Tt;i+=256) labs[i] = labels[b*Tt+i];
    __syncthreads();
    int r0 = blockIdx.y * 32;
    int r1 = min(r0+32, nv);
    for (int r=r0; r<r1; r++){
        int info = rowinfo[b*Tt + r];
        int s = info >> 16, e = info & 0xffff;
        float a0=0.f,a1=0.f,a2=0.f;
        int cnt = 0;
        for (int t=s;t<e;t++){
            if (labs[t] != 0){
                cnt++;
                const float* hp = hidden + ((size_t)(b*Tt)+t)*Hh;
                a0 += hp[tid]; a1 += hp[tid+256]; a2 += hp[tid+512];
            }
        }
        float inv = 1.0f / (float)cnt;
        size_t off = ((size_t)(d + r))*Hh;
        __half hv, lv;
        split16(a0*inv, hv, lv); ph[off+tid]     = hv; pl[off+tid]     = lv;
        split16(a1*inv, hv, lv); ph[off+tid+256] = hv; pl[off+tid+256] = lv;
        split16(a2*inv, hv, lv); ph[off+tid+512] = hv; pl[off+tid+512] = lv;
    }
}

// ---------------- row log-softmax over compacted sc ------------------------------
__global__ void __launch_bounds__(256) lsm_kernel(
    const float* __restrict__ sc, const int* __restrict__ lsm_nv,
    const int* __restrict__ lsm_base, float* __restrict__ out1, float* __restrict__ out2)
{
    int row = blockIdx.x*8 + (threadIdx.x >> 5);  // output row within a pass
    int p   = blockIdx.y;
    int lane = threadIdx.x & 31;
    int bb = row >> 9, t = row & 511;
    int nv = lsm_nv[p*Bb + bb];
    float* op = (p ? out2 : out1) + (size_t)row*Nn;
    if (t >= nv){
        const float CNEG = -7.6246189861593985f;   // -log(2048)
        float4 c4 = make_float4(CNEG,CNEG,CNEG,CNEG);
        for (int i=lane;i<Nn/4;i+=32) ((float4*)op)[i] = c4;
        return;
    }
    int srow = lsm_base[p*Bb + bb] + t;
    const float4* ip = (const float4*)(sc + (size_t)srow*Nn);
    float4 v[16];
    float m = -3.4e38f;
    #pragma unroll
    for (int i=0;i<16;i++){
        v[i] = ip[lane + i*32];
        m = fmaxf(m, fmaxf(fmaxf(v[i].x,v[i].y), fmaxf(v[i].z,v[i].w)));
    }
    #pragma unroll
    for (int off=16;off;off>>=1) m = fmaxf(m, __shfl_xor_sync(0xffffffffu, m, off));
    float s = 0.f;
    #pragma unroll
    for (int i=0;i<16;i++)
        s += expf(v[i].x-m)+expf(v[i].y-m)+expf(v[i].z-m)+expf(v[i].w-m);
    #pragma unroll
    for (int off=16;off;off>>=1) s += __shfl_xor_sync(0xffffffffu, s, off);
    float corr = m + logf(s);
    #pragma unroll
    for (int i=0;i<16;i++){
        float4 o = v[i];
        o.x-=corr; o.y-=corr; o.z-=corr; o.w-=corr;
        ((float4*)op)[lane + i*32] = o;
    }
}

// ---------------- host -------------------------------------------------------------
extern "C" void kernel_launch(void* const* d_in, const int* in_sizes, int n_in,
                              void* d_out, int out_size)
{
    (void)in_sizes; (void)n_in; (void)out_size;
    const int*   labels = (const int*)  d_in[0];
    const float* hidden = (const float*)d_in[1];
    const float* ent    = (const float*)d_in[2];
    const float* W1     = (const float*)d_in[3];
    const float* b1     = (const float*)d_in[4];
    const float* W2     = (const float*)d_in[5];
    const float* b2     = (const float*)d_in[6];
    const float* Wm     = (const float*)d_in[7];
    const float* Wd     = (const float*)d_in[8];

    float* out0 = (float*)d_out;
    float* s1o  = out0 + (size_t)BT*3;
    float* s2o  = s1o  + (size_t)BT*Nn;

    __half *hidh,*hidl,*enth,*entl,*w1h,*w1l,*wmh,*wml,*wdh,*wdl;
    __half *poolh,*pooll,*pmh,*pml,*pdh,*pdl;
    float *gpart, *sc;
    int *pred, *ri0, *ri1, *nv0, *nv1, *b0, *b1a, *lnv, *lbs, *rtot;
    cudaGetSymbolAddress((void**)&hidh, g_hid_h);  cudaGetSymbolAddress((void**)&hidl, g_hid_l);
    cudaGetSymbolAddress((void**)&enth, g_ent_h);  cudaGetSymbolAddress((void**)&entl, g_ent_l);
    cudaGetSymbolAddress((void**)&w1h,  g_W1_h);   cudaGetSymbolAddress((void**)&w1l,  g_W1_l);
    cudaGetSymbolAddress((void**)&wmh,  g_Wm_h);   cudaGetSymbolAddress((void**)&wml,  g_Wm_l);
    cudaGetSymbolAddress((void**)&wdh,  g_Wd_h);   cudaGetSymbolAddress((void**)&wdl,  g_Wd_l);
    cudaGetSymbolAddress((void**)&poolh,g_pool_h); cudaGetSymbolAddress((void**)&pooll,g_pool_l);
    cudaGetSymbolAddress((void**)&pmh,  g_pm_h);   cudaGetSymbolAddress((void**)&pml,  g_pm_l);
    cudaGetSymbolAddress((void**)&pdh,  g_pd_h);   cudaGetSymbolAddress((void**)&pdl,  g_pd_l);
    cudaGetSymbolAddress((void**)&gpart,g_part);
    cudaGetSymbolAddress((void**)&sc,   g_sc);
    cudaGetSymbolAddress((void**)&pred, g_pred);
    cudaGetSymbolAddress((void**)&ri0,  g_rowinfo0);
    cudaGetSymbolAddress((void**)&ri1,  g_rowinfo1);
    cudaGetSymbolAddress((void**)&nv0,  g_nvraw0);
    cudaGetSymbolAddress((void**)&nv1,  g_nvraw1);
    cudaGetSymbolAddress((void**)&b0,   g_base0);
    cudaGetSymbolAddress((void**)&b1a,  g_base1);
    cudaGetSymbolAddress((void**)&lnv,  g_lsm_nv);
    cudaGetSymbolAddress((void**)&lbs,  g_lsm_base);
    cudaGetSymbolAddress((void**)&rtot, g_Rtot);

    cudaFuncSetAttribute((const void*)mma_gemm<EP_LOGITS,false,3>, cudaFuncAttributeMaxDynamicSharedMemorySize, SMEM_LOG);
    cudaFuncSetAttribute((const void*)mma_gemm<EP_PAD,false,3>,    cudaFuncAttributeMaxDynamicSharedMemorySize, SMEM_GEMM);
    cudaFuncSetAttribute((const void*)mma_gemm<EP_PAD,true,2>,     cudaFuncAttributeMaxDynamicSharedMemorySize, SMEM_GEMM);
    cudaFuncSetAttribute((const void*)mma_gemm<EP_PLAIN,true,2>,   cudaFuncAttributeMaxDynamicSharedMemorySize, SMEM_GEMM);

    // launches 1-3: splits needed by gemm1; launch 4 = gemm1 (ncu capture slot)
    split_kernel<<<(BT*Hh+255)/256, 256>>>(hidden, hidh, hidl, BT*Hh);
    split_kernel<<<(Hh*Hh+255)/256, 256>>>(W1, w1h, w1l, Hh*Hh);
    split_kernel<<<(Nn*Hh+255)/256, 256>>>(ent, enth, entl, Nn*Hh);

    // 1) fused: h = relu(x@W1^T+b1); gpart[cb] = h_block @ W2^T  (h never stored)
    mma_gemm<EP_LOGITS,false,3><<<dim3(Hh/128, BT/128), NTHR, SMEM_LOG>>>(
        hidh, hidl, w1h, w1l, gpart, nullptr, nullptr, Hh, Hh, 3, Hh, Hh, Hh, b1, nullptr, W2);

    split_kernel<<<(Pp*Hh+255)/256, 256>>>(Wm, wmh, wml, Pp*Hh);
    split_kernel<<<(Pp*Hh+255)/256, 256>>>(Wd, wdh, wdl, Pp*Hh);

    // 2) bio logits -> out0 + predicted labels (sum col-tile partials, fixed order)
    logits2_kernel<<<BT/256, 256>>>(gpart, b2, out0, pred);

    // 3) pd = ent @ Wd^T -> half hi/lo planes, K-padded to KP (3-term, cheap)
    mma_gemm<EP_PAD,false,3><<<dim3(3, Nn/128), NTHR, SMEM_GEMM>>>(
        enth, entl, wdh, wdl, nullptr, pdh, pdl, Hh, Hh, KP, Hh, Pp, Pp, nullptr, nullptr, nullptr);

    // 4) both pooling passes, globally compacted
    scan_kernel<<<Bb, 32>>>(labels, ri0, nv0);
    scan_kernel<<<Bb, 32>>>(pred,   ri1, nv1);
    combine2_kernel<<<1, 1>>>(nv0, nv1, b0, b1a, lnv, lbs, rtot);
    pool_kernel<<<dim3(Bb, 16), 256>>>(labels, hidden, ri0, nv0, b0,  poolh, pooll);
    pool_kernel<<<dim3(Bb, 16), 256>>>(pred,   hidden, ri1, nv1, b1a, poolh, pooll);
    padzero_kernel<<<128, 256>>>(rtot, poolh, pooll);

    // 5) pm = pooled @ Wm^T over compacted rows — 2-term (smooth path)
    mma_gemm<EP_PAD,true,2><<<dim3(3, BT2/128), NTHR, SMEM_GEMM>>>(
        poolh, pooll, wmh, wml, nullptr, pmh, pml, Hh, Hh, KP, Hh, Pp, Pp, nullptr, rtot, nullptr);

    // 6) sc = pm @ pd^T over compacted rows — 2-term (smooth path)
    mma_gemm<EP_PLAIN,true,2><<<dim3(Nn/128, BT2/128), NTHR, SMEM_GEMM>>>(
        pmh, pml, pdh, pdl, sc, nullptr, nullptr, KP, KP, Nn, KP, Nn, Nn, nullptr, rtot, nullptr);

    // 7) log-softmax scatter to both outputs
    lsm_kernel<<<dim3(BT/8, 2), 256>>>(sc, lnv, lbs, s1o, s2o);
}

// round 13
// speedup vs baseline: 3.8469x; 1.0911x over previous
#include <cuda_runtime.h>
#include <cuda_fp16.h>
#include <math.h>
#include <stdint.h>

#define Bb 64
#define Tt 512
#define Hh 768
#define Nn 2048
#define Pp 300
#define KP 320
#define BT (Bb*Tt)
#define BT2 (2*BT)

// ---------------- scratch (device globals; no allocation allowed) ----------
__device__ __half g_ent_h[(size_t)Nn*Hh],   g_ent_l[(size_t)Nn*Hh];
__device__ __half g_W1_h[Hh*Hh],            g_W1_l[Hh*Hh];
__device__ __half g_Wm_h[Pp*Hh],            g_Wm_l[Pp*Hh];
__device__ __half g_Wd_h[Pp*Hh],            g_Wd_l[Pp*Hh];
__device__ __half g_pool_h[(size_t)BT2*Hh], g_pool_l[(size_t)BT2*Hh];
__device__ __half g_pm_h[(size_t)BT2*KP],   g_pm_l[(size_t)BT2*KP];
__device__ __half g_pd_h[(size_t)Nn*KP],    g_pd_l[(size_t)Nn*KP];
__device__ float  g_part[(size_t)6*BT*3];   // logits partials per col-tile
__device__ float  g_sc[(size_t)BT2*Nn];
__device__ int    g_pred[BT];
__device__ int    g_rowinfo0[BT], g_rowinfo1[BT];
__device__ int    g_nvraw0[Bb],  g_nvraw1[Bb];
__device__ int    g_base0[Bb],   g_base1[Bb];
__device__ int    g_lsm_nv[2*Bb], g_lsm_base[2*Bb];
__device__ int    g_Rtot[4];                     // [0]=Rpad  [1]=R

// ---------------- helpers ----------------------------------------------------
__device__ __forceinline__ uint32_t smem_u32(const void* p){
    uint32_t a;
    asm("{ .reg .u64 t; cvta.to.shared.u64 t, %1; cvt.u32.u64 %0, t; }" : "=r"(a) : "l"(p));
    return a;
}
__device__ __forceinline__ void cp_async16(uint32_t dst, const void* src, bool ok){
    int sz = ok ? 16 : 0;   // src-size 0 -> zero-fill 16B
    asm volatile("cp.async.cg.shared.global [%0], [%1], 16, %2;" :: "r"(dst), "l"(src), "r"(sz));
}
__device__ __forceinline__ void cp_commit(){ asm volatile("cp.async.commit_group;" ::: "memory"); }
template<int N> __device__ __forceinline__ void cp_wait(){ asm volatile("cp.async.wait_group %0;" :: "n"(N) : "memory"); }

__device__ __forceinline__ void ldsm4(uint32_t* r, uint32_t addr){
    asm volatile("ldmatrix.sync.aligned.m8n8.x4.shared.b16 {%0,%1,%2,%3}, [%4];"
        : "=r"(r[0]), "=r"(r[1]), "=r"(r[2]), "=r"(r[3]) : "r"(addr));
}
__device__ __forceinline__ void mma16(float* d, const uint32_t* a, uint32_t b0, uint32_t b1){
    asm volatile(
        "mma.sync.aligned.m16n8k16.row.col.f32.f16.f16.f32 "
        "{%0,%1,%2,%3}, {%4,%5,%6,%7}, {%8,%9}, {%0,%1,%2,%3};"
        : "+f"(d[0]), "+f"(d[1]), "+f"(d[2]), "+f"(d[3])
        : "r"(a[0]), "r"(a[1]), "r"(a[2]), "r"(a[3]), "r"(b0), "r"(b1));
}
__device__ __forceinline__ void split16(float v, __half& h, __half& l){
    h = __float2half_rn(v);
    l = __float2half_rn(v - __half2float(h));
}

// ---------------- fp16 GEMM: C[M,N] = A[M,K] @ B[N,K]^T ----------------------
// CTA tile 128x128, BK=32, 8 warps (2m x 4n), warp tile 64x32, 3-stage cp.async,
// __launch_bounds__(256,2) -> <=128 regs -> 2 CTAs/SM.
// EP_LOGITS: fused relu(h)+W2 projection -> per-col-tile partials.
// CVT: A arrives as raw fp32 (gemm1); converted in-stage to interleaved h/l
//      planes (per-64-row groups: h at group*8192, l at +4096).
enum { EP_LOGITS = 0, EP_PAD = 1, EP_PLAIN = 2 };
#define ST_ALO 8192
#define ST_B   16384
#define ST_BLO 8192      // relative to ST_B
#define STAGE  32768
#define SMEM_GEMM (3*STAGE)              // 98304
#define SMEM_LOG  (3*STAGE + 6144 + 1536) // + psum[4][128][3] + w2s[3][128]
#define NTHR 256

template<int EPI, bool ROWMASK, int TERMS, bool CVT>
__global__ void __launch_bounds__(NTHR, 2) mma_gemm(
    const __half* __restrict__ Ah, const __half* __restrict__ Al,
    const float* __restrict__ Afp,
    const __half* __restrict__ Bh, const __half* __restrict__ Bl,
    float* __restrict__ C, __half* __restrict__ Ch, __half* __restrict__ Cl,
    int lda, int ldb, int ldc, int K, int Nreal, int NBreal,
    const float* __restrict__ bias, const int* __restrict__ rtot,
    const float* __restrict__ w2)
{
    extern __shared__ char smem[];
    const int m0 = blockIdx.y * 128, n0 = blockIdx.x * 128;
    const int tid = threadIdx.x;
    if (ROWMASK){
        if (m0 >= rtot[0]) return;     // beyond compacted rows
    }
    const uint32_t sb0 = smem_u32(smem);
    const int warp = tid >> 5, lane = tid & 31;
    const int wm = warp >> 2, wn = warp & 3;     // 2 x 4 warp grid, warp tile 64x32
    const int lr = lane >> 2, lc = lane & 3;

    float* psum = (float*)(smem + 3*STAGE);          // [4][128][3]
    float* w2s  = (float*)(smem + 3*STAGE + 6144);   // [3][128]
    if (EPI == EP_LOGITS && tid < 128){
        #pragma unroll
        for (int c = 0; c < 3; c++) w2s[c*128 + tid] = w2[c*Hh + n0 + tid];
    }

    float acc[4][4][4];
    #pragma unroll
    for (int i=0;i<4;i++)
        #pragma unroll
        for (int j=0;j<4;j++)
            #pragma unroll
            for (int q=0;q<4;q++) acc[i][j][q] = 0.f;

    const int arl = (lane & 7) + ((lane >> 3) & 1) * 8;
    const int acs = lane >> 4;
    const int nrl = (lane & 7) + (lane >> 4) * 8;
    const int bcs = (lane >> 3) & 1;
    uint32_t aoff[4], boff[2];
    #pragma unroll
    for (int mt = 0; mt < 4; mt++){
        int r = wm*64 + mt*16 + arl;
        int swz = acs ^ (r & 3) ^ ((r >> 2) & 1);
        if (CVT) aoff[mt] = (uint32_t)(((r >> 6) << 13) + ((r & 63) << 6) + (swz << 4));
        else     aoff[mt] = (uint32_t)((r << 6) + (swz << 4));
    }
    #pragma unroll
    for (int nb = 0; nb < 2; nb++){
        int r = wn*32 + nb*16 + nrl;
        boff[nb] = (uint32_t)ST_B + (uint32_t)((r << 6) + ((bcs ^ (r & 3) ^ ((r >> 2) & 1)) << 4));
    }
    const uint32_t ALO = CVT ? 4096u : (uint32_t)ST_ALO;

    auto load_tile = [&](int kt, int s){
        const int k0 = kt * 32;
        const uint32_t sbs = sb0 + (uint32_t)s * STAGE;
        if (CVT){
            #pragma unroll
            for (int j = 0; j < 8; j++){
                int idx = tid + j*NTHR;                 // 0..2047
                if (idx < 1024){                        // raw fp32 A: 128 rows x 8 float4
                    int row = idx >> 3, q = idx & 7;
                    uint32_t so = sbs + (uint32_t)(row*128 + q*16);
                    cp_async16(so, Afp + (size_t)(m0 + row)*lda + k0 + q*4, true);
                } else {                                // B planes: Bh, Bl
                    int b   = idx - 1024;
                    int pl  = b >> 9;
                    int rem = b & 511;
                    int row = rem >> 2, c = rem & 3;
                    int c2  = c ^ (row & 3) ^ ((row >> 2) & 1);
                    uint32_t so = sbs + (uint32_t)(ST_B + pl*ST_BLO + row*64 + c2*16);
                    bool ok = (n0 + row) < NBreal;
                    const __half* base = pl ? Bl : Bh;
                    const __half* src = ok ? (base + (size_t)(n0 + row)*ldb + k0 + c*8) : base;
                    cp_async16(so, src, ok);
                }
            }
        } else if (TERMS == 3){
            #pragma unroll
            for (int j = 0; j < 8; j++){
                int idx = tid + j*NTHR;
                if (idx < 1024){                        // A planes: Ah, Al
                    int pl  = idx >> 9;
                    int rem = idx & 511;
                    int row = rem >> 2, c = rem & 3;
                    int c2  = c ^ (row & 3) ^ ((row >> 2) & 1);
                    uint32_t so = sbs + (uint32_t)(pl*ST_ALO + row*64 + c2*16);
                    const __half* src = (pl ? Al : Ah) + (size_t)(m0 + row)*lda + k0 + c*8;
                    cp_async16(so, src, true);
                } else {
                    int b   = idx - 1024;
                    int pl  = b >> 9;
                    int rem = b & 511;
                    int row = rem >> 2, c = rem & 3;
                    int c2  = c ^ (row & 3) ^ ((row >> 2) & 1);
                    uint32_t so = sbs + (uint32_t)(ST_B + pl*ST_BLO + row*64 + c2*16);
                    bool ok = (n0 + row) < NBreal;
                    const __half* base = pl ? Bl : Bh;
                    const __half* src = ok ? (base + (size_t)(n0 + row)*ldb + k0 + c*8) : base;
                    cp_async16(so, src, ok);
                }
            }
        } else {   // TERMS == 2: planes Ah, Bh, Bl only
            #pragma unroll
            for (int j = 0; j < 6; j++){
                int idx = tid + j*NTHR;
                if (idx < 512){                          // Ah
                    int row = idx >> 2, c = idx & 3;
                    int c2  = c ^ (row & 3) ^ ((row >> 2) & 1);
                    uint32_t so = sbs + (uint32_t)(row*64 + c2*16);
                    cp_async16(so, Ah + (size_t)(m0 + row)*lda + k0 + c*8, true);
                } else {
                    int b   = idx - 512;
                    int pl  = b >> 9;
                    int rem = b & 511;
                    int row = rem >> 2, c = rem & 3;
                    int c2  = c ^ (row & 3) ^ ((row >> 2) & 1);
                    uint32_t so = sbs + (uint32_t)(ST_B + pl*ST_BLO + row*64 + c2*16);
                    bool ok = (n0 + row) < NBreal;
                    const __half* base = pl ? Bl : Bh;
                    const __half* src = ok ? (base + (size_t)(n0 + row)*ldb + k0 + c*8) : base;
                    cp_async16(so, src, ok);
                }
            }
        }
        cp_commit();
    };

    const int nkt = K >> 5;
    load_tile(0, 0);
    if (nkt > 1) load_tile(1, 1);
    for (int kt = 0; kt < nkt; kt++){
        const int s = kt % 3;
        if (kt + 1 < nkt) cp_wait<1>(); else cp_wait<0>();
        __syncthreads();

        if (CVT){
            // in-stage fp32 -> interleaved h/l conversion, 2 row-group rounds
            char* sp = smem + s*STAGE;
            #pragma unroll
            for (int rnd = 0; rnd < 2; rnd++){
                int r   = rnd*64 + (tid >> 2);
                int seg = tid & 3;
                const float4* fp = (const float4*)(sp + (r & 63)*128 + (r >> 6)*8192 + seg*32);
                float4 f0 = fp[0], f1 = fp[1];
                __syncthreads();
                float f[8] = {f0.x,f0.y,f0.z,f0.w,f1.x,f1.y,f1.z,f1.w};
                __half hv[8], lv[8];
                #pragma unroll
                for (int j = 0; j < 8; j++) split16(f[j], hv[j], lv[j]);
                int c2 = seg ^ (r & 3) ^ ((r >> 2) & 1);
                char* hp = sp + ((r >> 6) << 13) + ((r & 63) << 6) + (c2 << 4);
                *(uint4*)hp          = *(uint4*)hv;
                *(uint4*)(hp + 4096) = *(uint4*)lv;
                __syncthreads();
            }
        }

        if (kt + 2 < nkt) load_tile(kt + 2, (kt + 2) % 3);
        const uint32_t sbs = sb0 + (uint32_t)s * STAGE;

        #pragma unroll
        for (int ks = 0; ks < 2; ks++){
            const uint32_t kx = (uint32_t)(ks << 5);
            uint32_t bhf[2][4], blf[2][4];
            #pragma unroll
            for (int nb = 0; nb < 2; nb++){
                uint32_t t = (sbs + boff[nb]) ^ kx;
                ldsm4(bhf[nb], t);
                ldsm4(blf[nb], t + ST_BLO);
            }
            #pragma unroll
            for (int mt = 0; mt < 4; mt++){
                uint32_t ahf[4], alf[4];
                uint32_t t = (sbs + aoff[mt]) ^ kx;
                ldsm4(ahf, t);
                if (TERMS == 3) ldsm4(alf, t + ALO);
                #pragma unroll
                for (int nt = 0; nt < 4; nt++){
                    const int nb = nt >> 1, p = (nt & 1) * 2;
                    float* d = acc[mt][nt];
                    mma16(d, ahf, bhf[nb][p], bhf[nb][p+1]);       // hi*hi
                    mma16(d, ahf, blf[nb][p], blf[nb][p+1]);       // hi*lo
                    if (TERMS == 3)
                        mma16(d, alf, bhf[nb][p], bhf[nb][p+1]);   // lo*hi
                }
            }
        }
        if (CVT) __syncthreads();   // stage s fully consumed before its reuse as fp32 target
    }

    if (EPI == EP_LOGITS){
        // fused: v = relu(acc + b1); partial[c] = sum_col v * W2[c][col]
        float w2v[4][2][3];
        float bv[4][2];
        #pragma unroll
        for (int nt = 0; nt < 4; nt++){
            int colL = wn*32 + nt*8 + lc*2;
            #pragma unroll
            for (int j = 0; j < 2; j++){
                bv[nt][j] = bias[n0 + colL + j];
                #pragma unroll
                for (int c = 0; c < 3; c++) w2v[nt][j][c] = w2s[c*128 + colL + j];
            }
        }
        #pragma unroll
        for (int mt = 0; mt < 4; mt++){
            float pA[3] = {0.f,0.f,0.f}, pB[3] = {0.f,0.f,0.f};
            #pragma unroll
            for (int nt = 0; nt < 4; nt++){
                float* a = acc[mt][nt];
                float v0 = a[0] + bv[nt][0]; v0 = v0 > 0.f ? v0 : 0.f;
                float v1 = a[1] + bv[nt][1]; v1 = v1 > 0.f ? v1 : 0.f;
                float v2 = a[2] + bv[nt][0]; v2 = v2 > 0.f ? v2 : 0.f;
                float v3 = a[3] + bv[nt][1]; v3 = v3 > 0.f ? v3 : 0.f;
                #pragma unroll
                for (int c = 0; c < 3; c++){
                    pA[c] += v0*w2v[nt][0][c] + v1*w2v[nt][1][c];
                    pB[c] += v2*w2v[nt][0][c] + v3*w2v[nt][1][c];
                }
            }
            #pragma unroll
            for (int off = 1; off <= 2; off <<= 1){
                #pragma unroll
                for (int c = 0; c < 3; c++){
                    pA[c] += __shfl_xor_sync(0xffffffffu, pA[c], off);
                    pB[c] += __shfl_xor_sync(0xffffffffu, pB[c], off);
                }
            }
            if (lc == 0){
                int rA = wm*64 + mt*16 + lr;
                #pragma unroll
                for (int c = 0; c < 3; c++){
                    psum[(wn*128 + rA)*3 + c]     = pA[c];
                    psum[(wn*128 + rA + 8)*3 + c] = pB[c];
                }
            }
        }
        __syncthreads();
        for (int r = tid; r < 128; r += NTHR){
            #pragma unroll
            for (int c = 0; c < 3; c++){
                float g = psum[(0*128 + r)*3 + c];
                g += psum[(1*128 + r)*3 + c];
                g += psum[(2*128 + r)*3 + c];
                g += psum[(3*128 + r)*3 + c];
                C[((size_t)blockIdx.x*BT + (m0 + r))*3 + c] = g;
            }
        }
        return;
    }

    // epilogue: registers -> gmem
    #pragma unroll
    for (int mt = 0; mt < 4; mt++){
        #pragma unroll
        for (int nt = 0; nt < 4; nt++){
            int row = m0 + wm*64 + mt*16 + lr;
            int col = n0 + wn*32 + nt*8 + lc*2;
            float* a = acc[mt][nt];
            if (EPI == EP_PLAIN){
                *(float2*)&C[(size_t)row*ldc + col]     = make_float2(a[0], a[1]);
                *(float2*)&C[(size_t)(row+8)*ldc + col] = make_float2(a[2], a[3]);
            } else { // EP_PAD: half hi/lo planes, zero pad columns
                if (col + 2 <= ldc){
                    float v0 = (col   < Nreal) ? a[0] : 0.f;
                    float v1 = (col+1 < Nreal) ? a[1] : 0.f;
                    float v2 = (col   < Nreal) ? a[2] : 0.f;
                    float v3 = (col+1 < Nreal) ? a[3] : 0.f;
                    __half h0,l0,h1,l1,h2,l2,h3,l3;
                    split16(v0,h0,l0); split16(v1,h1,l1);
                    split16(v2,h2,l2); split16(v3,h3,l3);
                    *(__half2*)&Ch[(size_t)row*ldc + col]     = __halves2half2(h0, h1);
                    *(__half2*)&Cl[(size_t)row*ldc + col]     = __halves2half2(l0, l1);
                    *(__half2*)&Ch[(size_t)(row+8)*ldc + col] = __halves2half2(h2, h3);
                    *(__half2*)&Cl[(size_t)(row+8)*ldc + col] = __halves2half2(l2, l3);
                }
            }
        }
    }
}

// ---------------- fused weight split: W1 | ent | Wm | Wd -----------------------
__global__ void __launch_bounds__(256) fsplit_kernel(
    const float* __restrict__ W1, const float* __restrict__ ent,
    const float* __restrict__ Wm, const float* __restrict__ Wd,
    __half* __restrict__ w1h, __half* __restrict__ w1l,
    __half* __restrict__ enth, __half* __restrict__ entl,
    __half* __restrict__ wmh, __half* __restrict__ wml,
    __half* __restrict__ wdh, __half* __restrict__ wdl)
{
    const int n1 = Hh*Hh, n2 = n1 + Nn*Hh, n3 = n2 + Pp*Hh, n4 = n3 + Pp*Hh;
    int i = blockIdx.x*256 + threadIdx.x;
    const float* src; __half *dh, *dl; int off;
    if (i < n1){ src = W1; dh = w1h; dl = w1l; off = i; }
    else if (i < n2){ src = ent; dh = enth; dl = entl; off = i - n1; }
    else if (i < n3){ src = Wm;  dh = wmh;  dl = wml;  off = i - n2; }
    else if (i < n4){ src = Wd;  dh = wdh;  dl = wdl;  off = i - n3; }
    else return;
    __half hv, lv; split16(src[off], hv, lv); dh[off] = hv; dl[off] = lv;
}

// ---------------- final 3-class head: sum partials + log_softmax + argmax -------
__global__ void __launch_bounds__(256) logits2_kernel(
    const float* __restrict__ gpart, const float* __restrict__ b2,
    float* __restrict__ out0, int* __restrict__ pred)
{
    int row = blockIdx.x*256 + threadIdx.x;
    float s[3];
    #pragma unroll
    for (int c = 0; c < 3; c++) s[c] = b2[c];
    #pragma unroll
    for (int k = 0; k < 6; k++)
        #pragma unroll
        for (int c = 0; c < 3; c++)
            s[c] += gpart[((size_t)k*BT + row)*3 + c];
    float m = fmaxf(s[0], fmaxf(s[1], s[2]));
    float lse = m + logf(expf(s[0]-m)+expf(s[1]-m)+expf(s[2]-m));
    size_t o = (size_t)row*3;
    out0[o+0] = s[0] - lse; out0[o+1] = s[1] - lse; out0[o+2] = s[2] - lse;
    int idx = 0; float best = s[0];
    if (s[1] > best){ best = s[1]; idx = 1; }
    if (s[2] > best){ idx = 2; }
    pred[row] = idx;
}

// ---------------- BIO segment scan, both passes (grid.y selects source) ---------
__global__ void scan2_kernel(const int* __restrict__ labels, const int* __restrict__ pred,
                             int* __restrict__ ri0, int* __restrict__ nv0,
                             int* __restrict__ ri1, int* __restrict__ nv1)
{
    __shared__ int pos[513];
    int b = blockIdx.x, lane = threadIdx.x;
    const int* lab = (blockIdx.y ? pred : labels) + b*Tt;
    int* rowinfo = blockIdx.y ? ri1 : ri0;
    int* nvraw   = blockIdx.y ? nv1 : nv0;
    int base = 0;
    int first1 = Tt;
    int any2 = 0;
    #pragma unroll 1
    for (int c = 0; c < Tt/32; c++){
        int l = lab[c*32 + lane];
        unsigned m1 = __ballot_sync(0xffffffffu, l == 1);
        unsigned m2 = __ballot_sync(0xffffffffu, l == 2);
        if (l == 1) pos[base + __popc(m1 & ((1u<<lane)-1))] = c*32 + lane;
        if (first1 == Tt){
            if (m1){
                int fl = __ffs(m1) - 1;
                first1 = c*32 + fl;
                any2 |= (m2 & ((1u<<fl)-1)) != 0;
            } else any2 |= (m2 != 0);
        }
        base += __popc(m1);
    }
    int m = base;
    int lead = any2;
    __syncwarp();
    if (lane == 0){
        pos[m] = Tt;
        if (lead) rowinfo[b*Tt] = (0<<16) | (m ? pos[0] : Tt);
        nvraw[b] = lead + m;
    }
    __syncwarp();
    for (int j = lane; j < m; j += 32){
        int s = pos[j], e = pos[j+1];
        rowinfo[b*Tt + lead + j] = (s<<16) | e;
    }
}

// ---------------- global compaction bookkeeping ---------------------------------
__global__ void combine2_kernel(const int* __restrict__ nvraw0, const int* __restrict__ nvraw1,
                                int* __restrict__ base0, int* __restrict__ base1,
                                int* __restrict__ lsm_nv, int* __restrict__ lsm_base,
                                int* __restrict__ rtot)
{
    if (threadIdx.x || blockIdx.x) return;
    int off = 0;
    int cnt = 0;
    for (int b=0;b<Bb;b++){
        int nv = nvraw0[b];
        if (nv > 0){ base0[b] = off; lsm_base[cnt] = off; lsm_nv[cnt] = nv; cnt++; off += nv; }
        else base0[b] = -1;
    }
    for (int k=cnt;k<Bb;k++) lsm_nv[k] = 0;
    cnt = 0;
    for (int b=0;b<Bb;b++){
        int nv = nvraw1[b];
        if (nv > 0){ base1[b] = off; lsm_base[Bb+cnt] = off; lsm_nv[Bb+cnt] = nv; cnt++; off += nv; }
        else base1[b] = -1;
    }
    for (int k=cnt;k<Bb;k++) lsm_nv[Bb+k] = 0;
    rtot[1] = off;
    rtot[0] = (off + 127) & ~127;   // Rpad (128-row tiles)
}

// ---------------- zero pooled pad rows [R, Rpad) --------------------------------
__global__ void __launch_bounds__(256) padzero_kernel(
    const int* __restrict__ rtot, __half* __restrict__ ph, __half* __restrict__ pl)
{
    int row = rtot[1] + blockIdx.x;
    if (row >= rtot[0]) return;
    size_t off = (size_t)row*Hh;
    __half z = __float2half(0.f);
    for (int i = threadIdx.x; i < Hh; i += 256){ ph[off+i] = z; pl[off+i] = z; }
}

// ---------------- segment means -> globally compacted pooled rows ---------------
// grid (Bb, 16, 2); z selects pass (labels vs pred)
__global__ void __launch_bounds__(256) pool2_kernel(
    const int* __restrict__ labels, const int* __restrict__ pred,
    const float* __restrict__ hidden,
    const int* __restrict__ ri0, const int* __restrict__ nv0arr, const int* __restrict__ b0arr,
    const int* __restrict__ ri1, const int* __restrict__ nv1arr, const int* __restrict__ b1arr,
    __half* __restrict__ ph, __half* __restrict__ pl)
{
    int b = blockIdx.x;
    int z = blockIdx.z;
    const int* lsrc   = (z ? pred : labels);
    const int* rowinfo = z ? ri1 : ri0;
    int d  = (z ? b1arr : b0arr)[b];
    if (d < 0) return;
    int nv = (z ? nv1arr : nv0arr)[b];
    __shared__ int labs[Tt];
    int tid = threadIdx.x;
    for (int i=tid;i<Tt;i+=256) labs[i] = lsrc[b*Tt+i];
    __syncthreads();
    int r0 = blockIdx.y * 32;
    int r1 = min(r0+32, nv);
    for (int r=r0; r<r1; r++){
        int info = rowinfo[b*Tt + r];
        int s = info >> 16, e = info & 0xffff;
        float a0=0.f,a1=0.f,a2=0.f;
        int cnt = 0;
        for (int t=s;t<e;t++){
            if (labs[t] != 0){
                cnt++;
                const float* hp = hidden + ((size_t)(b*Tt)+t)*Hh;
                a0 += hp[tid]; a1 += hp[tid+256]; a2 += hp[tid+512];
            }
        }
        float inv = 1.0f / (float)cnt;
        size_t off = ((size_t)(d + r))*Hh;
        __half hv, lv;
        split16(a0*inv, hv, lv); ph[off+tid]     = hv; pl[off+tid]     = lv;
        split16(a1*inv, hv, lv); ph[off+tid+256] = hv; pl[off+tid+256] = lv;
        split16(a2*inv, hv, lv); ph[off+tid+512] = hv; pl[off+tid+512] = lv;
    }
}

// ---------------- row log-softmax over compacted sc ------------------------------
__global__ void __launch_bounds__(256) lsm_kernel(
    const float* __restrict__ sc, const int* __restrict__ lsm_nv,
    const int* __restrict__ lsm_base, float* __restrict__ out1, float* __restrict__ out2)
{
    int row = blockIdx.x*8 + (threadIdx.x >> 5);
    int p   = blockIdx.y;
    int lane = threadIdx.x & 31;
    int bb = row >> 9, t = row & 511;
    int nv = lsm_nv[p*Bb + bb];
    float* op = (p ? out2 : out1) + (size_t)row*Nn;
    if (t >= nv){
        const float CNEG = -7.6246189861593985f;   // -log(2048)
        float4 c4 = make_float4(CNEG,CNEG,CNEG,CNEG);
        for (int i=lane;i<Nn/4;i+=32) ((float4*)op)[i] = c4;
        return;
    }
    int srow = lsm_base[p*Bb + bb] + t;
    const float4* ip = (const float4*)(sc + (size_t)srow*Nn);
    float4 v[16];
    float m = -3.4e38f;
    #pragma unroll
    for (int i=0;i<16;i++){
        v[i] = ip[lane + i*32];
        m = fmaxf(m, fmaxf(fmaxf(v[i].x,v[i].y), fmaxf(v[i].z,v[i].w)));
    }
    #pragma unroll
    for (int off=16;off;off>>=1) m = fmaxf(m, __shfl_xor_sync(0xffffffffu, m, off));
    float s = 0.f;
    #pragma unroll
    for (int i=0;i<16;i++)
        s += expf(v[i].x-m)+expf(v[i].y-m)+expf(v[i].z-m)+expf(v[i].w-m);
    #pragma unroll
    for (int off=16;off;off>>=1) s += __shfl_xor_sync(0xffffffffu, s, off);
    float corr = m + logf(s);
    #pragma unroll
    for (int i=0;i<16;i++){
        float4 o = v[i];
        o.x-=corr; o.y-=corr; o.z-=corr; o.w-=corr;
        ((float4*)op)[lane + i*32] = o;
    }
}

// ---------------- host -------------------------------------------------------------
extern "C" void kernel_launch(void* const* d_in, const int* in_sizes, int n_in,
                              void* d_out, int out_size)
{
    (void)in_sizes; (void)n_in; (void)out_size;
    const int*   labels = (const int*)  d_in[0];
    const float* hidden = (const float*)d_in[1];
    const float* ent    = (const float*)d_in[2];
    const float* W1     = (const float*)d_in[3];
    const float* b1     = (const float*)d_in[4];
    const float* W2     = (const float*)d_in[5];
    const float* b2     = (const float*)d_in[6];
    const float* Wm     = (const float*)d_in[7];
    const float* Wd     = (const float*)d_in[8];

    float* out0 = (float*)d_out;
    float* s1o  = out0 + (size_t)BT*3;
    float* s2o  = s1o  + (size_t)BT*Nn;

    __half *enth,*entl,*w1h,*w1l,*wmh,*wml,*wdh,*wdl;
    __half *poolh,*pooll,*pmh,*pml,*pdh,*pdl;
    float *gpart, *sc;
    int *pred, *ri0, *ri1, *nv0, *nv1, *b0, *b1a, *lnv, *lbs, *rtot;
    cudaGetSymbolAddress((void**)&enth, g_ent_h);  cudaGetSymbolAddress((void**)&entl, g_ent_l);
    cudaGetSymbolAddress((void**)&w1h,  g_W1_h);   cudaGetSymbolAddress((void**)&w1l,  g_W1_l);
    cudaGetSymbolAddress((void**)&wmh,  g_Wm_h);   cudaGetSymbolAddress((void**)&wml,  g_Wm_l);
    cudaGetSymbolAddress((void**)&wdh,  g_Wd_h);   cudaGetSymbolAddress((void**)&wdl,  g_Wd_l);
    cudaGetSymbolAddress((void**)&poolh,g_pool_h); cudaGetSymbolAddress((void**)&pooll,g_pool_l);
    cudaGetSymbolAddress((void**)&pmh,  g_pm_h);   cudaGetSymbolAddress((void**)&pml,  g_pm_l);
    cudaGetSymbolAddress((void**)&pdh,  g_pd_h);   cudaGetSymbolAddress((void**)&pdl,  g_pd_l);
    cudaGetSymbolAddress((void**)&gpart,g_part);
    cudaGetSymbolAddress((void**)&sc,   g_sc);
    cudaGetSymbolAddress((void**)&pred, g_pred);
    cudaGetSymbolAddress((void**)&ri0,  g_rowinfo0);
    cudaGetSymbolAddress((void**)&ri1,  g_rowinfo1);
    cudaGetSymbolAddress((void**)&nv0,  g_nvraw0);
    cudaGetSymbolAddress((void**)&nv1,  g_nvraw1);
    cudaGetSymbolAddress((void**)&b0,   g_base0);
    cudaGetSymbolAddress((void**)&b1a,  g_base1);
    cudaGetSymbolAddress((void**)&lnv,  g_lsm_nv);
    cudaGetSymbolAddress((void**)&lbs,  g_lsm_base);
    cudaGetSymbolAddress((void**)&rtot, g_Rtot);

    cudaFuncSetAttribute((const void*)mma_gemm<EP_LOGITS,false,3,true>, cudaFuncAttributeMaxDynamicSharedMemorySize, SMEM_LOG);
    cudaFuncSetAttribute((const void*)mma_gemm<EP_PAD,false,2,false>,   cudaFuncAttributeMaxDynamicSharedMemorySize, SMEM_GEMM);
    cudaFuncSetAttribute((const void*)mma_gemm<EP_PAD,true,2,false>,    cudaFuncAttributeMaxDynamicSharedMemorySize, SMEM_GEMM);
    cudaFuncSetAttribute((const void*)mma_gemm<EP_PLAIN,true,2,false>,  cudaFuncAttributeMaxDynamicSharedMemorySize, SMEM_GEMM);

    const int NSPLIT = Hh*Hh + Nn*Hh + 2*Pp*Hh;

    // 1) fused weight splits (one launch)
    fsplit_kernel<<<(NSPLIT+255)/256, 256>>>(W1, ent, Wm, Wd,
        w1h, w1l, enth, entl, wmh, wml, wdh, wdl);

    // 2) fused gemm1: h = relu(x@W1^T+b1) in-flight (fp32 A converted in-stage);
    //    gpart[cb] = h_block @ W2^T  (h never materialized)
    mma_gemm<EP_LOGITS,false,3,true><<<dim3(Hh/128, BT/128), NTHR, SMEM_LOG>>>(
        nullptr, nullptr, hidden, w1h, w1l, gpart, nullptr, nullptr,
        Hh, Hh, 3, Hh, Hh, Hh, b1, nullptr, W2);

    // 3) bio logits -> out0 + predicted labels
    logits2_kernel<<<BT/256, 256>>>(gpart, b2, out0, pred);

    // 4) pd = ent @ Wd^T -> half hi/lo planes, K-padded to KP (2-term)
    mma_gemm<EP_PAD,false,2,false><<<dim3(3, Nn/128), NTHR, SMEM_GEMM>>>(
        enth, entl, nullptr, wdh, wdl, nullptr, pdh, pdl,
        Hh, Hh, KP, Hh, Pp, Pp, nullptr, nullptr, nullptr);

    // 5) both scans (one launch), compaction, both pools (one launch), pad-zero
    scan2_kernel<<<dim3(Bb, 2), 32>>>(labels, pred, ri0, nv0, ri1, nv1);
    combine2_kernel<<<1, 1>>>(nv0, nv1, b0, b1a, lnv, lbs, rtot);
    pool2_kernel<<<dim3(Bb, 16, 2), 256>>>(labels, pred, hidden,
        ri0, nv0, b0, ri1, nv1, b1a, poolh, pooll);
    padzero_kernel<<<128, 256>>>(rtot, poolh, pooll);

    // 6) pm = pooled @ Wm^T over compacted rows — 2-term
    mma_gemm<EP_PAD,true,2,false><<<dim3(3, BT2/128), NTHR, SMEM_GEMM>>>(
        poolh, pooll, nullptr, wmh, wml, nullptr, pmh, pml,
        Hh, Hh, KP, Hh, Pp, Pp, nullptr, rtot, nullptr);

    // 7) sc = pm @ pd^T over compacted rows — 2-term
    mma_gemm<EP_PLAIN,true,2,false><<<dim3(Nn/128, BT2/128), NTHR, SMEM_GEMM>>>(
        pmh, pml, nullptr, pdh, pdl, sc, nullptr, nullptr,
        KP, KP, Nn, KP, Nn, Nn, nullptr, rtot, nullptr);

    // 8) log-softmax scatter to both outputs
    lsm_kernel<<<dim3(BT/8, 2), 256>>>(sc, lnv, lbs, s1o, s2o);
}